// round 3
// baseline (speedup 1.0000x reference)
#include <cuda_runtime.h>
#include <math.h>

#define BATCH  4
#define SEQ    2048
#define INDIM  1024
#define DMODEL 1024
#define NHEADS 16
#define HDIM   64

// Scratch (static device globals are the allowed scratch mechanism)
__device__ float g_Q[BATCH*NHEADS*SEQ*HDIM];   // [B,H,S,Dh]
__device__ float g_K[BATCH*NHEADS*SEQ*HDIM];
__device__ float g_V[BATCH*NHEADS*SEQ*HDIM];
__device__ float g_AO[BATCH*SEQ*DMODEL];       // [B,S,D] (head-concat layout)

// ---------------------------------------------------------------------------
// Kernel 1: fused QKV projection.  C[m,n] = sum_k x[m,k]*W[n,k] + b[n]
// 128x128 tile, BK=8, 256 threads, 8x8 microtile. z selects Q/K/V.
// Epilogue scatters into [B,H,S,Dh].
// ---------------------------------------------------------------------------
__global__ __launch_bounds__(256) void qkv_gemm(
    const float* __restrict__ x,
    const float* __restrict__ Wq, const float* __restrict__ bq,
    const float* __restrict__ Wk, const float* __restrict__ bk,
    const float* __restrict__ Wv, const float* __restrict__ bv)
{
    __shared__ float As[8][128];
    __shared__ float Bs[8][128];
    const int z = blockIdx.z;
    const float* W    = (z==0) ? Wq : (z==1) ? Wk : Wv;
    const float* bias = (z==0) ? bq : (z==1) ? bk : bv;
    float* out        = (z==0) ? g_Q : (z==1) ? g_K : g_V;

    const int m0 = blockIdx.y * 128;
    const int n0 = blockIdx.x * 128;
    const int t  = threadIdx.x;
    const int lr = t >> 1;            // 0..127
    const int lc = (t & 1) << 2;      // 0 or 4
    const int tx = t & 15;
    const int ty = t >> 4;

    const float* xg = x + (size_t)(m0 + lr) * INDIM + lc;
    const float* wg = W + (size_t)(n0 + lr) * INDIM + lc;

    float acc[8][8];
#pragma unroll
    for (int i = 0; i < 8; i++)
#pragma unroll
        for (int j = 0; j < 8; j++) acc[i][j] = 0.f;

    for (int k0 = 0; k0 < INDIM; k0 += 8) {
        float4 av  = *(const float4*)(xg + k0);
        float4 wv4 = *(const float4*)(wg + k0);
        As[lc+0][lr] = av.x;  As[lc+1][lr] = av.y;  As[lc+2][lr] = av.z;  As[lc+3][lr] = av.w;
        Bs[lc+0][lr] = wv4.x; Bs[lc+1][lr] = wv4.y; Bs[lc+2][lr] = wv4.z; Bs[lc+3][lr] = wv4.w;
        __syncthreads();
#pragma unroll
        for (int kk = 0; kk < 8; kk++) {
            float4 a0 = *(const float4*)&As[kk][ty*4];
            float4 a1 = *(const float4*)&As[kk][64 + ty*4];
            float4 b0 = *(const float4*)&Bs[kk][tx*4];
            float4 b1 = *(const float4*)&Bs[kk][64 + tx*4];
            float a[8] = {a0.x,a0.y,a0.z,a0.w, a1.x,a1.y,a1.z,a1.w};
            float b[8] = {b0.x,b0.y,b0.z,b0.w, b1.x,b1.y,b1.z,b1.w};
#pragma unroll
            for (int i = 0; i < 8; i++)
#pragma unroll
                for (int j = 0; j < 8; j++) acc[i][j] = fmaf(a[i], b[j], acc[i][j]);
        }
        __syncthreads();
    }

#pragma unroll
    for (int i = 0; i < 8; i++) {
        int row = (i < 4) ? (ty*4 + i) : (64 + ty*4 + (i - 4));
        int m  = m0 + row;
        int bb = m >> 11;          // m / 2048
        int ss = m & (SEQ - 1);
#pragma unroll
        for (int jj = 0; jj < 2; jj++) {
            int col = jj*64 + tx*4;
            int n   = n0 + col;
            int h   = n >> 6;
            int dh  = n & 63;
            float4 bv4 = *(const float4*)&bias[n];
            float4 r;
            r.x = acc[i][jj*4+0] + bv4.x;
            r.y = acc[i][jj*4+1] + bv4.y;
            r.z = acc[i][jj*4+2] + bv4.z;
            r.w = acc[i][jj*4+3] + bv4.w;
            *(float4*)&out[(((size_t)bb*NHEADS + h)*SEQ + ss)*HDIM + dh] = r;
        }
    }
}

// ---------------------------------------------------------------------------
// Kernel 2: causal flash attention (fp32). 64 queries x 64-key tiles.
// Q,K transposed in smem with stride 68 (16B-aligned, conflict-reduced).
// P tile aliases the K region (separated by __syncthreads).
// Dynamic smem = (2*64*68 + 64*64) * 4 = 51200 bytes.
// ---------------------------------------------------------------------------
#define TSTR 68                     // padded stride for transposed tiles

__global__ __launch_bounds__(256) void attn_kernel()
{
    extern __shared__ float sm[];
    float* Qs   = sm;               // [d][q]  stride TSTR
    float* KsPs = sm + 64*TSTR;     // Ks: [d][k] stride TSTR ; later Ps: [q][k] stride TSTR
    float* Vs   = sm + 2*64*TSTR;   // [k][d]  stride 64

    const int qt = blockIdx.x;
    const int h  = blockIdx.y;
    const int bb = blockIdx.z;
    const int q0 = qt * 64;
    const size_t head_off = ((size_t)bb*NHEADS + h) * SEQ * HDIM;
    const float* Qg = g_Q + head_off;
    const float* Kg = g_K + head_off;
    const float* Vg = g_V + head_off;

    const int t  = threadIdx.x;
    const int tx = t & 15;
    const int ty = t >> 4;

    // load Q tile transposed, pre-scaled by 1/sqrt(64)
    for (int idx = t; idx < 64*64; idx += 256) {
        int r = idx >> 6, d = idx & 63;
        Qs[d*TSTR + r] = Qg[(size_t)(q0 + r)*HDIM + d] * 0.125f;
    }

    float o[4][4];
    float mrow[4], lrow[4];
#pragma unroll
    for (int i = 0; i < 4; i++) {
        mrow[i] = -1e30f; lrow[i] = 0.f;
#pragma unroll
        for (int j = 0; j < 4; j++) o[i][j] = 0.f;
    }

    for (int kt = 0; kt <= qt; kt++) {
        const int k0 = kt * 64;
        // load K transposed + V natural
        for (int idx = t; idx < 64*64; idx += 256) {
            int r = idx >> 6, d = idx & 63;
            KsPs[d*TSTR + r] = Kg[(size_t)(k0 + r)*HDIM + d];
        }
        for (int idx = t; idx < 64*64; idx += 256) {
            Vs[idx] = Vg[(size_t)k0*HDIM + idx];
        }
        __syncthreads();

        // scores: sc[i][j] = Q[q0+ty*4+i] . K[k0+tx*4+j]  (pre-scaled)
        float sc[4][4];
#pragma unroll
        for (int i = 0; i < 4; i++)
#pragma unroll
            for (int j = 0; j < 4; j++) sc[i][j] = 0.f;
#pragma unroll 8
        for (int d = 0; d < 64; d++) {
            float4 qa = *(const float4*)&Qs[d*TSTR + ty*4];
            float4 kb = *(const float4*)&KsPs[d*TSTR + tx*4];
            float a[4] = {qa.x, qa.y, qa.z, qa.w};
            float b[4] = {kb.x, kb.y, kb.z, kb.w};
#pragma unroll
            for (int i = 0; i < 4; i++)
#pragma unroll
                for (int j = 0; j < 4; j++) sc[i][j] = fmaf(a[i], b[j], sc[i][j]);
        }

        if (kt == qt) {            // diagonal tile: causal mask (k0 == q0)
#pragma unroll
            for (int i = 0; i < 4; i++)
#pragma unroll
                for (int j = 0; j < 4; j++)
                    if (tx*4 + j > ty*4 + i) sc[i][j] = -1e30f;
        }

        // online softmax per query row (rows spread over 16 tx lanes)
#pragma unroll
        for (int i = 0; i < 4; i++) {
            float vmax = fmaxf(fmaxf(sc[i][0], sc[i][1]), fmaxf(sc[i][2], sc[i][3]));
#pragma unroll
            for (int off = 8; off > 0; off >>= 1)
                vmax = fmaxf(vmax, __shfl_xor_sync(0xffffffffu, vmax, off, 16));
            float mnew = fmaxf(mrow[i], vmax);
            float rsum = 0.f;
#pragma unroll
            for (int j = 0; j < 4; j++) {
                float p = __expf(fmaxf(sc[i][j] - mnew, -80.f));
                sc[i][j] = p;
                rsum += p;
            }
#pragma unroll
            for (int off = 8; off > 0; off >>= 1)
                rsum += __shfl_xor_sync(0xffffffffu, rsum, off, 16);
            float sold = __expf(fmaxf(mrow[i] - mnew, -80.f));
            lrow[i] = lrow[i] * sold + rsum;
            mrow[i] = mnew;
#pragma unroll
            for (int j = 0; j < 4; j++) o[i][j] *= sold;
        }
        __syncthreads();           // all threads done reading Ks

        // write P into the (now free) K region: Ps[q][k] stride TSTR
#pragma unroll
        for (int i = 0; i < 4; i++) {
            float4 p4 = make_float4(sc[i][0], sc[i][1], sc[i][2], sc[i][3]);
            *(float4*)&KsPs[(ty*4 + i)*TSTR + tx*4] = p4;
        }
        __syncthreads();

        // O += P @ V   (o[i][j]: q rows ty*4+i, dh cols tx*4+j)
#pragma unroll 8
        for (int kk = 0; kk < 64; kk++) {
            float4 vb = *(const float4*)&Vs[kk*64 + tx*4];
            float b[4] = {vb.x, vb.y, vb.z, vb.w};
            float a0 = KsPs[(ty*4 + 0)*TSTR + kk];
            float a1 = KsPs[(ty*4 + 1)*TSTR + kk];
            float a2 = KsPs[(ty*4 + 2)*TSTR + kk];
            float a3 = KsPs[(ty*4 + 3)*TSTR + kk];
#pragma unroll
            for (int j = 0; j < 4; j++) {
                o[0][j] = fmaf(a0, b[j], o[0][j]);
                o[1][j] = fmaf(a1, b[j], o[1][j]);
                o[2][j] = fmaf(a2, b[j], o[2][j]);
                o[3][j] = fmaf(a3, b[j], o[3][j]);
            }
        }
        __syncthreads();           // safe to overwrite Ks/Vs next tile
    }

    // normalize and write AO[b, s, h*64 + dh]
#pragma unroll
    for (int i = 0; i < 4; i++) {
        float inv = 1.f / lrow[i];
        int s_ = q0 + ty*4 + i;
        float4 r = make_float4(o[i][0]*inv, o[i][1]*inv, o[i][2]*inv, o[i][3]*inv);
        *(float4*)&g_AO[((size_t)bb*SEQ + s_)*DMODEL + h*HDIM + tx*4] = r;
    }
}

// ---------------------------------------------------------------------------
// Kernel 3: output projection.  out[m,n] = sum_k AO[m,k]*Wo[n,k] + bo[n]
// ---------------------------------------------------------------------------
__global__ __launch_bounds__(256) void o_gemm(
    const float* __restrict__ Wo, const float* __restrict__ bo,
    float* __restrict__ out)
{
    __shared__ float As[8][128];
    __shared__ float Bs[8][128];

    const int m0 = blockIdx.y * 128;
    const int n0 = blockIdx.x * 128;
    const int t  = threadIdx.x;
    const int lr = t >> 1;
    const int lc = (t & 1) << 2;
    const int tx = t & 15;
    const int ty = t >> 4;

    const float* xg = g_AO + (size_t)(m0 + lr) * DMODEL + lc;
    const float* wg = Wo   + (size_t)(n0 + lr) * DMODEL + lc;

    float acc[8][8];
#pragma unroll
    for (int i = 0; i < 8; i++)
#pragma unroll
        for (int j = 0; j < 8; j++) acc[i][j] = 0.f;

    for (int k0 = 0; k0 < DMODEL; k0 += 8) {
        float4 av  = *(const float4*)(xg + k0);
        float4 wv4 = *(const float4*)(wg + k0);
        As[lc+0][lr] = av.x;  As[lc+1][lr] = av.y;  As[lc+2][lr] = av.z;  As[lc+3][lr] = av.w;
        Bs[lc+0][lr] = wv4.x; Bs[lc+1][lr] = wv4.y; Bs[lc+2][lr] = wv4.z; Bs[lc+3][lr] = wv4.w;
        __syncthreads();
#pragma unroll
        for (int kk = 0; kk < 8; kk++) {
            float4 a0 = *(const float4*)&As[kk][ty*4];
            float4 a1 = *(const float4*)&As[kk][64 + ty*4];
            float4 b0 = *(const float4*)&Bs[kk][tx*4];
            float4 b1 = *(const float4*)&Bs[kk][64 + tx*4];
            float a[8] = {a0.x,a0.y,a0.z,a0.w, a1.x,a1.y,a1.z,a1.w};
            float b[8] = {b0.x,b0.y,b0.z,b0.w, b1.x,b1.y,b1.z,b1.w};
#pragma unroll
            for (int i = 0; i < 8; i++)
#pragma unroll
                for (int j = 0; j < 8; j++) acc[i][j] = fmaf(a[i], b[j], acc[i][j]);
        }
        __syncthreads();
    }

#pragma unroll
    for (int i = 0; i < 8; i++) {
        int row = (i < 4) ? (ty*4 + i) : (64 + ty*4 + (i - 4));
        int m = m0 + row;
#pragma unroll
        for (int jj = 0; jj < 2; jj++) {
            int n = n0 + jj*64 + tx*4;
            float4 bv4 = *(const float4*)&bo[n];
            float4 r;
            r.x = acc[i][jj*4+0] + bv4.x;
            r.y = acc[i][jj*4+1] + bv4.y;
            r.z = acc[i][jj*4+2] + bv4.z;
            r.w = acc[i][jj*4+3] + bv4.w;
            *(float4*)&out[(size_t)m*DMODEL + n] = r;
        }
    }
}

// ---------------------------------------------------------------------------
extern "C" void kernel_launch(void* const* d_in, const int* in_sizes, int n_in,
                              void* d_out, int out_size)
{
    const float* x  = (const float*)d_in[0];
    const float* Wq = (const float*)d_in[1];
    const float* bq = (const float*)d_in[2];
    const float* Wk = (const float*)d_in[3];
    const float* bk = (const float*)d_in[4];
    const float* Wv = (const float*)d_in[5];
    const float* bv = (const float*)d_in[6];
    const float* Wo = (const float*)d_in[7];
    const float* bo = (const float*)d_in[8];
    float* out = (float*)d_out;

    const int ATTN_SMEM = (2*64*TSTR + 64*64) * (int)sizeof(float);  // 51200 B
    cudaFuncSetAttribute(attn_kernel, cudaFuncAttributeMaxDynamicSharedMemorySize, ATTN_SMEM);

    dim3 g1(DMODEL/128, (BATCH*SEQ)/128, 3);
    qkv_gemm<<<g1, 256>>>(x, Wq, bq, Wk, bk, Wv, bv);

    dim3 g2(SEQ/64, NHEADS, BATCH);
    attn_kernel<<<g2, 256, ATTN_SMEM>>>();

    dim3 g3(DMODEL/128, (BATCH*SEQ)/128, 1);
    o_gemm<<<g3, 256>>>(Wo, bo, out);
}

// round 5
// speedup vs baseline: 1.2731x; 1.2731x over previous
#include <cuda_runtime.h>
#include <cuda_bf16.h>
#include <mma.h>
#include <stdint.h>
#include <math.h>

#define BATCH  4
#define SEQ    2048
#define INDIM  1024
#define DMODEL 1024
#define NHEADS 16
#define HDIM   64
#define KTOT   1024

// ---------------------------------------------------------------------------
// Device scratch
// ---------------------------------------------------------------------------
__device__ float g_Q[BATCH*NHEADS*SEQ*HDIM];   // [B,H,S,Dh]
__device__ float g_K[BATCH*NHEADS*SEQ*HDIM];
__device__ float g_V[BATCH*NHEADS*SEQ*HDIM];
__device__ float g_AO[BATCH*SEQ*DMODEL];       // [B,S,D]

__device__ __nv_bfloat16 g_xh[BATCH*SEQ*INDIM];
__device__ __nv_bfloat16 g_xl[BATCH*SEQ*INDIM];
__device__ __nv_bfloat16 g_AOh[BATCH*SEQ*DMODEL];
__device__ __nv_bfloat16 g_AOl[BATCH*SEQ*DMODEL];
__device__ __nv_bfloat16 g_Wh[4][DMODEL*INDIM];   // Wq,Wk,Wv,Wo hi
__device__ __nv_bfloat16 g_Wl[4][DMODEL*INDIM];   // lo

// ---------------------------------------------------------------------------
// cp.async helpers (portable PTX, sm_80+)
// ---------------------------------------------------------------------------
__device__ __forceinline__ uint32_t smem_u32(const void* p) {
    uint32_t a;
    asm("{ .reg .u64 t; cvta.to.shared.u64 t, %1; cvt.u32.u64 %0, t; }"
        : "=r"(a) : "l"(p));
    return a;
}
__device__ __forceinline__ void cp_async16(uint32_t dst, const void* src) {
    asm volatile("cp.async.cg.shared.global [%0], [%1], 16;" :: "r"(dst), "l"(src));
}
__device__ __forceinline__ void cp_commit()  { asm volatile("cp.async.commit_group;"); }
__device__ __forceinline__ void cp_wait0()   { asm volatile("cp.async.wait_group 0;"); }
__device__ __forceinline__ void cp_wait1()   { asm volatile("cp.async.wait_group 1;"); }

// ---------------------------------------------------------------------------
// fp32 -> bf16 hi/lo split conversion.  which: 0=x 1=Wq 2=Wk 3=Wv 4=Wo 5=AO
// ---------------------------------------------------------------------------
__global__ __launch_bounds__(256) void conv_hl(const float* __restrict__ src, int which)
{
    __nv_bfloat16 *h, *l;
    switch (which) {
        case 0:  h = g_xh;    l = g_xl;    break;
        case 1:  h = g_Wh[0]; l = g_Wl[0]; break;
        case 2:  h = g_Wh[1]; l = g_Wl[1]; break;
        case 3:  h = g_Wh[2]; l = g_Wl[2]; break;
        case 4:  h = g_Wh[3]; l = g_Wl[3]; break;
        default: h = g_AOh;   l = g_AOl;   src = g_AO; break;
    }
    size_t i = ((size_t)blockIdx.x * 256 + threadIdx.x) * 4;
    float4 v = *(const float4*)(src + i);
    __nv_bfloat16 h0 = __float2bfloat16(v.x), h1 = __float2bfloat16(v.y);
    __nv_bfloat16 h2 = __float2bfloat16(v.z), h3 = __float2bfloat16(v.w);
    __nv_bfloat16 l0 = __float2bfloat16(v.x - __bfloat162float(h0));
    __nv_bfloat16 l1 = __float2bfloat16(v.y - __bfloat162float(h1));
    __nv_bfloat16 l2 = __float2bfloat16(v.z - __bfloat162float(h2));
    __nv_bfloat16 l3 = __float2bfloat16(v.w - __bfloat162float(h3));
    h[i+0] = h0; h[i+1] = h1; h[i+2] = h2; h[i+3] = h3;
    l[i+0] = l0; l[i+1] = l1; l[i+2] = l2; l[i+3] = l3;
}

// ---------------------------------------------------------------------------
// wmma split-bf16 GEMM:  C[m,n] = sum_k A[m,k] * W[n,k] + bias[n]
// 128x128x32 block tile, 8 warps (warp tile 64x32), hi/lo 3-MMA split,
// cp.async double-buffered SMEM.
// mode 0: QKV (blockIdx.z selects W/bias/out, scatter into [B,H,S,Dh])
// mode 1: O-proj (A = AO hi/lo, W = Wo, plain [m,n] out)
// ---------------------------------------------------------------------------
#define BM 128
#define BN 128
#define BK 32
#define NCH (KTOT/BK)          // 32
#define LDS 72                 // bf16 elems per smem row (144B: conflict-free)
#define TILE_ELE (128*LDS)     // per-tile smem elems
#define STAGE_ELE (4*TILE_ELE)
#define OUTLD 132              // f32 staging stride
#define GEMM_SMEM_BYTES (2*STAGE_ELE*2)   // 147456 B (>= 128*OUTLD*4 = 67584)

struct GemmArgs {
    const float* bias0; const float* bias1; const float* bias2;
    float* out_o;
    int mode;
};

using namespace nvcuda;

__global__ __launch_bounds__(256) void hl_gemm(GemmArgs args)
{
    extern __shared__ __align__(16) char dsm[];
    __nv_bfloat16* smT = (__nv_bfloat16*)dsm;    // [2 stages][4 tiles][128*LDS]
    float* outsm = (float*)dsm;                  // epilogue staging (aliased)

    const int t   = threadIdx.x;
    const int wid = t >> 5;
    const int z   = blockIdx.z;
    const int m0  = blockIdx.y * BM;
    const int n0  = blockIdx.x * BN;
    const int wm  = wid & 1;      // 2 warp-rows of 64
    const int wn  = wid >> 1;     // 4 warp-cols of 32

    const __nv_bfloat16 *Ah, *Al, *Bh, *Bl;
    const float* bias; float* outp; int scatter;
    if (args.mode == 0) {
        Ah = g_xh; Al = g_xl;
        Bh = g_Wh[z]; Bl = g_Wl[z];
        bias = (z == 0) ? args.bias0 : (z == 1) ? args.bias1 : args.bias2;
        outp = (z == 0) ? g_Q : (z == 1) ? g_K : g_V;
        scatter = 1;
    } else {
        Ah = g_AOh; Al = g_AOl;
        Bh = g_Wh[3]; Bl = g_Wl[3];
        bias = args.bias0;
        outp = args.out_o;
        scatter = 0;
    }
    const __nv_bfloat16* srcs[4] = { Ah, Al, Bh, Bl };
    const int r0s[4] = { m0, m0, n0, n0 };

    wmma::fragment<wmma::accumulator, 16, 16, 16, float> c[4][2];
#pragma unroll
    for (int i = 0; i < 4; i++)
#pragma unroll
        for (int j = 0; j < 2; j++) wmma::fill_fragment(c[i][j], 0.0f);

    // --- async stage loader: 4 tiles x 128 rows x 4 x 16B chunks = 2048 ---
    auto load_stage = [&](int stage, int kc) {
#pragma unroll
        for (int it = 0; it < 8; it++) {
            int idx  = t + it * 256;
            int tile = idx >> 9;
            int rem  = idx & 511;
            int row  = rem & 127;          // consecutive threads -> rows
            int ch   = rem >> 7;           // 0..3 (8 bf16 each)
            const __nv_bfloat16* sp = srcs[tile]
                + (size_t)(r0s[tile] + row) * KTOT + kc * BK + ch * 8;
            uint32_t dp = smem_u32(smT + (stage * 4 + tile) * TILE_ELE
                                   + row * LDS + ch * 8);
            cp_async16(dp, sp);
        }
        cp_commit();
    };

    load_stage(0, 0);

    for (int kc = 0; kc < NCH; kc++) {
        const int stage = kc & 1;
        if (kc + 1 < NCH) { load_stage(stage ^ 1, kc + 1); cp_wait1(); }
        else             { cp_wait0(); }
        __syncthreads();

        const __nv_bfloat16* sAh = smT + (stage * 4 + 0) * TILE_ELE;
        const __nv_bfloat16* sAl = smT + (stage * 4 + 1) * TILE_ELE;
        const __nv_bfloat16* sBh = smT + (stage * 4 + 2) * TILE_ELE;
        const __nv_bfloat16* sBl = smT + (stage * 4 + 3) * TILE_ELE;

#pragma unroll
        for (int ks = 0; ks < 2; ks++) {
            wmma::fragment<wmma::matrix_a, 16, 16, 16, __nv_bfloat16, wmma::row_major> ah[4], al[4];
            wmma::fragment<wmma::matrix_b, 16, 16, 16, __nv_bfloat16, wmma::col_major> bh[2], bl[2];
#pragma unroll
            for (int i = 0; i < 4; i++) {
                wmma::load_matrix_sync(ah[i], sAh + (wm*64 + i*16) * LDS + ks*16, LDS);
                wmma::load_matrix_sync(al[i], sAl + (wm*64 + i*16) * LDS + ks*16, LDS);
            }
#pragma unroll
            for (int j = 0; j < 2; j++) {
                wmma::load_matrix_sync(bh[j], sBh + (wn*32 + j*16) * LDS + ks*16, LDS);
                wmma::load_matrix_sync(bl[j], sBl + (wn*32 + j*16) * LDS + ks*16, LDS);
            }
#pragma unroll
            for (int i = 0; i < 4; i++)
#pragma unroll
                for (int j = 0; j < 2; j++) {
                    wmma::mma_sync(c[i][j], ah[i], bh[j], c[i][j]);
                    wmma::mma_sync(c[i][j], ah[i], bl[j], c[i][j]);
                    wmma::mma_sync(c[i][j], al[i], bh[j], c[i][j]);
                }
        }
        __syncthreads();   // stage reusable for load kc+2
    }

    // --- epilogue: frags -> smem staging -> bias + (scatter) global ---
    __syncthreads();
#pragma unroll
    for (int i = 0; i < 4; i++)
#pragma unroll
        for (int j = 0; j < 2; j++)
            wmma::store_matrix_sync(outsm + (wm*64 + i*16) * OUTLD + wn*32 + j*16,
                                    c[i][j], OUTLD, wmma::mem_row_major);
    __syncthreads();

    {
        const int row  = t >> 1;
        const int cb   = (t & 1) * 64;
        const int m    = m0 + row;
        const int bb   = m >> 11;
        const int ss   = m & (SEQ - 1);
#pragma unroll
        for (int jj = 0; jj < 16; jj++) {
            const int col = cb + jj * 4;
            const int n   = n0 + col;
            float4 v  = *(const float4*)&outsm[row * OUTLD + col];
            float4 bv = *(const float4*)&bias[n];
            float4 o;
            o.x = v.x + bv.x; o.y = v.y + bv.y; o.z = v.z + bv.z; o.w = v.w + bv.w;
            float* dst;
            if (scatter) {
                const int h  = n >> 6;
                const int dh = n & 63;
                dst = outp + (((size_t)bb * NHEADS + h) * SEQ + ss) * HDIM + dh;
            } else {
                dst = outp + (size_t)m * DMODEL + n;
            }
            *(float4*)dst = o;
        }
    }
}

// ---------------------------------------------------------------------------
// Kernel 2: causal flash attention (fp32 SIMT, unchanged)
// ---------------------------------------------------------------------------
#define TSTR 68

__global__ __launch_bounds__(256) void attn_kernel()
{
    extern __shared__ float sm[];
    float* Qs   = sm;
    float* KsPs = sm + 64*TSTR;
    float* Vs   = sm + 2*64*TSTR;

    const int qt = blockIdx.x;
    const int h  = blockIdx.y;
    const int bb = blockIdx.z;
    const int q0 = qt * 64;
    const size_t head_off = ((size_t)bb*NHEADS + h) * SEQ * HDIM;
    const float* Qg = g_Q + head_off;
    const float* Kg = g_K + head_off;
    const float* Vg = g_V + head_off;

    const int t  = threadIdx.x;
    const int tx = t & 15;
    const int ty = t >> 4;

    for (int idx = t; idx < 64*64; idx += 256) {
        int r = idx >> 6, d = idx & 63;
        Qs[d*TSTR + r] = Qg[(size_t)(q0 + r)*HDIM + d] * 0.125f;
    }

    float o[4][4];
    float mrow[4], lrow[4];
#pragma unroll
    for (int i = 0; i < 4; i++) {
        mrow[i] = -1e30f; lrow[i] = 0.f;
#pragma unroll
        for (int j = 0; j < 4; j++) o[i][j] = 0.f;
    }

    for (int kt = 0; kt <= qt; kt++) {
        const int k0 = kt * 64;
        for (int idx = t; idx < 64*64; idx += 256) {
            int r = idx >> 6, d = idx & 63;
            KsPs[d*TSTR + r] = Kg[(size_t)(k0 + r)*HDIM + d];
        }
        for (int idx = t; idx < 64*64; idx += 256) {
            Vs[idx] = Vg[(size_t)k0*HDIM + idx];
        }
        __syncthreads();

        float sc[4][4];
#pragma unroll
        for (int i = 0; i < 4; i++)
#pragma unroll
            for (int j = 0; j < 4; j++) sc[i][j] = 0.f;
#pragma unroll 8
        for (int d = 0; d < 64; d++) {
            float4 qa = *(const float4*)&Qs[d*TSTR + ty*4];
            float4 kb = *(const float4*)&KsPs[d*TSTR + tx*4];
            float a[4] = {qa.x, qa.y, qa.z, qa.w};
            float b[4] = {kb.x, kb.y, kb.z, kb.w};
#pragma unroll
            for (int i = 0; i < 4; i++)
#pragma unroll
                for (int j = 0; j < 4; j++) sc[i][j] = fmaf(a[i], b[j], sc[i][j]);
        }

        if (kt == qt) {
#pragma unroll
            for (int i = 0; i < 4; i++)
#pragma unroll
                for (int j = 0; j < 4; j++)
                    if (tx*4 + j > ty*4 + i) sc[i][j] = -1e30f;
        }

#pragma unroll
        for (int i = 0; i < 4; i++) {
            float vmax = fmaxf(fmaxf(sc[i][0], sc[i][1]), fmaxf(sc[i][2], sc[i][3]));
#pragma unroll
            for (int off = 8; off > 0; off >>= 1)
                vmax = fmaxf(vmax, __shfl_xor_sync(0xffffffffu, vmax, off, 16));
            float mnew = fmaxf(mrow[i], vmax);
            float rsum = 0.f;
#pragma unroll
            for (int j = 0; j < 4; j++) {
                float p = __expf(fmaxf(sc[i][j] - mnew, -80.f));
                sc[i][j] = p;
                rsum += p;
            }
#pragma unroll
            for (int off = 8; off > 0; off >>= 1)
                rsum += __shfl_xor_sync(0xffffffffu, rsum, off, 16);
            float sold = __expf(fmaxf(mrow[i] - mnew, -80.f));
            lrow[i] = lrow[i] * sold + rsum;
            mrow[i] = mnew;
#pragma unroll
            for (int j = 0; j < 4; j++) o[i][j] *= sold;
        }
        __syncthreads();

#pragma unroll
        for (int i = 0; i < 4; i++) {
            float4 p4 = make_float4(sc[i][0], sc[i][1], sc[i][2], sc[i][3]);
            *(float4*)&KsPs[(ty*4 + i)*TSTR + tx*4] = p4;
        }
        __syncthreads();

#pragma unroll 8
        for (int kk = 0; kk < 64; kk++) {
            float4 vb = *(const float4*)&Vs[kk*64 + tx*4];
            float b[4] = {vb.x, vb.y, vb.z, vb.w};
            float a0 = KsPs[(ty*4 + 0)*TSTR + kk];
            float a1 = KsPs[(ty*4 + 1)*TSTR + kk];
            float a2 = KsPs[(ty*4 + 2)*TSTR + kk];
            float a3 = KsPs[(ty*4 + 3)*TSTR + kk];
#pragma unroll
            for (int j = 0; j < 4; j++) {
                o[0][j] = fmaf(a0, b[j], o[0][j]);
                o[1][j] = fmaf(a1, b[j], o[1][j]);
                o[2][j] = fmaf(a2, b[j], o[2][j]);
                o[3][j] = fmaf(a3, b[j], o[3][j]);
            }
        }
        __syncthreads();
    }

#pragma unroll
    for (int i = 0; i < 4; i++) {
        float inv = 1.f / lrow[i];
        int s_ = q0 + ty*4 + i;
        float4 r = make_float4(o[i][0]*inv, o[i][1]*inv, o[i][2]*inv, o[i][3]*inv);
        *(float4*)&g_AO[((size_t)bb*SEQ + s_)*DMODEL + h*HDIM + tx*4] = r;
    }
}

// ---------------------------------------------------------------------------
extern "C" void kernel_launch(void* const* d_in, const int* in_sizes, int n_in,
                              void* d_out, int out_size)
{
    const float* x  = (const float*)d_in[0];
    const float* Wq = (const float*)d_in[1];
    const float* bq = (const float*)d_in[2];
    const float* Wk = (const float*)d_in[3];
    const float* bk = (const float*)d_in[4];
    const float* Wv = (const float*)d_in[5];
    const float* bv = (const float*)d_in[6];
    const float* Wo = (const float*)d_in[7];
    const float* bo = (const float*)d_in[8];
    float* out = (float*)d_out;

    const int ATTN_SMEM = (2*64*TSTR + 64*64) * (int)sizeof(float);   // 51200 B
    cudaFuncSetAttribute(attn_kernel, cudaFuncAttributeMaxDynamicSharedMemorySize, ATTN_SMEM);
    cudaFuncSetAttribute(hl_gemm,     cudaFuncAttributeMaxDynamicSharedMemorySize, GEMM_SMEM_BYTES);

    // hi/lo conversions
    conv_hl<<<(BATCH*SEQ*INDIM)/1024, 256>>>(x, 0);
    conv_hl<<<(DMODEL*INDIM)/1024, 256>>>(Wq, 1);
    conv_hl<<<(DMODEL*INDIM)/1024, 256>>>(Wk, 2);
    conv_hl<<<(DMODEL*INDIM)/1024, 256>>>(Wv, 3);
    conv_hl<<<(DMODEL*DMODEL)/1024, 256>>>(Wo, 4);

    // QKV projections (HMMA split-bf16)
    GemmArgs qa;
    qa.bias0 = bq; qa.bias1 = bk; qa.bias2 = bv; qa.out_o = nullptr; qa.mode = 0;
    hl_gemm<<<dim3(DMODEL/BN, (BATCH*SEQ)/BM, 3), 256, GEMM_SMEM_BYTES>>>(qa);

    // attention
    attn_kernel<<<dim3(SEQ/64, NHEADS, BATCH), 256, ATTN_SMEM>>>();

    // AO conversion + O projection
    conv_hl<<<(BATCH*SEQ*DMODEL)/1024, 256>>>(nullptr, 5);
    GemmArgs oa;
    oa.bias0 = bo; oa.bias1 = nullptr; oa.bias2 = nullptr; oa.out_o = out; oa.mode = 1;
    hl_gemm<<<dim3(DMODEL/BN, (BATCH*SEQ)/BM, 1), 256, GEMM_SMEM_BYTES>>>(oa);
}

// round 6
// speedup vs baseline: 1.5177x; 1.1922x over previous
#include <cuda_runtime.h>
#include <cuda_bf16.h>
#include <mma.h>
#include <stdint.h>
#include <math.h>

#define BATCH  4
#define SEQ    2048
#define INDIM  1024
#define DMODEL 1024
#define NHEADS 16
#define HDIM   64
#define KTOT   1024

using namespace nvcuda;

// ---------------------------------------------------------------------------
// Device scratch (bf16 hi/lo pairs everywhere)
// ---------------------------------------------------------------------------
#define QKV_ELE (BATCH*NHEADS*SEQ*HDIM)
__device__ __nv_bfloat16 g_Qh[QKV_ELE], g_Ql[QKV_ELE];   // [B,H,S,Dh], pre-scaled 1/8
__device__ __nv_bfloat16 g_Kh[QKV_ELE], g_Kl[QKV_ELE];
__device__ __nv_bfloat16 g_Vh[QKV_ELE], g_Vl[QKV_ELE];
__device__ __nv_bfloat16 g_AOh[BATCH*SEQ*DMODEL], g_AOl[BATCH*SEQ*DMODEL];
__device__ __nv_bfloat16 g_xh[BATCH*SEQ*INDIM],  g_xl[BATCH*SEQ*INDIM];
__device__ __nv_bfloat16 g_Wh[4][DMODEL*INDIM],  g_Wl[4][DMODEL*INDIM];

// ---------------------------------------------------------------------------
// cp.async helpers (portable PTX, sm_80+)
// ---------------------------------------------------------------------------
__device__ __forceinline__ uint32_t smem_u32(const void* p) {
    uint32_t a;
    asm("{ .reg .u64 t; cvta.to.shared.u64 t, %1; cvt.u32.u64 %0, t; }"
        : "=r"(a) : "l"(p));
    return a;
}
__device__ __forceinline__ void cp_async16(uint32_t dst, const void* src) {
    asm volatile("cp.async.cg.shared.global [%0], [%1], 16;" :: "r"(dst), "l"(src));
}
__device__ __forceinline__ void cp_commit()  { asm volatile("cp.async.commit_group;"); }
__device__ __forceinline__ void cp_wait0()   { asm volatile("cp.async.wait_group 0;"); }
__device__ __forceinline__ void cp_wait1()   { asm volatile("cp.async.wait_group 1;"); }

__device__ __forceinline__ void split_hl(float v, __nv_bfloat16& h, __nv_bfloat16& l) {
    h = __float2bfloat16(v);
    l = __float2bfloat16(v - __bfloat162float(h));
}

// ---------------------------------------------------------------------------
// fp32 -> bf16 hi/lo split.  which: 0=x 1..4=Wq/Wk/Wv/Wo
// ---------------------------------------------------------------------------
__global__ __launch_bounds__(256) void conv_hl(const float* __restrict__ src, int which)
{
    __nv_bfloat16 *h, *l;
    switch (which) {
        case 0:  h = g_xh;    l = g_xl;    break;
        case 1:  h = g_Wh[0]; l = g_Wl[0]; break;
        case 2:  h = g_Wh[1]; l = g_Wl[1]; break;
        case 3:  h = g_Wh[2]; l = g_Wl[2]; break;
        default: h = g_Wh[3]; l = g_Wl[3]; break;
    }
    size_t i = ((size_t)blockIdx.x * 256 + threadIdx.x) * 4;
    float4 v = *(const float4*)(src + i);
    __nv_bfloat16 h0, h1, h2, h3, l0, l1, l2, l3;
    split_hl(v.x, h0, l0); split_hl(v.y, h1, l1);
    split_hl(v.z, h2, l2); split_hl(v.w, h3, l3);
    h[i+0] = h0; h[i+1] = h1; h[i+2] = h2; h[i+3] = h3;
    l[i+0] = l0; l[i+1] = l1; l[i+2] = l2; l[i+3] = l3;
}

// ---------------------------------------------------------------------------
// wmma split-bf16 GEMM: C[m,n] = sum_k A[m,k]*W[n,k] + bias[n]
// mode 0: QKV -> bf16 hi/lo scatter into [B,H,S,Dh] (Q pre-scaled by 1/8)
// mode 1: O-proj -> fp32 out [m,n]
// ---------------------------------------------------------------------------
#define BM 128
#define BN 128
#define BK 32
#define NCH (KTOT/BK)
#define LDSB 72
#define TILE_ELE (128*LDSB)
#define STAGE_ELE (4*TILE_ELE)
#define OUTLD 132
#define GEMM_SMEM_BYTES (2*STAGE_ELE*2)

struct GemmArgs {
    const float* bias0; const float* bias1; const float* bias2;
    float* out_o;
    int mode;
};

__global__ __launch_bounds__(256) void hl_gemm(GemmArgs args)
{
    extern __shared__ __align__(16) char dsm[];
    __nv_bfloat16* smT = (__nv_bfloat16*)dsm;
    float* outsm = (float*)dsm;

    const int t   = threadIdx.x;
    const int wid = t >> 5;
    const int z   = blockIdx.z;
    const int m0  = blockIdx.y * BM;
    const int n0  = blockIdx.x * BN;
    const int wm  = wid & 1;
    const int wn  = wid >> 1;

    const __nv_bfloat16 *Ah, *Al, *Bh, *Bl;
    const float* bias;
    if (args.mode == 0) {
        Ah = g_xh; Al = g_xl;
        Bh = g_Wh[z]; Bl = g_Wl[z];
        bias = (z == 0) ? args.bias0 : (z == 1) ? args.bias1 : args.bias2;
    } else {
        Ah = g_AOh; Al = g_AOl;
        Bh = g_Wh[3]; Bl = g_Wl[3];
        bias = args.bias0;
    }
    const __nv_bfloat16* srcs[4] = { Ah, Al, Bh, Bl };
    const int r0s[4] = { m0, m0, n0, n0 };

    wmma::fragment<wmma::accumulator, 16, 16, 16, float> c[4][2];
#pragma unroll
    for (int i = 0; i < 4; i++)
#pragma unroll
        for (int j = 0; j < 2; j++) wmma::fill_fragment(c[i][j], 0.0f);

    auto load_stage = [&](int stage, int kc) {
#pragma unroll
        for (int it = 0; it < 8; it++) {
            int idx  = t + it * 256;
            int tile = idx >> 9;
            int rem  = idx & 511;
            int row  = rem & 127;
            int ch   = rem >> 7;
            const __nv_bfloat16* sp = srcs[tile]
                + (size_t)(r0s[tile] + row) * KTOT + kc * BK + ch * 8;
            uint32_t dp = smem_u32(smT + (stage * 4 + tile) * TILE_ELE
                                   + row * LDSB + ch * 8);
            cp_async16(dp, sp);
        }
        cp_commit();
    };

    load_stage(0, 0);

    for (int kc = 0; kc < NCH; kc++) {
        const int stage = kc & 1;
        if (kc + 1 < NCH) { load_stage(stage ^ 1, kc + 1); cp_wait1(); }
        else             { cp_wait0(); }
        __syncthreads();

        const __nv_bfloat16* sAh = smT + (stage * 4 + 0) * TILE_ELE;
        const __nv_bfloat16* sAl = smT + (stage * 4 + 1) * TILE_ELE;
        const __nv_bfloat16* sBh = smT + (stage * 4 + 2) * TILE_ELE;
        const __nv_bfloat16* sBl = smT + (stage * 4 + 3) * TILE_ELE;

#pragma unroll
        for (int ks = 0; ks < 2; ks++) {
            wmma::fragment<wmma::matrix_a, 16, 16, 16, __nv_bfloat16, wmma::row_major> ah[4], al[4];
            wmma::fragment<wmma::matrix_b, 16, 16, 16, __nv_bfloat16, wmma::col_major> bh[2], bl[2];
#pragma unroll
            for (int i = 0; i < 4; i++) {
                wmma::load_matrix_sync(ah[i], sAh + (wm*64 + i*16) * LDSB + ks*16, LDSB);
                wmma::load_matrix_sync(al[i], sAl + (wm*64 + i*16) * LDSB + ks*16, LDSB);
            }
#pragma unroll
            for (int j = 0; j < 2; j++) {
                wmma::load_matrix_sync(bh[j], sBh + (wn*32 + j*16) * LDSB + ks*16, LDSB);
                wmma::load_matrix_sync(bl[j], sBl + (wn*32 + j*16) * LDSB + ks*16, LDSB);
            }
#pragma unroll
            for (int i = 0; i < 4; i++)
#pragma unroll
                for (int j = 0; j < 2; j++) {
                    wmma::mma_sync(c[i][j], ah[i], bh[j], c[i][j]);
                    wmma::mma_sync(c[i][j], ah[i], bl[j], c[i][j]);
                    wmma::mma_sync(c[i][j], al[i], bh[j], c[i][j]);
                }
        }
        __syncthreads();
    }

    __syncthreads();
#pragma unroll
    for (int i = 0; i < 4; i++)
#pragma unroll
        for (int j = 0; j < 2; j++)
            wmma::store_matrix_sync(outsm + (wm*64 + i*16) * OUTLD + wn*32 + j*16,
                                    c[i][j], OUTLD, wmma::mem_row_major);
    __syncthreads();

    {
        const int row = t >> 1;
        const int cb  = (t & 1) * 64;
        const int m   = m0 + row;
        const int bb  = m >> 11;
        const int ss  = m & (SEQ - 1);
        const float qscale = (args.mode == 0 && z == 0) ? 0.125f : 1.0f;
#pragma unroll
        for (int jj = 0; jj < 16; jj++) {
            const int col = cb + jj * 4;
            const int n   = n0 + col;
            float4 v  = *(const float4*)&outsm[row * OUTLD + col];
            float4 bv = *(const float4*)&bias[n];
            float r0 = (v.x + bv.x) * qscale;
            float r1 = (v.y + bv.y) * qscale;
            float r2 = (v.z + bv.z) * qscale;
            float r3 = (v.w + bv.w) * qscale;
            if (args.mode == 0) {
                const int h  = n >> 6;
                const int dh = n & 63;
                size_t off = (((size_t)bb * NHEADS + h) * SEQ + ss) * HDIM + dh;
                __nv_bfloat16 *dh_, *dl_;
                if (z == 0)      { dh_ = g_Qh; dl_ = g_Ql; }
                else if (z == 1) { dh_ = g_Kh; dl_ = g_Kl; }
                else             { dh_ = g_Vh; dl_ = g_Vl; }
                __nv_bfloat16 hh[4], ll[4];
                split_hl(r0, hh[0], ll[0]); split_hl(r1, hh[1], ll[1]);
                split_hl(r2, hh[2], ll[2]); split_hl(r3, hh[3], ll[3]);
                *(uint2*)(dh_ + off) = *(uint2*)hh;
                *(uint2*)(dl_ + off) = *(uint2*)ll;
            } else {
                float4 o = make_float4(r0, r1, r2, r3);
                *(float4*)(args.out_o + (size_t)m * DMODEL + n) = o;
            }
        }
    }
}

// ---------------------------------------------------------------------------
// Tensor-core causal flash attention (split-bf16 HMMA).
// 128 q-rows/block, 64-key tiles, 8 warps, warp owns 16 q-rows.
// SMEM layout (bytes):
//   sQh 0..18432, sQl 18432, sKh 36864(9216), sKl 46080, sVh 55296,
//   sVl 64512, sS 73728(34816 f32 128x68), sPh 108544, sPl 126976 -> 145408
// ---------------------------------------------------------------------------
#define ASTR 72
#define SSTR 68
#define ATTN_SMEM_BYTES 145408

__global__ __launch_bounds__(256) void attn_tc()
{
    extern __shared__ __align__(16) char asmem[];
    __nv_bfloat16* sQh = (__nv_bfloat16*)(asmem);
    __nv_bfloat16* sQl = (__nv_bfloat16*)(asmem + 18432);
    __nv_bfloat16* sKh = (__nv_bfloat16*)(asmem + 36864);
    __nv_bfloat16* sKl = (__nv_bfloat16*)(asmem + 46080);
    __nv_bfloat16* sVh = (__nv_bfloat16*)(asmem + 55296);
    __nv_bfloat16* sVl = (__nv_bfloat16*)(asmem + 64512);
    float*         sS  = (float*)       (asmem + 73728);
    __nv_bfloat16* sPh = (__nv_bfloat16*)(asmem + 108544);
    __nv_bfloat16* sPl = (__nv_bfloat16*)(asmem + 126976);

    const int t    = threadIdx.x;
    const int wid  = t >> 5;
    const int lane = t & 31;
    const int r16  = lane >> 1;       // warp-local q row (0..15)
    const int half = lane & 1;        // column half (0..1), 32 cols each
    const int bq   = blockIdx.x;
    const int h    = blockIdx.y;
    const int bb   = blockIdx.z;
    const int q0   = bq * 128;
    const size_t base = ((size_t)bb * NHEADS + h) * SEQ * HDIM;

    // load Q tiles (hi/lo) once: 128 rows x 64 cols, 8 bf16 per 16B chunk
    for (int it = 0; it < 4; it++) {
        int idx = t + it * 256;       // 0..1023
        int row = idx >> 3, ch = idx & 7;
        *(uint4*)(sQh + row*ASTR + ch*8) = *(const uint4*)(g_Qh + base + (size_t)(q0+row)*HDIM + ch*8);
        *(uint4*)(sQl + row*ASTR + ch*8) = *(const uint4*)(g_Ql + base + (size_t)(q0+row)*HDIM + ch*8);
    }
    __syncthreads();

    const int qg = q0 + wid*16 + r16;
    float mrow = -1e30f, lrow = 0.f;
    float o[32];
#pragma unroll
    for (int j = 0; j < 32; j++) o[j] = 0.f;

    const int nkt = (q0 >> 6) + 2;
    for (int kt = 0; kt < nkt; kt++) {
        const int k0 = kt * 64;
        const bool diag = (k0 + 64 > q0);

        // load K/V hi/lo tiles: 4 arrays x 64 rows x 8 chunks = 2048
        {
            const __nv_bfloat16* gsrc[4] = { g_Kh, g_Kl, g_Vh, g_Vl };
            __nv_bfloat16* sdst[4] = { sKh, sKl, sVh, sVl };
#pragma unroll
            for (int it = 0; it < 8; it++) {
                int idx = t + it * 256;
                int a   = idx >> 9;
                int rem = idx & 511;
                int row = rem >> 3, ch = rem & 7;
                *(uint4*)(sdst[a] + row*ASTR + ch*8) =
                    *(const uint4*)(gsrc[a] + base + (size_t)(k0+row)*HDIM + ch*8);
            }
        }
        __syncthreads();

        // --- S = Q.K^T (pre-scaled), split 3-MMA ---
        wmma::fragment<wmma::accumulator, 16, 16, 16, float> c[4];
#pragma unroll
        for (int j = 0; j < 4; j++) wmma::fill_fragment(c[j], 0.0f);
#pragma unroll
        for (int ks = 0; ks < 4; ks++) {
            wmma::fragment<wmma::matrix_a, 16, 16, 16, __nv_bfloat16, wmma::row_major> ah, al;
            wmma::load_matrix_sync(ah, sQh + (wid*16)*ASTR + ks*16, ASTR);
            wmma::load_matrix_sync(al, sQl + (wid*16)*ASTR + ks*16, ASTR);
#pragma unroll
            for (int j = 0; j < 4; j++) {
                wmma::fragment<wmma::matrix_b, 16, 16, 16, __nv_bfloat16, wmma::col_major> bh, bl;
                wmma::load_matrix_sync(bh, sKh + (j*16)*ASTR + ks*16, ASTR);
                wmma::load_matrix_sync(bl, sKl + (j*16)*ASTR + ks*16, ASTR);
                wmma::mma_sync(c[j], ah, bh, c[j]);
                wmma::mma_sync(c[j], ah, bl, c[j]);
                wmma::mma_sync(c[j], al, bh, c[j]);
            }
        }
#pragma unroll
        for (int j = 0; j < 4; j++)
            wmma::store_matrix_sync(sS + (wid*16)*SSTR + j*16, c[j], SSTR, wmma::mem_row_major);
        __syncwarp();

        // --- warp-local online softmax (lane owns row r16, cols half*32..+31) ---
        float sv[32];
        float smax = -1e30f;
        const float* srow = sS + (wid*16 + r16)*SSTR + half*32;
#pragma unroll
        for (int j = 0; j < 32; j++) {
            float s = srow[j];
            if (diag && (k0 + half*32 + j > qg)) s = -1e30f;
            sv[j] = s;
            smax = fmaxf(smax, s);
        }
        smax = fmaxf(smax, __shfl_xor_sync(0xffffffffu, smax, 1));
        const float mnew = fmaxf(mrow, smax);
        float rsum = 0.f;
#pragma unroll
        for (int j = 0; j < 32; j++) {
            float p = __expf(fmaxf(sv[j] - mnew, -80.f));
            sv[j] = p;
            rsum += p;
        }
        rsum += __shfl_xor_sync(0xffffffffu, rsum, 1);
        const float sold = __expf(fmaxf(mrow - mnew, -80.f));
        lrow = lrow * sold + rsum;
        mrow = mnew;

        // write P hi/lo (own row)
        {
            __nv_bfloat16* ph = sPh + (wid*16 + r16)*ASTR + half*32;
            __nv_bfloat16* pl = sPl + (wid*16 + r16)*ASTR + half*32;
#pragma unroll
            for (int j = 0; j < 16; j++) {
                __nv_bfloat16 h0, h1, l0, l1;
                split_hl(sv[2*j+0], h0, l0);
                split_hl(sv[2*j+1], h1, l1);
                ((__nv_bfloat162*)ph)[j] = __nv_bfloat162(h0, h1);
                ((__nv_bfloat162*)pl)[j] = __nv_bfloat162(l0, l1);
            }
        }
        __syncwarp();

        // --- PV: [16 x 64keys] x [64keys x 64dh], split 3-MMA ---
        wmma::fragment<wmma::accumulator, 16, 16, 16, float> pv[4];
#pragma unroll
        for (int j = 0; j < 4; j++) wmma::fill_fragment(pv[j], 0.0f);
#pragma unroll
        for (int ks = 0; ks < 4; ks++) {
            wmma::fragment<wmma::matrix_a, 16, 16, 16, __nv_bfloat16, wmma::row_major> ph, pl;
            wmma::load_matrix_sync(ph, sPh + (wid*16)*ASTR + ks*16, ASTR);
            wmma::load_matrix_sync(pl, sPl + (wid*16)*ASTR + ks*16, ASTR);
#pragma unroll
            for (int j = 0; j < 4; j++) {
                wmma::fragment<wmma::matrix_b, 16, 16, 16, __nv_bfloat16, wmma::row_major> vh, vl;
                wmma::load_matrix_sync(vh, sVh + (ks*16)*ASTR + j*16, ASTR);
                wmma::load_matrix_sync(vl, sVl + (ks*16)*ASTR + j*16, ASTR);
                wmma::mma_sync(pv[j], ph, vh, pv[j]);
                wmma::mma_sync(pv[j], ph, vl, pv[j]);
                wmma::mma_sync(pv[j], pl, vh, pv[j]);
            }
        }
#pragma unroll
        for (int j = 0; j < 4; j++)
            wmma::store_matrix_sync(sS + (wid*16)*SSTR + j*16, pv[j], SSTR, wmma::mem_row_major);
        __syncwarp();

        // merge into register O (own row)
        {
            const float* pvrow = sS + (wid*16 + r16)*SSTR + half*32;
#pragma unroll
            for (int j = 0; j < 32; j++) o[j] = o[j] * sold + pvrow[j];
        }
        __syncthreads();   // before next tile overwrites K/V (and sS reuse)
    }

    // epilogue: AO hi/lo at [b, qg, h*64 + col]
    {
        const float inv = 1.f / lrow;
        size_t off = ((size_t)bb * SEQ + qg) * DMODEL + h * HDIM + half * 32;
        __nv_bfloat16* dh_ = g_AOh + off;
        __nv_bfloat16* dl_ = g_AOl + off;
#pragma unroll
        for (int j = 0; j < 16; j++) {
            __nv_bfloat16 h0, h1, l0, l1;
            split_hl(o[2*j+0] * inv, h0, l0);
            split_hl(o[2*j+1] * inv, h1, l1);
            ((__nv_bfloat162*)dh_)[j] = __nv_bfloat162(h0, h1);
            ((__nv_bfloat162*)dl_)[j] = __nv_bfloat162(l0, l1);
        }
    }
}

// ---------------------------------------------------------------------------
extern "C" void kernel_launch(void* const* d_in, const int* in_sizes, int n_in,
                              void* d_out, int out_size)
{
    const float* x  = (const float*)d_in[0];
    const float* Wq = (const float*)d_in[1];
    const float* bq = (const float*)d_in[2];
    const float* Wk = (const float*)d_in[3];
    const float* bk = (const float*)d_in[4];
    const float* Wv = (const float*)d_in[5];
    const float* bv = (const float*)d_in[6];
    const float* Wo = (const float*)d_in[7];
    const float* bo = (const float*)d_in[8];
    float* out = (float*)d_out;

    cudaFuncSetAttribute(hl_gemm, cudaFuncAttributeMaxDynamicSharedMemorySize, GEMM_SMEM_BYTES);
    cudaFuncSetAttribute(attn_tc, cudaFuncAttributeMaxDynamicSharedMemorySize, ATTN_SMEM_BYTES);

    conv_hl<<<(BATCH*SEQ*INDIM)/1024, 256>>>(x, 0);
    conv_hl<<<(DMODEL*INDIM)/1024, 256>>>(Wq, 1);
    conv_hl<<<(DMODEL*INDIM)/1024, 256>>>(Wk, 2);
    conv_hl<<<(DMODEL*INDIM)/1024, 256>>>(Wv, 3);
    conv_hl<<<(DMODEL*DMODEL)/1024, 256>>>(Wo, 4);

    GemmArgs qa;
    qa.bias0 = bq; qa.bias1 = bk; qa.bias2 = bv; qa.out_o = nullptr; qa.mode = 0;
    hl_gemm<<<dim3(DMODEL/BN, (BATCH*SEQ)/BM, 3), 256, GEMM_SMEM_BYTES>>>(qa);

    attn_tc<<<dim3(SEQ/128, NHEADS, BATCH), 256, ATTN_SMEM_BYTES>>>();

    GemmArgs oa;
    oa.bias0 = bo; oa.bias1 = nullptr; oa.bias2 = nullptr; oa.out_o = out; oa.mode = 1;
    hl_gemm<<<dim3(DMODEL/BN, (BATCH*SEQ)/BM, 1), 256, GEMM_SMEM_BYTES>>>(oa);
}

// round 7
// speedup vs baseline: 1.9093x; 1.2580x over previous
#include <cuda_runtime.h>
#include <cuda_bf16.h>
#include <mma.h>
#include <stdint.h>
#include <math.h>

#define BATCH  4
#define SEQ    2048
#define INDIM  1024
#define DMODEL 1024
#define NHEADS 16
#define HDIM   64
#define KTOT   1024

using namespace nvcuda;

// ---------------------------------------------------------------------------
// Device scratch (bf16 hi/lo pairs everywhere)
// ---------------------------------------------------------------------------
#define QKV_ELE (BATCH*NHEADS*SEQ*HDIM)
__device__ __nv_bfloat16 g_Qh[QKV_ELE], g_Ql[QKV_ELE];   // [B,H,S,Dh], pre-scaled 1/8
__device__ __nv_bfloat16 g_Kh[QKV_ELE], g_Kl[QKV_ELE];
__device__ __nv_bfloat16 g_Vh[QKV_ELE], g_Vl[QKV_ELE];
__device__ __nv_bfloat16 g_AOh[BATCH*SEQ*DMODEL], g_AOl[BATCH*SEQ*DMODEL];
__device__ __nv_bfloat16 g_xh[BATCH*SEQ*INDIM],  g_xl[BATCH*SEQ*INDIM];
__device__ __nv_bfloat16 g_Wh[4][DMODEL*INDIM],  g_Wl[4][DMODEL*INDIM];

// ---------------------------------------------------------------------------
// PTX helpers
// ---------------------------------------------------------------------------
__device__ __forceinline__ uint32_t smem_u32(const void* p) {
    uint32_t a;
    asm("{ .reg .u64 t; cvta.to.shared.u64 t, %1; cvt.u32.u64 %0, t; }"
        : "=r"(a) : "l"(p));
    return a;
}
__device__ __forceinline__ void cp_async16(uint32_t dst, const void* src) {
    asm volatile("cp.async.cg.shared.global [%0], [%1], 16;" :: "r"(dst), "l"(src));
}
__device__ __forceinline__ void cp_commit()  { asm volatile("cp.async.commit_group;"); }
__device__ __forceinline__ void cp_wait0()   { asm volatile("cp.async.wait_group 0;"); }
__device__ __forceinline__ void cp_wait1()   { asm volatile("cp.async.wait_group 1;"); }

__device__ __forceinline__ void ldsm_x4(uint32_t* r, uint32_t a) {
    asm volatile("ldmatrix.sync.aligned.m8n8.x4.shared.b16 {%0,%1,%2,%3}, [%4];"
        : "=r"(r[0]), "=r"(r[1]), "=r"(r[2]), "=r"(r[3]) : "r"(a));
}
__device__ __forceinline__ void ldsm_x4_t(uint32_t* r, uint32_t a) {
    asm volatile("ldmatrix.sync.aligned.m8n8.x4.trans.shared.b16 {%0,%1,%2,%3}, [%4];"
        : "=r"(r[0]), "=r"(r[1]), "=r"(r[2]), "=r"(r[3]) : "r"(a));
}
__device__ __forceinline__ void mma_bf16(float* c, const uint32_t* a, const uint32_t* b) {
    asm volatile(
        "mma.sync.aligned.m16n8k16.row.col.f32.bf16.bf16.f32 "
        "{%0,%1,%2,%3}, {%4,%5,%6,%7}, {%8,%9}, {%0,%1,%2,%3};"
        : "+f"(c[0]), "+f"(c[1]), "+f"(c[2]), "+f"(c[3])
        : "r"(a[0]), "r"(a[1]), "r"(a[2]), "r"(a[3]), "r"(b[0]), "r"(b[1]));
}

__device__ __forceinline__ void split_hl(float v, __nv_bfloat16& h, __nv_bfloat16& l) {
    h = __float2bfloat16(v);
    l = __float2bfloat16(v - __bfloat162float(h));
}
__device__ __forceinline__ void pack_hl2(float x, float y, uint32_t& hp, uint32_t& lp) {
    __nv_bfloat16 hx, lx, hy, ly;
    split_hl(x, hx, lx); split_hl(y, hy, ly);
    hp = ((uint32_t)__bfloat16_as_ushort(hy) << 16) | __bfloat16_as_ushort(hx);
    lp = ((uint32_t)__bfloat16_as_ushort(ly) << 16) | __bfloat16_as_ushort(lx);
}

// ---------------------------------------------------------------------------
// fp32 -> bf16 hi/lo split.  which: 0=x 1..4=Wq/Wk/Wv/Wo
// ---------------------------------------------------------------------------
__global__ __launch_bounds__(256) void conv_hl(const float* __restrict__ src, int which)
{
    __nv_bfloat16 *h, *l;
    switch (which) {
        case 0:  h = g_xh;    l = g_xl;    break;
        case 1:  h = g_Wh[0]; l = g_Wl[0]; break;
        case 2:  h = g_Wh[1]; l = g_Wl[1]; break;
        case 3:  h = g_Wh[2]; l = g_Wl[2]; break;
        default: h = g_Wh[3]; l = g_Wl[3]; break;
    }
    size_t i = ((size_t)blockIdx.x * 256 + threadIdx.x) * 4;
    float4 v = *(const float4*)(src + i);
    __nv_bfloat16 h0, h1, h2, h3, l0, l1, l2, l3;
    split_hl(v.x, h0, l0); split_hl(v.y, h1, l1);
    split_hl(v.z, h2, l2); split_hl(v.w, h3, l3);
    h[i+0] = h0; h[i+1] = h1; h[i+2] = h2; h[i+3] = h3;
    l[i+0] = l0; l[i+1] = l1; l[i+2] = l2; l[i+3] = l3;
}

// ---------------------------------------------------------------------------
// wmma split-bf16 GEMM (unchanged from R6): C = A*W^T + bias
// ---------------------------------------------------------------------------
#define BM 128
#define BN 128
#define BK 32
#define NCH (KTOT/BK)
#define LDSB 72
#define TILE_ELE (128*LDSB)
#define STAGE_ELE (4*TILE_ELE)
#define OUTLD 132
#define GEMM_SMEM_BYTES (2*STAGE_ELE*2)

struct GemmArgs {
    const float* bias0; const float* bias1; const float* bias2;
    float* out_o;
    int mode;
};

__global__ __launch_bounds__(256) void hl_gemm(GemmArgs args)
{
    extern __shared__ __align__(16) char dsm[];
    __nv_bfloat16* smT = (__nv_bfloat16*)dsm;
    float* outsm = (float*)dsm;

    const int t   = threadIdx.x;
    const int wid = t >> 5;
    const int z   = blockIdx.z;
    const int m0  = blockIdx.y * BM;
    const int n0  = blockIdx.x * BN;
    const int wm  = wid & 1;
    const int wn  = wid >> 1;

    const __nv_bfloat16 *Ah, *Al, *Bh, *Bl;
    const float* bias;
    if (args.mode == 0) {
        Ah = g_xh; Al = g_xl;
        Bh = g_Wh[z]; Bl = g_Wl[z];
        bias = (z == 0) ? args.bias0 : (z == 1) ? args.bias1 : args.bias2;
    } else {
        Ah = g_AOh; Al = g_AOl;
        Bh = g_Wh[3]; Bl = g_Wl[3];
        bias = args.bias0;
    }
    const __nv_bfloat16* srcs[4] = { Ah, Al, Bh, Bl };
    const int r0s[4] = { m0, m0, n0, n0 };

    wmma::fragment<wmma::accumulator, 16, 16, 16, float> c[4][2];
#pragma unroll
    for (int i = 0; i < 4; i++)
#pragma unroll
        for (int j = 0; j < 2; j++) wmma::fill_fragment(c[i][j], 0.0f);

    auto load_stage = [&](int stage, int kc) {
#pragma unroll
        for (int it = 0; it < 8; it++) {
            int idx  = t + it * 256;
            int tile = idx >> 9;
            int rem  = idx & 511;
            int row  = rem & 127;
            int ch   = rem >> 7;
            const __nv_bfloat16* sp = srcs[tile]
                + (size_t)(r0s[tile] + row) * KTOT + kc * BK + ch * 8;
            uint32_t dp = smem_u32(smT + (stage * 4 + tile) * TILE_ELE
                                   + row * LDSB + ch * 8);
            cp_async16(dp, sp);
        }
        cp_commit();
    };

    load_stage(0, 0);

    for (int kc = 0; kc < NCH; kc++) {
        const int stage = kc & 1;
        if (kc + 1 < NCH) { load_stage(stage ^ 1, kc + 1); cp_wait1(); }
        else             { cp_wait0(); }
        __syncthreads();

        const __nv_bfloat16* sAh = smT + (stage * 4 + 0) * TILE_ELE;
        const __nv_bfloat16* sAl = smT + (stage * 4 + 1) * TILE_ELE;
        const __nv_bfloat16* sBh = smT + (stage * 4 + 2) * TILE_ELE;
        const __nv_bfloat16* sBl = smT + (stage * 4 + 3) * TILE_ELE;

#pragma unroll
        for (int ks = 0; ks < 2; ks++) {
            wmma::fragment<wmma::matrix_a, 16, 16, 16, __nv_bfloat16, wmma::row_major> ah[4], al[4];
            wmma::fragment<wmma::matrix_b, 16, 16, 16, __nv_bfloat16, wmma::col_major> bh[2], bl[2];
#pragma unroll
            for (int i = 0; i < 4; i++) {
                wmma::load_matrix_sync(ah[i], sAh + (wm*64 + i*16) * LDSB + ks*16, LDSB);
                wmma::load_matrix_sync(al[i], sAl + (wm*64 + i*16) * LDSB + ks*16, LDSB);
            }
#pragma unroll
            for (int j = 0; j < 2; j++) {
                wmma::load_matrix_sync(bh[j], sBh + (wn*32 + j*16) * LDSB + ks*16, LDSB);
                wmma::load_matrix_sync(bl[j], sBl + (wn*32 + j*16) * LDSB + ks*16, LDSB);
            }
#pragma unroll
            for (int i = 0; i < 4; i++)
#pragma unroll
                for (int j = 0; j < 2; j++) {
                    wmma::mma_sync(c[i][j], ah[i], bh[j], c[i][j]);
                    wmma::mma_sync(c[i][j], ah[i], bl[j], c[i][j]);
                    wmma::mma_sync(c[i][j], al[i], bh[j], c[i][j]);
                }
        }
        __syncthreads();
    }

    __syncthreads();
#pragma unroll
    for (int i = 0; i < 4; i++)
#pragma unroll
        for (int j = 0; j < 2; j++)
            wmma::store_matrix_sync(outsm + (wm*64 + i*16) * OUTLD + wn*32 + j*16,
                                    c[i][j], OUTLD, wmma::mem_row_major);
    __syncthreads();

    {
        const int row = t >> 1;
        const int cb  = (t & 1) * 64;
        const int m   = m0 + row;
        const int bb  = m >> 11;
        const int ss  = m & (SEQ - 1);
        const float qscale = (args.mode == 0 && z == 0) ? 0.125f : 1.0f;
#pragma unroll
        for (int jj = 0; jj < 16; jj++) {
            const int col = cb + jj * 4;
            const int n   = n0 + col;
            float4 v  = *(const float4*)&outsm[row * OUTLD + col];
            float4 bv = *(const float4*)&bias[n];
            float r0 = (v.x + bv.x) * qscale;
            float r1 = (v.y + bv.y) * qscale;
            float r2 = (v.z + bv.z) * qscale;
            float r3 = (v.w + bv.w) * qscale;
            if (args.mode == 0) {
                const int h  = n >> 6;
                const int dh = n & 63;
                size_t off = (((size_t)bb * NHEADS + h) * SEQ + ss) * HDIM + dh;
                __nv_bfloat16 *dh_, *dl_;
                if (z == 0)      { dh_ = g_Qh; dl_ = g_Ql; }
                else if (z == 1) { dh_ = g_Kh; dl_ = g_Kl; }
                else             { dh_ = g_Vh; dl_ = g_Vl; }
                __nv_bfloat16 hh[4], ll[4];
                split_hl(r0, hh[0], ll[0]); split_hl(r1, hh[1], ll[1]);
                split_hl(r2, hh[2], ll[2]); split_hl(r3, hh[3], ll[3]);
                *(uint2*)(dh_ + off) = *(uint2*)hh;
                *(uint2*)(dl_ + off) = *(uint2*)ll;
            } else {
                float4 o = make_float4(r0, r1, r2, r3);
                *(float4*)(args.out_o + (size_t)m * DMODEL + n) = o;
            }
        }
    }
}

// ---------------------------------------------------------------------------
// Register-resident causal flash attention (raw mma.m16n8k16, split-bf16).
// 128 q-rows/block, 64-key tiles, 8 warps; warp owns 16 q-rows.
// Scores, softmax, P-split, and O-accum all stay in registers.
// ---------------------------------------------------------------------------
#define ASTR 72
#define ATTN_SMEM_BYTES 73728   // Qh/Ql 128x72 + Kh/Kl/Vh/Vl 64x72 (bf16)

__global__ __launch_bounds__(256, 2) void attn_tc()
{
    extern __shared__ __align__(16) char asmem[];
    __nv_bfloat16* sQh = (__nv_bfloat16*)(asmem);             // 128x72
    __nv_bfloat16* sQl = (__nv_bfloat16*)(asmem + 18432);
    __nv_bfloat16* sKh = (__nv_bfloat16*)(asmem + 36864);     // 64x72
    __nv_bfloat16* sKl = (__nv_bfloat16*)(asmem + 46080);
    __nv_bfloat16* sVh = (__nv_bfloat16*)(asmem + 55296);
    __nv_bfloat16* sVl = (__nv_bfloat16*)(asmem + 64512);

    const int t    = threadIdx.x;
    const int wid  = t >> 5;
    const int lane = t & 31;
    const int bq   = blockIdx.x;
    const int h    = blockIdx.y;
    const int bb   = blockIdx.z;
    const int q0   = bq * 128;
    const size_t base = ((size_t)bb * NHEADS + h) * SEQ * HDIM;

    // load Q hi/lo tiles once (pre-scaled by 1/8 upstream)
#pragma unroll
    for (int it = 0; it < 4; it++) {
        int idx = t + it * 256;
        int row = idx >> 3, ch = idx & 7;
        *(uint4*)(sQh + row*ASTR + ch*8) = *(const uint4*)(g_Qh + base + (size_t)(q0+row)*HDIM + ch*8);
        *(uint4*)(sQl + row*ASTR + ch*8) = *(const uint4*)(g_Ql + base + (size_t)(q0+row)*HDIM + ch*8);
    }
    __syncthreads();

    const uint32_t uQh = smem_u32(sQh), uQl = smem_u32(sQl);
    const uint32_t uKh = smem_u32(sKh), uKl = smem_u32(sKl);
    const uint32_t uVh = smem_u32(sVh), uVl = smem_u32(sVl);

    // ldmatrix per-lane byte offsets
    // A (Q, 16x16 at row wid*16, k-col ks*16):
    const uint32_t aoff = (uint32_t)(((wid*16 + (lane & 15)) * ASTR + ((lane >> 4) << 3)) * 2);
    // K B-frag x4 (j-pair base: keys jp*16, dh ks*16):
    const uint32_t kboff = (uint32_t)(((((lane >> 4) << 3) + (lane & 7)) * ASTR + (((lane >> 3) & 1) << 3)) * 2);
    // V B-frag x4 trans (key chunk kk*16, dh pair jp*16):
    const uint32_t vboff = (uint32_t)((((((lane >> 3) & 1) << 3) + (lane & 7)) * ASTR + ((lane >> 4) << 3)) * 2);

    float o[8][4];
#pragma unroll
    for (int j = 0; j < 8; j++)
#pragma unroll
        for (int r = 0; r < 4; r++) o[j][r] = 0.f;

    const int rA = q0 + wid*16 + (lane >> 2);   // global q row (low)
    const int rB = rA + 8;                       // global q row (high)
    const int qwmin = q0 + wid*16;
    const int qwmax = qwmin + 15;
    float mA = -1e30f, mB = -1e30f, lA = 0.f, lB = 0.f;

    const int nkt = 2*bq + 2;
    for (int kt = 0; kt < nkt; kt++) {
        const int k0 = kt * 64;

        // load K/V hi/lo tiles (64 rows x 64 cols each)
        {
            const __nv_bfloat16* gsrc[4] = { g_Kh, g_Kl, g_Vh, g_Vl };
            __nv_bfloat16* sdst[4] = { sKh, sKl, sVh, sVl };
#pragma unroll
            for (int it = 0; it < 8; it++) {
                int idx = t + it * 256;
                int a   = idx >> 9;
                int rem = idx & 511;
                int row = rem >> 3, ch = rem & 7;
                *(uint4*)(sdst[a] + row*ASTR + ch*8) =
                    *(const uint4*)(gsrc[a] + base + (size_t)(k0+row)*HDIM + ch*8);
            }
        }
        __syncthreads();

        if (k0 <= qwmax) {     // tile has at least one unmasked column for this warp
            // ---- S = Q.K^T ----
            float c[8][4];
#pragma unroll
            for (int j = 0; j < 8; j++)
#pragma unroll
                for (int r = 0; r < 4; r++) c[j][r] = 0.f;

#pragma unroll
            for (int ks = 0; ks < 4; ks++) {
                uint32_t ah[4], al[4];
                ldsm_x4(ah, uQh + aoff + ks*32);
                ldsm_x4(al, uQl + aoff + ks*32);
#pragma unroll
                for (int jp = 0; jp < 4; jp++) {
                    uint32_t bh[4], bl[4];
                    ldsm_x4(bh, uKh + kboff + (uint32_t)(jp*16*ASTR*2) + ks*32);
                    ldsm_x4(bl, uKl + kboff + (uint32_t)(jp*16*ASTR*2) + ks*32);
                    mma_bf16(c[2*jp],   ah, bh);
                    mma_bf16(c[2*jp],   ah, bl);
                    mma_bf16(c[2*jp],   al, bh);
                    mma_bf16(c[2*jp+1], ah, bh+2);
                    mma_bf16(c[2*jp+1], ah, bl+2);
                    mma_bf16(c[2*jp+1], al, bh+2);
                }
            }

            // ---- causal mask (only when diagonal crosses this warp's rows) ----
            if (k0 + 63 > qwmin) {
#pragma unroll
                for (int j = 0; j < 8; j++) {
                    int colb = k0 + j*8 + (lane & 3)*2;
                    if (colb     > rA) c[j][0] = -1e30f;
                    if (colb + 1 > rA) c[j][1] = -1e30f;
                    if (colb     > rB) c[j][2] = -1e30f;
                    if (colb + 1 > rB) c[j][3] = -1e30f;
                }
            }

            // ---- online softmax in registers (quad shuffles) ----
            float vmA = -1e30f, vmB = -1e30f;
#pragma unroll
            for (int j = 0; j < 8; j++) {
                vmA = fmaxf(vmA, fmaxf(c[j][0], c[j][1]));
                vmB = fmaxf(vmB, fmaxf(c[j][2], c[j][3]));
            }
            vmA = fmaxf(vmA, __shfl_xor_sync(0xffffffffu, vmA, 1));
            vmA = fmaxf(vmA, __shfl_xor_sync(0xffffffffu, vmA, 2));
            vmB = fmaxf(vmB, __shfl_xor_sync(0xffffffffu, vmB, 1));
            vmB = fmaxf(vmB, __shfl_xor_sync(0xffffffffu, vmB, 2));
            const float mnA = fmaxf(mA, vmA);
            const float mnB = fmaxf(mB, vmB);

            float sA = 0.f, sB = 0.f;
#pragma unroll
            for (int j = 0; j < 8; j++) {
                c[j][0] = __expf(c[j][0] - mnA);
                c[j][1] = __expf(c[j][1] - mnA);
                c[j][2] = __expf(c[j][2] - mnB);
                c[j][3] = __expf(c[j][3] - mnB);
                sA += c[j][0] + c[j][1];
                sB += c[j][2] + c[j][3];
            }
            sA += __shfl_xor_sync(0xffffffffu, sA, 1);
            sA += __shfl_xor_sync(0xffffffffu, sA, 2);
            sB += __shfl_xor_sync(0xffffffffu, sB, 1);
            sB += __shfl_xor_sync(0xffffffffu, sB, 2);

            const float soA = __expf(mA - mnA);
            const float soB = __expf(mB - mnB);
            lA = lA * soA + sA;  mA = mnA;
            lB = lB * soB + sB;  mB = mnB;

            // rescale O accumulators
#pragma unroll
            for (int j = 0; j < 8; j++) {
                o[j][0] *= soA; o[j][1] *= soA;
                o[j][2] *= soB; o[j][3] *= soB;
            }

            // ---- O += P.V  (P A-frags built in registers from score frags) ----
#pragma unroll
            for (int kk = 0; kk < 4; kk++) {
                uint32_t ph[4], pl[4];
                pack_hl2(c[2*kk][0],   c[2*kk][1],   ph[0], pl[0]);
                pack_hl2(c[2*kk][2],   c[2*kk][3],   ph[1], pl[1]);
                pack_hl2(c[2*kk+1][0], c[2*kk+1][1], ph[2], pl[2]);
                pack_hl2(c[2*kk+1][2], c[2*kk+1][3], ph[3], pl[3]);
#pragma unroll
                for (int jp = 0; jp < 4; jp++) {
                    uint32_t vh[4], vl[4];
                    ldsm_x4_t(vh, uVh + vboff + (uint32_t)(kk*16*ASTR*2) + jp*32);
                    ldsm_x4_t(vl, uVl + vboff + (uint32_t)(kk*16*ASTR*2) + jp*32);
                    mma_bf16(o[2*jp],   ph, vh);
                    mma_bf16(o[2*jp],   ph, vl);
                    mma_bf16(o[2*jp],   pl, vh);
                    mma_bf16(o[2*jp+1], ph, vh+2);
                    mma_bf16(o[2*jp+1], ph, vl+2);
                    mma_bf16(o[2*jp+1], pl, vh+2);
                }
            }
        }
        __syncthreads();   // protect K/V smem before next tile's load
    }

    // ---- epilogue: normalize + write AO hi/lo [b, s, h*64+col] ----
    {
        const float invA = 1.f / lA;
        const float invB = 1.f / lB;
        const size_t offA = ((size_t)bb * SEQ + rA) * DMODEL + h * HDIM + (lane & 3) * 2;
        const size_t offB = ((size_t)bb * SEQ + rB) * DMODEL + h * HDIM + (lane & 3) * 2;
#pragma unroll
        for (int j = 0; j < 8; j++) {
            uint32_t hp, lp;
            pack_hl2(o[j][0] * invA, o[j][1] * invA, hp, lp);
            *(uint32_t*)(g_AOh + offA + j*8) = hp;
            *(uint32_t*)(g_AOl + offA + j*8) = lp;
            pack_hl2(o[j][2] * invB, o[j][3] * invB, hp, lp);
            *(uint32_t*)(g_AOh + offB + j*8) = hp;
            *(uint32_t*)(g_AOl + offB + j*8) = lp;
        }
    }
}

// ---------------------------------------------------------------------------
extern "C" void kernel_launch(void* const* d_in, const int* in_sizes, int n_in,
                              void* d_out, int out_size)
{
    const float* x  = (const float*)d_in[0];
    const float* Wq = (const float*)d_in[1];
    const float* bq = (const float*)d_in[2];
    const float* Wk = (const float*)d_in[3];
    const float* bk = (const float*)d_in[4];
    const float* Wv = (const float*)d_in[5];
    const float* bv = (const float*)d_in[6];
    const float* Wo = (const float*)d_in[7];
    const float* bo = (const float*)d_in[8];
    float* out = (float*)d_out;

    cudaFuncSetAttribute(hl_gemm, cudaFuncAttributeMaxDynamicSharedMemorySize, GEMM_SMEM_BYTES);
    cudaFuncSetAttribute(attn_tc, cudaFuncAttributeMaxDynamicSharedMemorySize, ATTN_SMEM_BYTES);

    conv_hl<<<(BATCH*SEQ*INDIM)/1024, 256>>>(x, 0);
    conv_hl<<<(DMODEL*INDIM)/1024, 256>>>(Wq, 1);
    conv_hl<<<(DMODEL*INDIM)/1024, 256>>>(Wk, 2);
    conv_hl<<<(DMODEL*INDIM)/1024, 256>>>(Wv, 3);
    conv_hl<<<(DMODEL*DMODEL)/1024, 256>>>(Wo, 4);

    GemmArgs qa;
    qa.bias0 = bq; qa.bias1 = bk; qa.bias2 = bv; qa.out_o = nullptr; qa.mode = 0;
    hl_gemm<<<dim3(DMODEL/BN, (BATCH*SEQ)/BM, 3), 256, GEMM_SMEM_BYTES>>>(qa);

    attn_tc<<<dim3(SEQ/128, NHEADS, BATCH), 256, ATTN_SMEM_BYTES>>>();

    GemmArgs oa;
    oa.bias0 = bo; oa.bias1 = nullptr; oa.bias2 = nullptr; oa.out_o = out; oa.mode = 1;
    hl_gemm<<<dim3(DMODEL/BN, (BATCH*SEQ)/BM, 1), 256, GEMM_SMEM_BYTES>>>(oa);
}

// round 8
// speedup vs baseline: 2.6572x; 1.3917x over previous
#include <cuda_runtime.h>
#include <cuda_bf16.h>
#include <stdint.h>
#include <math.h>

#define BATCH  4
#define SEQ    2048
#define INDIM  1024
#define DMODEL 1024
#define NHEADS 16
#define HDIM   64
#define KTOT   1024

// ---------------------------------------------------------------------------
// Device scratch (bf16 hi/lo pairs everywhere)
// ---------------------------------------------------------------------------
#define QKV_ELE (BATCH*NHEADS*SEQ*HDIM)
__device__ __nv_bfloat16 g_Qh[QKV_ELE], g_Ql[QKV_ELE];   // [B,H,S,Dh], pre-scaled 1/8
__device__ __nv_bfloat16 g_Kh[QKV_ELE], g_Kl[QKV_ELE];
__device__ __nv_bfloat16 g_Vh[QKV_ELE], g_Vl[QKV_ELE];
__device__ __nv_bfloat16 g_AOh[BATCH*SEQ*DMODEL], g_AOl[BATCH*SEQ*DMODEL];
__device__ __nv_bfloat16 g_xh[BATCH*SEQ*INDIM],  g_xl[BATCH*SEQ*INDIM];
__device__ __nv_bfloat16 g_Wh[4][DMODEL*INDIM],  g_Wl[4][DMODEL*INDIM];

// ---------------------------------------------------------------------------
// PTX helpers
// ---------------------------------------------------------------------------
__device__ __forceinline__ uint32_t smem_u32(const void* p) {
    uint32_t a;
    asm("{ .reg .u64 t; cvta.to.shared.u64 t, %1; cvt.u32.u64 %0, t; }"
        : "=r"(a) : "l"(p));
    return a;
}
__device__ __forceinline__ void cp_async16(uint32_t dst, const void* src) {
    asm volatile("cp.async.cg.shared.global [%0], [%1], 16;" :: "r"(dst), "l"(src));
}
__device__ __forceinline__ void cp_commit()  { asm volatile("cp.async.commit_group;"); }
__device__ __forceinline__ void cp_wait0()   { asm volatile("cp.async.wait_group 0;"); }
__device__ __forceinline__ void cp_wait1()   { asm volatile("cp.async.wait_group 1;"); }

__device__ __forceinline__ void ldsm_x4(uint32_t* r, uint32_t a) {
    asm volatile("ldmatrix.sync.aligned.m8n8.x4.shared.b16 {%0,%1,%2,%3}, [%4];"
        : "=r"(r[0]), "=r"(r[1]), "=r"(r[2]), "=r"(r[3]) : "r"(a));
}
__device__ __forceinline__ void ldsm_x4_t(uint32_t* r, uint32_t a) {
    asm volatile("ldmatrix.sync.aligned.m8n8.x4.trans.shared.b16 {%0,%1,%2,%3}, [%4];"
        : "=r"(r[0]), "=r"(r[1]), "=r"(r[2]), "=r"(r[3]) : "r"(a));
}
__device__ __forceinline__ void mma_bf16(float* c, const uint32_t* a, const uint32_t* b) {
    asm volatile(
        "mma.sync.aligned.m16n8k16.row.col.f32.bf16.bf16.f32 "
        "{%0,%1,%2,%3}, {%4,%5,%6,%7}, {%8,%9}, {%0,%1,%2,%3};"
        : "+f"(c[0]), "+f"(c[1]), "+f"(c[2]), "+f"(c[3])
        : "r"(a[0]), "r"(a[1]), "r"(a[2]), "r"(a[3]), "r"(b[0]), "r"(b[1]));
}

__device__ __forceinline__ void split_hl(float v, __nv_bfloat16& h, __nv_bfloat16& l) {
    h = __float2bfloat16(v);
    l = __float2bfloat16(v - __bfloat162float(h));
}
__device__ __forceinline__ void pack_hl2(float x, float y, uint32_t& hp, uint32_t& lp) {
    __nv_bfloat16 hx, lx, hy, ly;
    split_hl(x, hx, lx); split_hl(y, hy, ly);
    hp = ((uint32_t)__bfloat16_as_ushort(hy) << 16) | __bfloat16_as_ushort(hx);
    lp = ((uint32_t)__bfloat16_as_ushort(ly) << 16) | __bfloat16_as_ushort(lx);
}

// ---------------------------------------------------------------------------
// fp32 -> bf16 hi/lo converters
// ---------------------------------------------------------------------------
__global__ __launch_bounds__(256) void conv_x(const float* __restrict__ src)
{
    size_t i = ((size_t)blockIdx.x * 256 + threadIdx.x) * 4;
    float4 v = *(const float4*)(src + i);
    __nv_bfloat16 h0, h1, h2, h3, l0, l1, l2, l3;
    split_hl(v.x, h0, l0); split_hl(v.y, h1, l1);
    split_hl(v.z, h2, l2); split_hl(v.w, h3, l3);
    g_xh[i+0] = h0; g_xh[i+1] = h1; g_xh[i+2] = h2; g_xh[i+3] = h3;
    g_xl[i+0] = l0; g_xl[i+1] = l1; g_xl[i+2] = l2; g_xl[i+3] = l3;
}

__global__ __launch_bounds__(256) void conv_w4(
    const float* __restrict__ Wq, const float* __restrict__ Wk,
    const float* __restrict__ Wv, const float* __restrict__ Wo)
{
    const int w = blockIdx.y;
    const float* src = (w == 0) ? Wq : (w == 1) ? Wk : (w == 2) ? Wv : Wo;
    __nv_bfloat16* h = g_Wh[w];
    __nv_bfloat16* l = g_Wl[w];
    size_t i = ((size_t)blockIdx.x * 256 + threadIdx.x) * 4;
    float4 v = *(const float4*)(src + i);
    __nv_bfloat16 h0, h1, h2, h3, l0, l1, l2, l3;
    split_hl(v.x, h0, l0); split_hl(v.y, h1, l1);
    split_hl(v.z, h2, l2); split_hl(v.w, h3, l3);
    h[i+0] = h0; h[i+1] = h1; h[i+2] = h2; h[i+3] = h3;
    l[i+0] = l0; l[i+1] = l1; l[i+2] = l2; l[i+3] = l3;
}

// ---------------------------------------------------------------------------
// Raw-MMA split-bf16 GEMM: C[m,n] = sum_k A[m,k]*W[n,k] + bias[n]
// 128x128 block, 8 warps (warp tile 64x32), BK=32, 3-stage cp.async pipeline,
// one __syncthreads per K-iter, register epilogue.
// mode 0: QKV -> bf16 hi/lo scatter into [B,H,S,Dh] (Q scaled 1/8)
// mode 1: O-proj -> fp32 out
// ---------------------------------------------------------------------------
#define BM 128
#define BN 128
#define BK 32
#define NCH (KTOT/BK)          // 32
#define LDK 40                 // smem row stride (80B: ldmatrix conflict-free)
#define TILE_E (128*LDK)       // 5120 elems / tile
#define STAGE_E (4*TILE_E)     // Ah, Al, Bh, Bl
#define NSTAGE 3
#define GEMM_SMEM_BYTES (NSTAGE*STAGE_E*2)   // 122880

struct GemmArgs {
    const float* bias0; const float* bias1; const float* bias2;
    float* out_o;
    int mode;
};

__global__ __launch_bounds__(256) void hl_gemm(GemmArgs args)
{
    extern __shared__ __align__(16) char dsm[];
    __nv_bfloat16* smT = (__nv_bfloat16*)dsm;

    const int t    = threadIdx.x;
    const int wid  = t >> 5;
    const int lane = t & 31;
    const int z    = blockIdx.z;
    const int m0   = blockIdx.y * BM;
    const int n0   = blockIdx.x * BN;
    const int wm   = wid & 1;      // warp row (64)
    const int wn   = wid >> 1;     // warp col (32)

    const __nv_bfloat16 *Ah, *Al, *Bh, *Bl;
    const float* bias;
    if (args.mode == 0) {
        Ah = g_xh; Al = g_xl;
        Bh = g_Wh[z]; Bl = g_Wl[z];
        bias = (z == 0) ? args.bias0 : (z == 1) ? args.bias1 : args.bias2;
    } else {
        Ah = g_AOh; Al = g_AOl;
        Bh = g_Wh[3]; Bl = g_Wl[3];
        bias = args.bias0;
    }
    const __nv_bfloat16* srcs[4] = { Ah, Al, Bh, Bl };
    const int r0s[4] = { m0, m0, n0, n0 };

    const uint32_t ub = smem_u32(smT);

    // ldmatrix per-lane byte offsets within a tile
    // A (row-major m16 x k16):
    const uint32_t abase = (uint32_t)(((wm*64 + (lane & 15)) * LDK + ((lane >> 4) << 3)) * 2);
    // B ([n][k] rows, x4 covers n16 x k16):
    const uint32_t bbase = (uint32_t)(((wn*32 + ((lane >> 4) << 3) + (lane & 7)) * LDK
                                      + (((lane >> 3) & 1) << 3)) * 2);

    float c[4][4][4];
#pragma unroll
    for (int mi = 0; mi < 4; mi++)
#pragma unroll
        for (int nj = 0; nj < 4; nj++)
#pragma unroll
            for (int r = 0; r < 4; r++) c[mi][nj][r] = 0.f;

    // stage fill: 4 tiles x 128 rows x 2 chunks(16B)... = 2048 chunks, 8/thread
    auto load_stage = [&](int stage, int kc) {
#pragma unroll
        for (int it = 0; it < 8; it++) {
            int idx  = t + it * 256;
            int tile = idx >> 9;
            int rem  = idx & 511;
            int row  = rem >> 2;
            int ch   = rem & 3;
            const __nv_bfloat16* sp = srcs[tile]
                + (size_t)(r0s[tile] + row) * KTOT + kc * BK + ch * 8;
            uint32_t dp = ub + (uint32_t)((stage * 4 + tile) * TILE_E + row * LDK + ch * 8) * 2;
            cp_async16(dp, sp);
        }
        cp_commit();
    };

    load_stage(0, 0);
    load_stage(1, 1);

    for (int kc = 0; kc < NCH; kc++) {
        if (kc + 1 < NCH) cp_wait1(); else cp_wait0();
        __syncthreads();
        if (kc + 2 < NCH) load_stage((kc + 2) % NSTAGE, kc + 2);

        const int s = kc % NSTAGE;
        const uint32_t uAh = ub + (uint32_t)((s*4 + 0) * TILE_E) * 2;
        const uint32_t uAl = ub + (uint32_t)((s*4 + 1) * TILE_E) * 2;
        const uint32_t uBh = ub + (uint32_t)((s*4 + 2) * TILE_E) * 2;
        const uint32_t uBl = ub + (uint32_t)((s*4 + 3) * TILE_E) * 2;

#pragma unroll
        for (int ks = 0; ks < 2; ks++) {
            uint32_t bh[2][4], bl[2][4];
#pragma unroll
            for (int j2 = 0; j2 < 2; j2++) {
                ldsm_x4(bh[j2], uBh + bbase + (uint32_t)(j2 * 16 * LDK * 2) + ks * 32);
                ldsm_x4(bl[j2], uBl + bbase + (uint32_t)(j2 * 16 * LDK * 2) + ks * 32);
            }
#pragma unroll
            for (int mi = 0; mi < 4; mi++) {
                uint32_t ah[4], al[4];
                ldsm_x4(ah, uAh + abase + (uint32_t)(mi * 16 * LDK * 2) + ks * 32);
                ldsm_x4(al, uAl + abase + (uint32_t)(mi * 16 * LDK * 2) + ks * 32);
#pragma unroll
                for (int nj = 0; nj < 4; nj++) {
                    const uint32_t* pbh = &bh[nj >> 1][(nj & 1) * 2];
                    const uint32_t* pbl = &bl[nj >> 1][(nj & 1) * 2];
                    mma_bf16(c[mi][nj], ah, pbh);
                    mma_bf16(c[mi][nj], ah, pbl);
                    mma_bf16(c[mi][nj], al, pbh);
                }
            }
        }
    }

    // -------- register epilogue --------
    const float qscale = (args.mode == 0 && z == 0) ? 0.125f : 1.0f;
    // per-nj column constants
    float2 bv[4];
    int nn[4];
#pragma unroll
    for (int nj = 0; nj < 4; nj++) {
        nn[nj] = n0 + wn*32 + nj*8 + (lane & 3)*2;
        bv[nj] = *(const float2*)&bias[nn[nj]];
    }

    if (args.mode == 0) {
        __nv_bfloat16 *dh_, *dl_;
        if (z == 0)      { dh_ = g_Qh; dl_ = g_Ql; }
        else if (z == 1) { dh_ = g_Kh; dl_ = g_Kl; }
        else             { dh_ = g_Vh; dl_ = g_Vl; }
#pragma unroll
        for (int mi = 0; mi < 4; mi++) {
#pragma unroll
            for (int half = 0; half < 2; half++) {
                const int m  = m0 + wm*64 + mi*16 + (lane >> 2) + half*8;
                const int bb = m >> 11;
                const int ss = m & (SEQ - 1);
#pragma unroll
                for (int nj = 0; nj < 4; nj++) {
                    const int n  = nn[nj];
                    const int h  = n >> 6;
                    const int dh = n & 63;
                    const float v0 = (c[mi][nj][half*2+0] + bv[nj].x) * qscale;
                    const float v1 = (c[mi][nj][half*2+1] + bv[nj].y) * qscale;
                    uint32_t hp, lp;
                    pack_hl2(v0, v1, hp, lp);
                    const size_t off = (((size_t)bb * NHEADS + h) * SEQ + ss) * HDIM + dh;
                    *(uint32_t*)(dh_ + off) = hp;
                    *(uint32_t*)(dl_ + off) = lp;
                }
            }
        }
    } else {
        float* outp = args.out_o;
#pragma unroll
        for (int mi = 0; mi < 4; mi++) {
#pragma unroll
            for (int half = 0; half < 2; half++) {
                const int m = m0 + wm*64 + mi*16 + (lane >> 2) + half*8;
#pragma unroll
                for (int nj = 0; nj < 4; nj++) {
                    const float v0 = c[mi][nj][half*2+0] + bv[nj].x;
                    const float v1 = c[mi][nj][half*2+1] + bv[nj].y;
                    *(float2*)(outp + (size_t)m * DMODEL + nn[nj]) = make_float2(v0, v1);
                }
            }
        }
    }
}

// ---------------------------------------------------------------------------
// Register-resident causal flash attention (unchanged from R7)
// ---------------------------------------------------------------------------
#define ASTR 72
#define ATTN_SMEM_BYTES 73728

__global__ __launch_bounds__(256, 2) void attn_tc()
{
    extern __shared__ __align__(16) char asmem[];
    __nv_bfloat16* sQh = (__nv_bfloat16*)(asmem);
    __nv_bfloat16* sQl = (__nv_bfloat16*)(asmem + 18432);
    __nv_bfloat16* sKh = (__nv_bfloat16*)(asmem + 36864);
    __nv_bfloat16* sKl = (__nv_bfloat16*)(asmem + 46080);
    __nv_bfloat16* sVh = (__nv_bfloat16*)(asmem + 55296);
    __nv_bfloat16* sVl = (__nv_bfloat16*)(asmem + 64512);

    const int t    = threadIdx.x;
    const int wid  = t >> 5;
    const int lane = t & 31;
    const int bq   = blockIdx.x;
    const int h    = blockIdx.y;
    const int bb   = blockIdx.z;
    const int q0   = bq * 128;
    const size_t base = ((size_t)bb * NHEADS + h) * SEQ * HDIM;

#pragma unroll
    for (int it = 0; it < 4; it++) {
        int idx = t + it * 256;
        int row = idx >> 3, ch = idx & 7;
        *(uint4*)(sQh + row*ASTR + ch*8) = *(const uint4*)(g_Qh + base + (size_t)(q0+row)*HDIM + ch*8);
        *(uint4*)(sQl + row*ASTR + ch*8) = *(const uint4*)(g_Ql + base + (size_t)(q0+row)*HDIM + ch*8);
    }
    __syncthreads();

    const uint32_t uQh = smem_u32(sQh), uQl = smem_u32(sQl);
    const uint32_t uKh = smem_u32(sKh), uKl = smem_u32(sKl);
    const uint32_t uVh = smem_u32(sVh), uVl = smem_u32(sVl);

    const uint32_t aoff = (uint32_t)(((wid*16 + (lane & 15)) * ASTR + ((lane >> 4) << 3)) * 2);
    const uint32_t kboff = (uint32_t)(((((lane >> 4) << 3) + (lane & 7)) * ASTR + (((lane >> 3) & 1) << 3)) * 2);
    const uint32_t vboff = (uint32_t)((((((lane >> 3) & 1) << 3) + (lane & 7)) * ASTR + ((lane >> 4) << 3)) * 2);

    float o[8][4];
#pragma unroll
    for (int j = 0; j < 8; j++)
#pragma unroll
        for (int r = 0; r < 4; r++) o[j][r] = 0.f;

    const int rA = q0 + wid*16 + (lane >> 2);
    const int rB = rA + 8;
    const int qwmin = q0 + wid*16;
    const int qwmax = qwmin + 15;
    float mA = -1e30f, mB = -1e30f, lA = 0.f, lB = 0.f;

    const int nkt = 2*bq + 2;
    for (int kt = 0; kt < nkt; kt++) {
        const int k0 = kt * 64;

        {
            const __nv_bfloat16* gsrc[4] = { g_Kh, g_Kl, g_Vh, g_Vl };
            __nv_bfloat16* sdst[4] = { sKh, sKl, sVh, sVl };
#pragma unroll
            for (int it = 0; it < 8; it++) {
                int idx = t + it * 256;
                int a   = idx >> 9;
                int rem = idx & 511;
                int row = rem >> 3, ch = rem & 7;
                *(uint4*)(sdst[a] + row*ASTR + ch*8) =
                    *(const uint4*)(gsrc[a] + base + (size_t)(k0+row)*HDIM + ch*8);
            }
        }
        __syncthreads();

        if (k0 <= qwmax) {
            float c[8][4];
#pragma unroll
            for (int j = 0; j < 8; j++)
#pragma unroll
                for (int r = 0; r < 4; r++) c[j][r] = 0.f;

#pragma unroll
            for (int ks = 0; ks < 4; ks++) {
                uint32_t ah[4], al[4];
                ldsm_x4(ah, uQh + aoff + ks*32);
                ldsm_x4(al, uQl + aoff + ks*32);
#pragma unroll
                for (int jp = 0; jp < 4; jp++) {
                    uint32_t bh[4], bl[4];
                    ldsm_x4(bh, uKh + kboff + (uint32_t)(jp*16*ASTR*2) + ks*32);
                    ldsm_x4(bl, uKl + kboff + (uint32_t)(jp*16*ASTR*2) + ks*32);
                    mma_bf16(c[2*jp],   ah, bh);
                    mma_bf16(c[2*jp],   ah, bl);
                    mma_bf16(c[2*jp],   al, bh);
                    mma_bf16(c[2*jp+1], ah, bh+2);
                    mma_bf16(c[2*jp+1], ah, bl+2);
                    mma_bf16(c[2*jp+1], al, bh+2);
                }
            }

            if (k0 + 63 > qwmin) {
#pragma unroll
                for (int j = 0; j < 8; j++) {
                    int colb = k0 + j*8 + (lane & 3)*2;
                    if (colb     > rA) c[j][0] = -1e30f;
                    if (colb + 1 > rA) c[j][1] = -1e30f;
                    if (colb     > rB) c[j][2] = -1e30f;
                    if (colb + 1 > rB) c[j][3] = -1e30f;
                }
            }

            float vmA = -1e30f, vmB = -1e30f;
#pragma unroll
            for (int j = 0; j < 8; j++) {
                vmA = fmaxf(vmA, fmaxf(c[j][0], c[j][1]));
                vmB = fmaxf(vmB, fmaxf(c[j][2], c[j][3]));
            }
            vmA = fmaxf(vmA, __shfl_xor_sync(0xffffffffu, vmA, 1));
            vmA = fmaxf(vmA, __shfl_xor_sync(0xffffffffu, vmA, 2));
            vmB = fmaxf(vmB, __shfl_xor_sync(0xffffffffu, vmB, 1));
            vmB = fmaxf(vmB, __shfl_xor_sync(0xffffffffu, vmB, 2));
            const float mnA = fmaxf(mA, vmA);
            const float mnB = fmaxf(mB, vmB);

            float sA = 0.f, sB = 0.f;
#pragma unroll
            for (int j = 0; j < 8; j++) {
                c[j][0] = __expf(c[j][0] - mnA);
                c[j][1] = __expf(c[j][1] - mnA);
                c[j][2] = __expf(c[j][2] - mnB);
                c[j][3] = __expf(c[j][3] - mnB);
                sA += c[j][0] + c[j][1];
                sB += c[j][2] + c[j][3];
            }
            sA += __shfl_xor_sync(0xffffffffu, sA, 1);
            sA += __shfl_xor_sync(0xffffffffu, sA, 2);
            sB += __shfl_xor_sync(0xffffffffu, sB, 1);
            sB += __shfl_xor_sync(0xffffffffu, sB, 2);

            const float soA = __expf(mA - mnA);
            const float soB = __expf(mB - mnB);
            lA = lA * soA + sA;  mA = mnA;
            lB = lB * soB + sB;  mB = mnB;

#pragma unroll
            for (int j = 0; j < 8; j++) {
                o[j][0] *= soA; o[j][1] *= soA;
                o[j][2] *= soB; o[j][3] *= soB;
            }

#pragma unroll
            for (int kk = 0; kk < 4; kk++) {
                uint32_t ph[4], pl[4];
                pack_hl2(c[2*kk][0],   c[2*kk][1],   ph[0], pl[0]);
                pack_hl2(c[2*kk][2],   c[2*kk][3],   ph[1], pl[1]);
                pack_hl2(c[2*kk+1][0], c[2*kk+1][1], ph[2], pl[2]);
                pack_hl2(c[2*kk+1][2], c[2*kk+1][3], ph[3], pl[3]);
#pragma unroll
                for (int jp = 0; jp < 4; jp++) {
                    uint32_t vh[4], vl[4];
                    ldsm_x4_t(vh, uVh + vboff + (uint32_t)(kk*16*ASTR*2) + jp*32);
                    ldsm_x4_t(vl, uVl + vboff + (uint32_t)(kk*16*ASTR*2) + jp*32);
                    mma_bf16(o[2*jp],   ph, vh);
                    mma_bf16(o[2*jp],   ph, vl);
                    mma_bf16(o[2*jp],   pl, vh);
                    mma_bf16(o[2*jp+1], ph, vh+2);
                    mma_bf16(o[2*jp+1], ph, vl+2);
                    mma_bf16(o[2*jp+1], pl, vh+2);
                }
            }
        }
        __syncthreads();
    }

    {
        const float invA = 1.f / lA;
        const float invB = 1.f / lB;
        const size_t offA = ((size_t)bb * SEQ + rA) * DMODEL + h * HDIM + (lane & 3) * 2;
        const size_t offB = ((size_t)bb * SEQ + rB) * DMODEL + h * HDIM + (lane & 3) * 2;
#pragma unroll
        for (int j = 0; j < 8; j++) {
            uint32_t hp, lp;
            pack_hl2(o[j][0] * invA, o[j][1] * invA, hp, lp);
            *(uint32_t*)(g_AOh + offA + j*8) = hp;
            *(uint32_t*)(g_AOl + offA + j*8) = lp;
            pack_hl2(o[j][2] * invB, o[j][3] * invB, hp, lp);
            *(uint32_t*)(g_AOh + offB + j*8) = hp;
            *(uint32_t*)(g_AOl + offB + j*8) = lp;
        }
    }
}

// ---------------------------------------------------------------------------
extern "C" void kernel_launch(void* const* d_in, const int* in_sizes, int n_in,
                              void* d_out, int out_size)
{
    const float* x  = (const float*)d_in[0];
    const float* Wq = (const float*)d_in[1];
    const float* bq = (const float*)d_in[2];
    const float* Wk = (const float*)d_in[3];
    const float* bk = (const float*)d_in[4];
    const float* Wv = (const float*)d_in[5];
    const float* bv = (const float*)d_in[6];
    const float* Wo = (const float*)d_in[7];
    const float* bo = (const float*)d_in[8];
    float* out = (float*)d_out;

    cudaFuncSetAttribute(hl_gemm, cudaFuncAttributeMaxDynamicSharedMemorySize, GEMM_SMEM_BYTES);
    cudaFuncSetAttribute(attn_tc, cudaFuncAttributeMaxDynamicSharedMemorySize, ATTN_SMEM_BYTES);

    conv_x<<<(BATCH*SEQ*INDIM)/1024, 256>>>(x);
    conv_w4<<<dim3((DMODEL*INDIM)/1024, 4), 256>>>(Wq, Wk, Wv, Wo);

    GemmArgs qa;
    qa.bias0 = bq; qa.bias1 = bk; qa.bias2 = bv; qa.out_o = nullptr; qa.mode = 0;
    hl_gemm<<<dim3(DMODEL/BN, (BATCH*SEQ)/BM, 3), 256, GEMM_SMEM_BYTES>>>(qa);

    attn_tc<<<dim3(SEQ/128, NHEADS, BATCH), 256, ATTN_SMEM_BYTES>>>();

    GemmArgs oa;
    oa.bias0 = bo; oa.bias1 = nullptr; oa.bias2 = nullptr; oa.out_o = out; oa.mode = 1;
    hl_gemm<<<dim3(DMODEL/BN, (BATCH*SEQ)/BM, 1), 256, GEMM_SMEM_BYTES>>>(oa);
}

// round 9
// speedup vs baseline: 2.9993x; 1.1288x over previous
#include <cuda_runtime.h>
#include <cuda_bf16.h>
#include <stdint.h>
#include <math.h>

#define BATCH  4
#define SEQ    2048
#define INDIM  1024
#define DMODEL 1024
#define NHEADS 16
#define HDIM   64
#define KTOT   1024

// ---------------------------------------------------------------------------
// Device scratch (bf16 hi/lo pairs everywhere)
// ---------------------------------------------------------------------------
#define QKV_ELE (BATCH*NHEADS*SEQ*HDIM)
__device__ __nv_bfloat16 g_Qh[QKV_ELE], g_Ql[QKV_ELE];   // [B,H,S,Dh], pre-scaled 1/8
__device__ __nv_bfloat16 g_Kh[QKV_ELE], g_Kl[QKV_ELE];
__device__ __nv_bfloat16 g_Vh[QKV_ELE], g_Vl[QKV_ELE];
__device__ __nv_bfloat16 g_AOh[BATCH*SEQ*DMODEL], g_AOl[BATCH*SEQ*DMODEL];
__device__ __nv_bfloat16 g_xh[BATCH*SEQ*INDIM],  g_xl[BATCH*SEQ*INDIM];
__device__ __nv_bfloat16 g_Wh[4][DMODEL*INDIM],  g_Wl[4][DMODEL*INDIM];

// ---------------------------------------------------------------------------
// PTX helpers
// ---------------------------------------------------------------------------
__device__ __forceinline__ uint32_t smem_u32(const void* p) {
    uint32_t a;
    asm("{ .reg .u64 t; cvta.to.shared.u64 t, %1; cvt.u32.u64 %0, t; }"
        : "=r"(a) : "l"(p));
    return a;
}
__device__ __forceinline__ void cp_async16(uint32_t dst, const void* src) {
    asm volatile("cp.async.cg.shared.global [%0], [%1], 16;" :: "r"(dst), "l"(src));
}
__device__ __forceinline__ void cp_commit()  { asm volatile("cp.async.commit_group;"); }
__device__ __forceinline__ void cp_wait0()   { asm volatile("cp.async.wait_group 0;"); }

__device__ __forceinline__ void ldsm_x4(uint32_t* r, uint32_t a) {
    asm volatile("ldmatrix.sync.aligned.m8n8.x4.shared.b16 {%0,%1,%2,%3}, [%4];"
        : "=r"(r[0]), "=r"(r[1]), "=r"(r[2]), "=r"(r[3]) : "r"(a));
}
__device__ __forceinline__ void ldsm_x4_t(uint32_t* r, uint32_t a) {
    asm volatile("ldmatrix.sync.aligned.m8n8.x4.trans.shared.b16 {%0,%1,%2,%3}, [%4];"
        : "=r"(r[0]), "=r"(r[1]), "=r"(r[2]), "=r"(r[3]) : "r"(a));
}
__device__ __forceinline__ void mma_bf16(float* c, const uint32_t* a, const uint32_t* b) {
    asm volatile(
        "mma.sync.aligned.m16n8k16.row.col.f32.bf16.bf16.f32 "
        "{%0,%1,%2,%3}, {%4,%5,%6,%7}, {%8,%9}, {%0,%1,%2,%3};"
        : "+f"(c[0]), "+f"(c[1]), "+f"(c[2]), "+f"(c[3])
        : "r"(a[0]), "r"(a[1]), "r"(a[2]), "r"(a[3]), "r"(b[0]), "r"(b[1]));
}

__device__ __forceinline__ void split_hl(float v, __nv_bfloat16& h, __nv_bfloat16& l) {
    h = __float2bfloat16(v);
    l = __float2bfloat16(v - __bfloat162float(h));
}
__device__ __forceinline__ void pack_hl2(float x, float y, uint32_t& hp, uint32_t& lp) {
    __nv_bfloat16 hx, lx, hy, ly;
    split_hl(x, hx, lx); split_hl(y, hy, ly);
    hp = ((uint32_t)__bfloat16_as_ushort(hy) << 16) | __bfloat16_as_ushort(hx);
    lp = ((uint32_t)__bfloat16_as_ushort(ly) << 16) | __bfloat16_as_ushort(lx);
}

// ---------------------------------------------------------------------------
// fp32 -> bf16 hi/lo converters
// ---------------------------------------------------------------------------
__global__ __launch_bounds__(256) void conv_x(const float* __restrict__ src)
{
    size_t i = ((size_t)blockIdx.x * 256 + threadIdx.x) * 4;
    float4 v = *(const float4*)(src + i);
    __nv_bfloat16 h0, h1, h2, h3, l0, l1, l2, l3;
    split_hl(v.x, h0, l0); split_hl(v.y, h1, l1);
    split_hl(v.z, h2, l2); split_hl(v.w, h3, l3);
    g_xh[i+0] = h0; g_xh[i+1] = h1; g_xh[i+2] = h2; g_xh[i+3] = h3;
    g_xl[i+0] = l0; g_xl[i+1] = l1; g_xl[i+2] = l2; g_xl[i+3] = l3;
}

__global__ __launch_bounds__(256) void conv_w4(
    const float* __restrict__ Wq, const float* __restrict__ Wk,
    const float* __restrict__ Wv, const float* __restrict__ Wo)
{
    const int w = blockIdx.y;
    const float* src = (w == 0) ? Wq : (w == 1) ? Wk : (w == 2) ? Wv : Wo;
    __nv_bfloat16* h = g_Wh[w];
    __nv_bfloat16* l = g_Wl[w];
    size_t i = ((size_t)blockIdx.x * 256 + threadIdx.x) * 4;
    float4 v = *(const float4*)(src + i);
    __nv_bfloat16 h0, h1, h2, h3, l0, l1, l2, l3;
    split_hl(v.x, h0, l0); split_hl(v.y, h1, l1);
    split_hl(v.z, h2, l2); split_hl(v.w, h3, l3);
    h[i+0] = h0; h[i+1] = h1; h[i+2] = h2; h[i+3] = h3;
    l[i+0] = l0; l[i+1] = l1; l[i+2] = l2; l[i+3] = l3;
}

// ---------------------------------------------------------------------------
// Raw-MMA split-bf16 GEMM: 128x128 block, 8 warps, BK=32, 2-stage cp.async,
// 2 CTAs/SM, one barrier per K-iter, register epilogue.
// ---------------------------------------------------------------------------
#define BM 128
#define BN 128
#define BK 32
#define NCH (KTOT/BK)          // 32
#define LDK 40                 // smem row stride (80B: ldmatrix conflict-free)
#define TILE_E (128*LDK)
#define STAGE_E (4*TILE_E)
#define GEMM_SMEM_BYTES (2*STAGE_E*2)   // 81920

struct GemmArgs {
    const float* bias0; const float* bias1; const float* bias2;
    float* out_o;
    int mode;
};

__global__ __launch_bounds__(256, 2) void hl_gemm(GemmArgs args)
{
    extern __shared__ __align__(16) char dsm[];
    __nv_bfloat16* smT = (__nv_bfloat16*)dsm;

    const int t    = threadIdx.x;
    const int wid  = t >> 5;
    const int lane = t & 31;
    const int z    = blockIdx.z;
    const int m0   = blockIdx.y * BM;
    const int n0   = blockIdx.x * BN;
    const int wm   = wid & 1;
    const int wn   = wid >> 1;

    const __nv_bfloat16 *Ah, *Al, *Bh, *Bl;
    const float* bias;
    if (args.mode == 0) {
        Ah = g_xh; Al = g_xl;
        Bh = g_Wh[z]; Bl = g_Wl[z];
        bias = (z == 0) ? args.bias0 : (z == 1) ? args.bias1 : args.bias2;
    } else {
        Ah = g_AOh; Al = g_AOl;
        Bh = g_Wh[3]; Bl = g_Wl[3];
        bias = args.bias0;
    }
    const __nv_bfloat16* srcs[4] = { Ah, Al, Bh, Bl };
    const int r0s[4] = { m0, m0, n0, n0 };

    const uint32_t ub = smem_u32(smT);
    const uint32_t abase = (uint32_t)(((wm*64 + (lane & 15)) * LDK + ((lane >> 4) << 3)) * 2);
    const uint32_t bbase = (uint32_t)(((wn*32 + ((lane >> 4) << 3) + (lane & 7)) * LDK
                                      + (((lane >> 3) & 1) << 3)) * 2);

    float c[4][4][4];
#pragma unroll
    for (int mi = 0; mi < 4; mi++)
#pragma unroll
        for (int nj = 0; nj < 4; nj++)
#pragma unroll
            for (int r = 0; r < 4; r++) c[mi][nj][r] = 0.f;

    auto load_stage = [&](int stage, int kc) {
#pragma unroll
        for (int it = 0; it < 8; it++) {
            int idx  = t + it * 256;
            int tile = idx >> 9;
            int rem  = idx & 511;
            int row  = rem >> 2;
            int ch   = rem & 3;
            const __nv_bfloat16* sp = srcs[tile]
                + (size_t)(r0s[tile] + row) * KTOT + kc * BK + ch * 8;
            uint32_t dp = ub + (uint32_t)((stage * 4 + tile) * TILE_E + row * LDK + ch * 8) * 2;
            cp_async16(dp, sp);
        }
        cp_commit();
    };

    load_stage(0, 0);

    for (int kc = 0; kc < NCH; kc++) {
        cp_wait0();
        __syncthreads();
        if (kc + 1 < NCH) load_stage((kc + 1) & 1, kc + 1);

        const int s = kc & 1;
        const uint32_t uAh = ub + (uint32_t)((s*4 + 0) * TILE_E) * 2;
        const uint32_t uAl = ub + (uint32_t)((s*4 + 1) * TILE_E) * 2;
        const uint32_t uBh = ub + (uint32_t)((s*4 + 2) * TILE_E) * 2;
        const uint32_t uBl = ub + (uint32_t)((s*4 + 3) * TILE_E) * 2;

#pragma unroll
        for (int ks = 0; ks < 2; ks++) {
            uint32_t bh[2][4], bl[2][4];
#pragma unroll
            for (int j2 = 0; j2 < 2; j2++) {
                ldsm_x4(bh[j2], uBh + bbase + (uint32_t)(j2 * 16 * LDK * 2) + ks * 32);
                ldsm_x4(bl[j2], uBl + bbase + (uint32_t)(j2 * 16 * LDK * 2) + ks * 32);
            }
#pragma unroll
            for (int mi = 0; mi < 4; mi++) {
                uint32_t ah[4], al[4];
                ldsm_x4(ah, uAh + abase + (uint32_t)(mi * 16 * LDK * 2) + ks * 32);
                ldsm_x4(al, uAl + abase + (uint32_t)(mi * 16 * LDK * 2) + ks * 32);
#pragma unroll
                for (int nj = 0; nj < 4; nj++) {
                    const uint32_t* pbh = &bh[nj >> 1][(nj & 1) * 2];
                    const uint32_t* pbl = &bl[nj >> 1][(nj & 1) * 2];
                    mma_bf16(c[mi][nj], ah, pbh);
                    mma_bf16(c[mi][nj], ah, pbl);
                    mma_bf16(c[mi][nj], al, pbh);
                }
            }
        }
    }

    // -------- register epilogue --------
    const float qscale = (args.mode == 0 && z == 0) ? 0.125f : 1.0f;
    float2 bv[4];
    int nn[4];
#pragma unroll
    for (int nj = 0; nj < 4; nj++) {
        nn[nj] = n0 + wn*32 + nj*8 + (lane & 3)*2;
        bv[nj] = *(const float2*)&bias[nn[nj]];
    }

    if (args.mode == 0) {
        __nv_bfloat16 *dh_, *dl_;
        if (z == 0)      { dh_ = g_Qh; dl_ = g_Ql; }
        else if (z == 1) { dh_ = g_Kh; dl_ = g_Kl; }
        else             { dh_ = g_Vh; dl_ = g_Vl; }
#pragma unroll
        for (int mi = 0; mi < 4; mi++) {
#pragma unroll
            for (int half = 0; half < 2; half++) {
                const int m  = m0 + wm*64 + mi*16 + (lane >> 2) + half*8;
                const int bb = m >> 11;
                const int ss = m & (SEQ - 1);
#pragma unroll
                for (int nj = 0; nj < 4; nj++) {
                    const int n  = nn[nj];
                    const int h  = n >> 6;
                    const int dh = n & 63;
                    const float v0 = (c[mi][nj][half*2+0] + bv[nj].x) * qscale;
                    const float v1 = (c[mi][nj][half*2+1] + bv[nj].y) * qscale;
                    uint32_t hp, lp;
                    pack_hl2(v0, v1, hp, lp);
                    const size_t off = (((size_t)bb * NHEADS + h) * SEQ + ss) * HDIM + dh;
                    *(uint32_t*)(dh_ + off) = hp;
                    *(uint32_t*)(dl_ + off) = lp;
                }
            }
        }
    } else {
        float* outp = args.out_o;
#pragma unroll
        for (int mi = 0; mi < 4; mi++) {
#pragma unroll
            for (int half = 0; half < 2; half++) {
                const int m = m0 + wm*64 + mi*16 + (lane >> 2) + half*8;
#pragma unroll
                for (int nj = 0; nj < 4; nj++) {
                    const float v0 = c[mi][nj][half*2+0] + bv[nj].x;
                    const float v1 = c[mi][nj][half*2+1] + bv[nj].y;
                    *(float2*)(outp + (size_t)m * DMODEL + nn[nj]) = make_float2(v0, v1);
                }
            }
        }
    }
}

// ---------------------------------------------------------------------------
// Register-resident causal flash attention, cp.async double-buffered K/V.
// SMEM: Qh/Ql 128x72 (36864) + 2 KV buffers (Kh,Kl,Vh,Vl 64x72 = 36864 each).
// ---------------------------------------------------------------------------
#define ASTR 72
#define KVBUF 36864
#define ATTN_SMEM_BYTES (36864 + 2*KVBUF)   // 110592

__global__ __launch_bounds__(256, 2) void attn_tc()
{
    extern __shared__ __align__(16) char asmem[];
    __nv_bfloat16* sQh = (__nv_bfloat16*)(asmem);
    __nv_bfloat16* sQl = (__nv_bfloat16*)(asmem + 18432);

    const int t    = threadIdx.x;
    const int wid  = t >> 5;
    const int lane = t & 31;
    const int bq   = gridDim.x - 1 - blockIdx.x;   // heavy tiles first
    const int h    = blockIdx.y;
    const int bb   = blockIdx.z;
    const int q0   = bq * 128;
    const size_t base = ((size_t)bb * NHEADS + h) * SEQ * HDIM;

    const __nv_bfloat16* gsrc[4] = { g_Kh, g_Kl, g_Vh, g_Vl };

    // KV tile loader (cp.async, one commit group)
    auto load_kv = [&](int buf, int k0) {
        char* dst0 = asmem + 36864 + buf * KVBUF;
#pragma unroll
        for (int it = 0; it < 8; it++) {
            int idx = t + it * 256;
            int a   = idx >> 9;
            int rem = idx & 511;
            int row = rem >> 3, ch = rem & 7;
            uint32_t dp = smem_u32(dst0 + a * 9216 + (row * ASTR + ch * 8) * 2);
            cp_async16(dp, gsrc[a] + base + (size_t)(k0 + row) * HDIM + ch * 8);
        }
        cp_commit();
    };

    // Q loader (cp.async, own group)
    {
#pragma unroll
        for (int it = 0; it < 8; it++) {
            int idx = t + it * 256;          // 0..2047: 2 arrays x 128 rows x 8 chunks
            int a   = idx >> 10;
            int rem = idx & 1023;
            int row = rem >> 3, ch = rem & 7;
            const __nv_bfloat16* src = (a == 0 ? g_Qh : g_Ql) + base + (size_t)(q0 + row) * HDIM + ch * 8;
            uint32_t dp = smem_u32(asmem + a * 18432 + (row * ASTR + ch * 8) * 2);
            cp_async16(dp, src);
        }
        cp_commit();
    }
    load_kv(0, 0);

    const uint32_t uQh = smem_u32(sQh), uQl = smem_u32(sQl);
    const uint32_t aoff  = (uint32_t)(((wid*16 + (lane & 15)) * ASTR + ((lane >> 4) << 3)) * 2);
    const uint32_t kboff = (uint32_t)(((((lane >> 4) << 3) + (lane & 7)) * ASTR + (((lane >> 3) & 1) << 3)) * 2);
    const uint32_t vboff = (uint32_t)((((((lane >> 3) & 1) << 3) + (lane & 7)) * ASTR + ((lane >> 4) << 3)) * 2);

    float o[8][4];
#pragma unroll
    for (int j = 0; j < 8; j++)
#pragma unroll
        for (int r = 0; r < 4; r++) o[j][r] = 0.f;

    const int rA = q0 + wid*16 + (lane >> 2);
    const int rB = rA + 8;
    const int qwmin = q0 + wid*16;
    const int qwmax = qwmin + 15;
    float mA = -1e30f, mB = -1e30f, lA = 0.f, lB = 0.f;

    const int nkt = 2*bq + 2;
    for (int kt = 0; kt < nkt; kt++) {
        const int k0 = kt * 64;
        cp_wait0();
        __syncthreads();
        if (kt + 1 < nkt) load_kv((kt + 1) & 1, k0 + 64);

        const uint32_t ukv = smem_u32(asmem + 36864 + (kt & 1) * KVBUF);
        const uint32_t uKh = ukv, uKl = ukv + 9216, uVh = ukv + 18432, uVl = ukv + 27648;

        if (k0 <= qwmax) {
            float c[8][4];
#pragma unroll
            for (int j = 0; j < 8; j++)
#pragma unroll
                for (int r = 0; r < 4; r++) c[j][r] = 0.f;

#pragma unroll
            for (int ks = 0; ks < 4; ks++) {
                uint32_t ah[4], al[4];
                ldsm_x4(ah, uQh + aoff + ks*32);
                ldsm_x4(al, uQl + aoff + ks*32);
#pragma unroll
                for (int jp = 0; jp < 4; jp++) {
                    uint32_t bh[4], bl[4];
                    ldsm_x4(bh, uKh + kboff + (uint32_t)(jp*16*ASTR*2) + ks*32);
                    ldsm_x4(bl, uKl + kboff + (uint32_t)(jp*16*ASTR*2) + ks*32);
                    mma_bf16(c[2*jp],   ah, bh);
                    mma_bf16(c[2*jp],   ah, bl);
                    mma_bf16(c[2*jp],   al, bh);
                    mma_bf16(c[2*jp+1], ah, bh+2);
                    mma_bf16(c[2*jp+1], ah, bl+2);
                    mma_bf16(c[2*jp+1], al, bh+2);
                }
            }

            if (k0 + 63 > qwmin) {
#pragma unroll
                for (int j = 0; j < 8; j++) {
                    int colb = k0 + j*8 + (lane & 3)*2;
                    if (colb     > rA) c[j][0] = -1e30f;
                    if (colb + 1 > rA) c[j][1] = -1e30f;
                    if (colb     > rB) c[j][2] = -1e30f;
                    if (colb + 1 > rB) c[j][3] = -1e30f;
                }
            }

            float vmA = -1e30f, vmB = -1e30f;
#pragma unroll
            for (int j = 0; j < 8; j++) {
                vmA = fmaxf(vmA, fmaxf(c[j][0], c[j][1]));
                vmB = fmaxf(vmB, fmaxf(c[j][2], c[j][3]));
            }
            vmA = fmaxf(vmA, __shfl_xor_sync(0xffffffffu, vmA, 1));
            vmA = fmaxf(vmA, __shfl_xor_sync(0xffffffffu, vmA, 2));
            vmB = fmaxf(vmB, __shfl_xor_sync(0xffffffffu, vmB, 1));
            vmB = fmaxf(vmB, __shfl_xor_sync(0xffffffffu, vmB, 2));
            const float mnA = fmaxf(mA, vmA);
            const float mnB = fmaxf(mB, vmB);

            float sA = 0.f, sB = 0.f;
#pragma unroll
            for (int j = 0; j < 8; j++) {
                c[j][0] = __expf(c[j][0] - mnA);
                c[j][1] = __expf(c[j][1] - mnA);
                c[j][2] = __expf(c[j][2] - mnB);
                c[j][3] = __expf(c[j][3] - mnB);
                sA += c[j][0] + c[j][1];
                sB += c[j][2] + c[j][3];
            }
            sA += __shfl_xor_sync(0xffffffffu, sA, 1);
            sA += __shfl_xor_sync(0xffffffffu, sA, 2);
            sB += __shfl_xor_sync(0xffffffffu, sB, 1);
            sB += __shfl_xor_sync(0xffffffffu, sB, 2);

            const float soA = __expf(mA - mnA);
            const float soB = __expf(mB - mnB);
            lA = lA * soA + sA;  mA = mnA;
            lB = lB * soB + sB;  mB = mnB;

#pragma unroll
            for (int j = 0; j < 8; j++) {
                o[j][0] *= soA; o[j][1] *= soA;
                o[j][2] *= soB; o[j][3] *= soB;
            }

#pragma unroll
            for (int kk = 0; kk < 4; kk++) {
                uint32_t ph[4], pl[4];
                pack_hl2(c[2*kk][0],   c[2*kk][1],   ph[0], pl[0]);
                pack_hl2(c[2*kk][2],   c[2*kk][3],   ph[1], pl[1]);
                pack_hl2(c[2*kk+1][0], c[2*kk+1][1], ph[2], pl[2]);
                pack_hl2(c[2*kk+1][2], c[2*kk+1][3], ph[3], pl[3]);
#pragma unroll
                for (int jp = 0; jp < 4; jp++) {
                    uint32_t vh[4], vl[4];
                    ldsm_x4_t(vh, uVh + vboff + (uint32_t)(kk*16*ASTR*2) + jp*32);
                    ldsm_x4_t(vl, uVl + vboff + (uint32_t)(kk*16*ASTR*2) + jp*32);
                    mma_bf16(o[2*jp],   ph, vh);
                    mma_bf16(o[2*jp],   ph, vl);
                    mma_bf16(o[2*jp],   pl, vh);
                    mma_bf16(o[2*jp+1], ph, vh+2);
                    mma_bf16(o[2*jp+1], ph, vl+2);
                    mma_bf16(o[2*jp+1], pl, vh+2);
                }
            }
        }
    }

    {
        const float invA = 1.f / lA;
        const float invB = 1.f / lB;
        const size_t offA = ((size_t)bb * SEQ + rA) * DMODEL + h * HDIM + (lane & 3) * 2;
        const size_t offB = ((size_t)bb * SEQ + rB) * DMODEL + h * HDIM + (lane & 3) * 2;
#pragma unroll
        for (int j = 0; j < 8; j++) {
            uint32_t hp, lp;
            pack_hl2(o[j][0] * invA, o[j][1] * invA, hp, lp);
            *(uint32_t*)(g_AOh + offA + j*8) = hp;
            *(uint32_t*)(g_AOl + offA + j*8) = lp;
            pack_hl2(o[j][2] * invB, o[j][3] * invB, hp, lp);
            *(uint32_t*)(g_AOh + offB + j*8) = hp;
            *(uint32_t*)(g_AOl + offB + j*8) = lp;
        }
    }
}

// ---------------------------------------------------------------------------
extern "C" void kernel_launch(void* const* d_in, const int* in_sizes, int n_in,
                              void* d_out, int out_size)
{
    const float* x  = (const float*)d_in[0];
    const float* Wq = (const float*)d_in[1];
    const float* bq = (const float*)d_in[2];
    const float* Wk = (const float*)d_in[3];
    const float* bk = (const float*)d_in[4];
    const float* Wv = (const float*)d_in[5];
    const float* bv = (const float*)d_in[6];
    const float* Wo = (const float*)d_in[7];
    const float* bo = (const float*)d_in[8];
    float* out = (float*)d_out;

    cudaFuncSetAttribute(hl_gemm, cudaFuncAttributeMaxDynamicSharedMemorySize, GEMM_SMEM_BYTES);
    cudaFuncSetAttribute(attn_tc, cudaFuncAttributeMaxDynamicSharedMemorySize, ATTN_SMEM_BYTES);

    conv_x<<<(BATCH*SEQ*INDIM)/1024, 256>>>(x);
    conv_w4<<<dim3((DMODEL*INDIM)/1024, 4), 256>>>(Wq, Wk, Wv, Wo);

    GemmArgs qa;
    qa.bias0 = bq; qa.bias1 = bk; qa.bias2 = bv; qa.out_o = nullptr; qa.mode = 0;
    hl_gemm<<<dim3(DMODEL/BN, (BATCH*SEQ)/BM, 3), 256, GEMM_SMEM_BYTES>>>(qa);

    attn_tc<<<dim3(SEQ/128, NHEADS, BATCH), 256, ATTN_SMEM_BYTES>>>();

    GemmArgs oa;
    oa.bias0 = bo; oa.bias1 = nullptr; oa.bias2 = nullptr; oa.out_o = out; oa.mode = 1;
    hl_gemm<<<dim3(DMODEL/BN, (BATCH*SEQ)/BM, 1), 256, GEMM_SMEM_BYTES>>>(oa);
}

// round 10
// speedup vs baseline: 3.8748x; 1.2919x over previous
#include <cuda_runtime.h>
#include <cuda_bf16.h>
#include <cuda_fp16.h>
#include <stdint.h>
#include <math.h>

#define BATCH  4
#define SEQ    2048
#define INDIM  1024
#define DMODEL 1024
#define NHEADS 16
#define HDIM   64
#define KTOT   1024

// ---------------------------------------------------------------------------
// Device scratch
// ---------------------------------------------------------------------------
#define QKV_ELE (BATCH*NHEADS*SEQ*HDIM)
__device__ __nv_bfloat16 g_Qh[QKV_ELE], g_Ql[QKV_ELE];   // [B,H,S,Dh], pre-scaled 1/8
__device__ __nv_bfloat16 g_Kh[QKV_ELE], g_Kl[QKV_ELE];
__device__ __nv_bfloat16 g_Vh[QKV_ELE], g_Vl[QKV_ELE];
__device__ __half g_AO16[BATCH*SEQ*DMODEL];              // plain fp16 (O-GEMM A operand)
__device__ __half g_x16[BATCH*SEQ*INDIM];                // plain fp16
__device__ __half g_Wh[4][DMODEL*INDIM], g_Wl[4][DMODEL*INDIM];  // fp16 hi/lo

// ---------------------------------------------------------------------------
// PTX helpers
// ---------------------------------------------------------------------------
__device__ __forceinline__ uint32_t smem_u32(const void* p) {
    uint32_t a;
    asm("{ .reg .u64 t; cvta.to.shared.u64 t, %1; cvt.u32.u64 %0, t; }"
        : "=r"(a) : "l"(p));
    return a;
}
__device__ __forceinline__ void cp_async16(uint32_t dst, const void* src) {
    asm volatile("cp.async.cg.shared.global [%0], [%1], 16;" :: "r"(dst), "l"(src));
}
__device__ __forceinline__ void cp_commit()  { asm volatile("cp.async.commit_group;"); }
__device__ __forceinline__ void cp_wait0()   { asm volatile("cp.async.wait_group 0;"); }

__device__ __forceinline__ void ldsm_x4(uint32_t* r, uint32_t a) {
    asm volatile("ldmatrix.sync.aligned.m8n8.x4.shared.b16 {%0,%1,%2,%3}, [%4];"
        : "=r"(r[0]), "=r"(r[1]), "=r"(r[2]), "=r"(r[3]) : "r"(a));
}
__device__ __forceinline__ void ldsm_x4_t(uint32_t* r, uint32_t a) {
    asm volatile("ldmatrix.sync.aligned.m8n8.x4.trans.shared.b16 {%0,%1,%2,%3}, [%4];"
        : "=r"(r[0]), "=r"(r[1]), "=r"(r[2]), "=r"(r[3]) : "r"(a));
}
__device__ __forceinline__ void mma_bf16(float* c, const uint32_t* a, const uint32_t* b) {
    asm volatile(
        "mma.sync.aligned.m16n8k16.row.col.f32.bf16.bf16.f32 "
        "{%0,%1,%2,%3}, {%4,%5,%6,%7}, {%8,%9}, {%0,%1,%2,%3};"
        : "+f"(c[0]), "+f"(c[1]), "+f"(c[2]), "+f"(c[3])
        : "r"(a[0]), "r"(a[1]), "r"(a[2]), "r"(a[3]), "r"(b[0]), "r"(b[1]));
}
__device__ __forceinline__ void mma_f16(float* c, const uint32_t* a, const uint32_t* b) {
    asm volatile(
        "mma.sync.aligned.m16n8k16.row.col.f32.f16.f16.f32 "
        "{%0,%1,%2,%3}, {%4,%5,%6,%7}, {%8,%9}, {%0,%1,%2,%3};"
        : "+f"(c[0]), "+f"(c[1]), "+f"(c[2]), "+f"(c[3])
        : "r"(a[0]), "r"(a[1]), "r"(a[2]), "r"(a[3]), "r"(b[0]), "r"(b[1]));
}

__device__ __forceinline__ void split_hl(float v, __nv_bfloat16& h, __nv_bfloat16& l) {
    h = __float2bfloat16(v);
    l = __float2bfloat16(v - __bfloat162float(h));
}
__device__ __forceinline__ void pack_hl2(float x, float y, uint32_t& hp, uint32_t& lp) {
    __nv_bfloat16 hx, lx, hy, ly;
    split_hl(x, hx, lx); split_hl(y, hy, ly);
    hp = ((uint32_t)__bfloat16_as_ushort(hy) << 16) | __bfloat16_as_ushort(hx);
    lp = ((uint32_t)__bfloat16_as_ushort(ly) << 16) | __bfloat16_as_ushort(lx);
}
__device__ __forceinline__ void split_hl16(float v, __half& h, __half& l) {
    h = __float2half(v);
    l = __float2half(v - __half2float(h));
}
__device__ __forceinline__ uint32_t pack_h16(float x, float y) {
    return ((uint32_t)__half_as_ushort(__float2half(y)) << 16)
         | __half_as_ushort(__float2half(x));
}

// ---------------------------------------------------------------------------
// converters:  x -> plain fp16 ;  W -> fp16 hi/lo
// ---------------------------------------------------------------------------
__global__ __launch_bounds__(256) void conv_x(const float* __restrict__ src)
{
    size_t i = ((size_t)blockIdx.x * 256 + threadIdx.x) * 4;
    float4 v = *(const float4*)(src + i);
    __half o[4] = { __float2half(v.x), __float2half(v.y),
                    __float2half(v.z), __float2half(v.w) };
    *(uint2*)(g_x16 + i) = *(uint2*)o;
}

__global__ __launch_bounds__(256) void conv_w4(
    const float* __restrict__ Wq, const float* __restrict__ Wk,
    const float* __restrict__ Wv, const float* __restrict__ Wo)
{
    const int w = blockIdx.y;
    const float* src = (w == 0) ? Wq : (w == 1) ? Wk : (w == 2) ? Wv : Wo;
    __half* h = g_Wh[w];
    __half* l = g_Wl[w];
    size_t i = ((size_t)blockIdx.x * 256 + threadIdx.x) * 4;
    float4 v = *(const float4*)(src + i);
    __half h0, h1, h2, h3, l0, l1, l2, l3;
    split_hl16(v.x, h0, l0); split_hl16(v.y, h1, l1);
    split_hl16(v.z, h2, l2); split_hl16(v.w, h3, l3);
    __half hh[4] = {h0, h1, h2, h3};
    __half ll[4] = {l0, l1, l2, l3};
    *(uint2*)(h + i) = *(uint2*)hh;
    *(uint2*)(l + i) = *(uint2*)ll;
}

// ---------------------------------------------------------------------------
// fp16 2-MMA GEMM:  C[m,n] = sum_k A[m,k]*W[n,k] + bias[n]
//   A plain fp16, W fp16 hi/lo:  C = A*Wh + A*Wl
// 128x128 block, 8 warps (64x32 warp tile), BK=64, 2-stage cp.async,
// 2 CTAs/SM, one barrier per K-iter, register epilogue.
// mode 0: QKV -> bf16 hi/lo scatter into [B,H,S,Dh] (Q scaled 1/8)
// mode 1: O-proj -> fp32 out
// ---------------------------------------------------------------------------
#define BM 128
#define BN 128
#define BK 64
#define NCH (KTOT/BK)          // 16
#define LDK 72                 // fp16 elems per smem row (144B, ldmatrix conflict-free)
#define TILE_E (128*LDK)       // 9216
#define STAGE_E (3*TILE_E)     // A, Bh, Bl
#define GEMM_SMEM_BYTES (2*STAGE_E*2)   // 110592

struct GemmArgs {
    const float* bias0; const float* bias1; const float* bias2;
    float* out_o;
    int mode;
};

__global__ __launch_bounds__(256, 2) void hl_gemm(GemmArgs args)
{
    extern __shared__ __align__(16) char dsm[];
    __half* smT = (__half*)dsm;

    const int t    = threadIdx.x;
    const int wid  = t >> 5;
    const int lane = t & 31;
    const int z    = blockIdx.z;
    const int m0   = blockIdx.y * BM;
    const int n0   = blockIdx.x * BN;
    const int wm   = wid & 1;
    const int wn   = wid >> 1;

    const __half *Ax, *Bh, *Bl;
    const float* bias;
    if (args.mode == 0) {
        Ax = g_x16;
        Bh = g_Wh[z]; Bl = g_Wl[z];
        bias = (z == 0) ? args.bias0 : (z == 1) ? args.bias1 : args.bias2;
    } else {
        Ax = g_AO16;
        Bh = g_Wh[3]; Bl = g_Wl[3];
        bias = args.bias0;
    }
    const __half* srcs[3] = { Ax, Bh, Bl };
    const int r0s[3] = { m0, n0, n0 };

    const uint32_t ub = smem_u32(smT);
    const uint32_t abase = (uint32_t)(((wm*64 + (lane & 15)) * LDK + ((lane >> 4) << 3)) * 2);
    const uint32_t bbase = (uint32_t)(((wn*32 + ((lane >> 4) << 3) + (lane & 7)) * LDK
                                      + (((lane >> 3) & 1) << 3)) * 2);

    float c[4][4][4];
#pragma unroll
    for (int mi = 0; mi < 4; mi++)
#pragma unroll
        for (int nj = 0; nj < 4; nj++)
#pragma unroll
            for (int r = 0; r < 4; r++) c[mi][nj][r] = 0.f;

    // stage fill: 3 tiles x 128 rows x 8 chunks(16B) = 3072, 12/thread
    auto load_stage = [&](int stage, int kc) {
#pragma unroll
        for (int it = 0; it < 12; it++) {
            int idx  = t + it * 256;
            int tile = idx >> 10;
            int rem  = idx & 1023;
            int row  = rem >> 3;
            int ch   = rem & 7;
            const __half* sp = srcs[tile]
                + (size_t)(r0s[tile] + row) * KTOT + kc * BK + ch * 8;
            uint32_t dp = ub + (uint32_t)((stage * 3 + tile) * TILE_E + row * LDK + ch * 8) * 2;
            cp_async16(dp, sp);
        }
        cp_commit();
    };

    load_stage(0, 0);

    for (int kc = 0; kc < NCH; kc++) {
        cp_wait0();
        __syncthreads();
        if (kc + 1 < NCH) load_stage((kc + 1) & 1, kc + 1);

        const int s = kc & 1;
        const uint32_t uA  = ub + (uint32_t)((s*3 + 0) * TILE_E) * 2;
        const uint32_t uBh = ub + (uint32_t)((s*3 + 1) * TILE_E) * 2;
        const uint32_t uBl = ub + (uint32_t)((s*3 + 2) * TILE_E) * 2;

#pragma unroll
        for (int ks = 0; ks < 4; ks++) {
            uint32_t a[4][4];
#pragma unroll
            for (int mi = 0; mi < 4; mi++)
                ldsm_x4(a[mi], uA + abase + (uint32_t)(mi * 16 * LDK * 2) + ks * 32);
            uint32_t bh[2][4], bl[2][4];
#pragma unroll
            for (int j2 = 0; j2 < 2; j2++) {
                ldsm_x4(bh[j2], uBh + bbase + (uint32_t)(j2 * 16 * LDK * 2) + ks * 32);
                ldsm_x4(bl[j2], uBl + bbase + (uint32_t)(j2 * 16 * LDK * 2) + ks * 32);
            }
            // pass 1: A*Bh over all 16 accumulators (RAW distance 16)
#pragma unroll
            for (int mi = 0; mi < 4; mi++)
#pragma unroll
                for (int nj = 0; nj < 4; nj++)
                    mma_f16(c[mi][nj], a[mi], &bh[nj >> 1][(nj & 1) * 2]);
            // pass 2: A*Bl
#pragma unroll
            for (int mi = 0; mi < 4; mi++)
#pragma unroll
                for (int nj = 0; nj < 4; nj++)
                    mma_f16(c[mi][nj], a[mi], &bl[nj >> 1][(nj & 1) * 2]);
        }
    }

    // -------- register epilogue --------
    const float qscale = (args.mode == 0 && z == 0) ? 0.125f : 1.0f;
    float2 bv[4];
    int nn[4];
#pragma unroll
    for (int nj = 0; nj < 4; nj++) {
        nn[nj] = n0 + wn*32 + nj*8 + (lane & 3)*2;
        bv[nj] = *(const float2*)&bias[nn[nj]];
    }

    if (args.mode == 0) {
        __nv_bfloat16 *dh_, *dl_;
        if (z == 0)      { dh_ = g_Qh; dl_ = g_Ql; }
        else if (z == 1) { dh_ = g_Kh; dl_ = g_Kl; }
        else             { dh_ = g_Vh; dl_ = g_Vl; }
#pragma unroll
        for (int mi = 0; mi < 4; mi++) {
#pragma unroll
            for (int half = 0; half < 2; half++) {
                const int m  = m0 + wm*64 + mi*16 + (lane >> 2) + half*8;
                const int bb = m >> 11;
                const int ss = m & (SEQ - 1);
#pragma unroll
                for (int nj = 0; nj < 4; nj++) {
                    const int n  = nn[nj];
                    const int h  = n >> 6;
                    const int dh = n & 63;
                    const float v0 = (c[mi][nj][half*2+0] + bv[nj].x) * qscale;
                    const float v1 = (c[mi][nj][half*2+1] + bv[nj].y) * qscale;
                    uint32_t hp, lp;
                    pack_hl2(v0, v1, hp, lp);
                    const size_t off = (((size_t)bb * NHEADS + h) * SEQ + ss) * HDIM + dh;
                    *(uint32_t*)(dh_ + off) = hp;
                    *(uint32_t*)(dl_ + off) = lp;
                }
            }
        }
    } else {
        float* outp = args.out_o;
#pragma unroll
        for (int mi = 0; mi < 4; mi++) {
#pragma unroll
            for (int half = 0; half < 2; half++) {
                const int m = m0 + wm*64 + mi*16 + (lane >> 2) + half*8;
#pragma unroll
                for (int nj = 0; nj < 4; nj++) {
                    const float v0 = c[mi][nj][half*2+0] + bv[nj].x;
                    const float v1 = c[mi][nj][half*2+1] + bv[nj].y;
                    *(float2*)(outp + (size_t)m * DMODEL + nn[nj]) = make_float2(v0, v1);
                }
            }
        }
    }
}

// ---------------------------------------------------------------------------
// Register-resident causal flash attention (bf16 3-MMA, validated path).
// cp.async double-buffered K/V; interleaved MMA chains; fp16 AO epilogue.
// ---------------------------------------------------------------------------
#define ASTR 72
#define KVBUF 36864
#define ATTN_SMEM_BYTES (36864 + 2*KVBUF)   // 110592

__global__ __launch_bounds__(256, 2) void attn_tc()
{
    extern __shared__ __align__(16) char asmem[];
    __nv_bfloat16* sQh = (__nv_bfloat16*)(asmem);
    __nv_bfloat16* sQl = (__nv_bfloat16*)(asmem + 18432);

    const int t    = threadIdx.x;
    const int wid  = t >> 5;
    const int lane = t & 31;
    const int bq   = gridDim.x - 1 - blockIdx.x;   // heavy tiles first
    const int h    = blockIdx.y;
    const int bb   = blockIdx.z;
    const int q0   = bq * 128;
    const size_t base = ((size_t)bb * NHEADS + h) * SEQ * HDIM;

    const __nv_bfloat16* gsrc[4] = { g_Kh, g_Kl, g_Vh, g_Vl };

    auto load_kv = [&](int buf, int k0) {
        char* dst0 = asmem + 36864 + buf * KVBUF;
#pragma unroll
        for (int it = 0; it < 8; it++) {
            int idx = t + it * 256;
            int a   = idx >> 9;
            int rem = idx & 511;
            int row = rem >> 3, ch = rem & 7;
            uint32_t dp = smem_u32(dst0 + a * 9216 + (row * ASTR + ch * 8) * 2);
            cp_async16(dp, gsrc[a] + base + (size_t)(k0 + row) * HDIM + ch * 8);
        }
        cp_commit();
    };

    {
#pragma unroll
        for (int it = 0; it < 8; it++) {
            int idx = t + it * 256;
            int a   = idx >> 10;
            int rem = idx & 1023;
            int row = rem >> 3, ch = rem & 7;
            const __nv_bfloat16* src = (a == 0 ? g_Qh : g_Ql) + base + (size_t)(q0 + row) * HDIM + ch * 8;
            uint32_t dp = smem_u32(asmem + a * 18432 + (row * ASTR + ch * 8) * 2);
            cp_async16(dp, src);
        }
        cp_commit();
    }
    load_kv(0, 0);

    const uint32_t uQh = smem_u32(sQh), uQl = smem_u32(sQl);
    const uint32_t aoff  = (uint32_t)(((wid*16 + (lane & 15)) * ASTR + ((lane >> 4) << 3)) * 2);
    const uint32_t kboff = (uint32_t)(((((lane >> 4) << 3) + (lane & 7)) * ASTR + (((lane >> 3) & 1) << 3)) * 2);
    const uint32_t vboff = (uint32_t)((((((lane >> 3) & 1) << 3) + (lane & 7)) * ASTR + ((lane >> 4) << 3)) * 2);

    float o[8][4];
#pragma unroll
    for (int j = 0; j < 8; j++)
#pragma unroll
        for (int r = 0; r < 4; r++) o[j][r] = 0.f;

    const int rA = q0 + wid*16 + (lane >> 2);
    const int rB = rA + 8;
    const int qwmin = q0 + wid*16;
    const int qwmax = qwmin + 15;
    float mA = -1e30f, mB = -1e30f, lA = 0.f, lB = 0.f;

    const int nkt = 2*bq + 2;
    for (int kt = 0; kt < nkt; kt++) {
        const int k0 = kt * 64;
        cp_wait0();
        __syncthreads();
        if (kt + 1 < nkt) load_kv((kt + 1) & 1, k0 + 64);

        const uint32_t ukv = smem_u32(asmem + 36864 + (kt & 1) * KVBUF);
        const uint32_t uKh = ukv, uKl = ukv + 9216, uVh = ukv + 18432, uVl = ukv + 27648;

        if (k0 <= qwmax) {
            float c[8][4];
#pragma unroll
            for (int j = 0; j < 8; j++)
#pragma unroll
                for (int r = 0; r < 4; r++) c[j][r] = 0.f;

#pragma unroll
            for (int ks = 0; ks < 4; ks++) {
                uint32_t ah[4], al[4];
                ldsm_x4(ah, uQh + aoff + ks*32);
                ldsm_x4(al, uQl + aoff + ks*32);
#pragma unroll
                for (int jp = 0; jp < 4; jp++) {
                    uint32_t bh[4], bl[4];
                    ldsm_x4(bh, uKh + kboff + (uint32_t)(jp*16*ASTR*2) + ks*32);
                    ldsm_x4(bl, uKl + kboff + (uint32_t)(jp*16*ASTR*2) + ks*32);
                    // interleave the two accumulator chains (RAW distance 2)
                    mma_bf16(c[2*jp],   ah, bh);
                    mma_bf16(c[2*jp+1], ah, bh+2);
                    mma_bf16(c[2*jp],   ah, bl);
                    mma_bf16(c[2*jp+1], ah, bl+2);
                    mma_bf16(c[2*jp],   al, bh);
                    mma_bf16(c[2*jp+1], al, bh+2);
                }
            }

            if (k0 + 63 > qwmin) {
#pragma unroll
                for (int j = 0; j < 8; j++) {
                    int colb = k0 + j*8 + (lane & 3)*2;
                    if (colb     > rA) c[j][0] = -1e30f;
                    if (colb + 1 > rA) c[j][1] = -1e30f;
                    if (colb     > rB) c[j][2] = -1e30f;
                    if (colb + 1 > rB) c[j][3] = -1e30f;
                }
            }

            float vmA = -1e30f, vmB = -1e30f;
#pragma unroll
            for (int j = 0; j < 8; j++) {
                vmA = fmaxf(vmA, fmaxf(c[j][0], c[j][1]));
                vmB = fmaxf(vmB, fmaxf(c[j][2], c[j][3]));
            }
            vmA = fmaxf(vmA, __shfl_xor_sync(0xffffffffu, vmA, 1));
            vmA = fmaxf(vmA, __shfl_xor_sync(0xffffffffu, vmA, 2));
            vmB = fmaxf(vmB, __shfl_xor_sync(0xffffffffu, vmB, 1));
            vmB = fmaxf(vmB, __shfl_xor_sync(0xffffffffu, vmB, 2));
            const float mnA = fmaxf(mA, vmA);
            const float mnB = fmaxf(mB, vmB);

            float sA = 0.f, sB = 0.f;
#pragma unroll
            for (int j = 0; j < 8; j++) {
                c[j][0] = __expf(c[j][0] - mnA);
                c[j][1] = __expf(c[j][1] - mnA);
                c[j][2] = __expf(c[j][2] - mnB);
                c[j][3] = __expf(c[j][3] - mnB);
                sA += c[j][0] + c[j][1];
                sB += c[j][2] + c[j][3];
            }
            sA += __shfl_xor_sync(0xffffffffu, sA, 1);
            sA += __shfl_xor_sync(0xffffffffu, sA, 2);
            sB += __shfl_xor_sync(0xffffffffu, sB, 1);
            sB += __shfl_xor_sync(0xffffffffu, sB, 2);

            const float soA = __expf(mA - mnA);
            const float soB = __expf(mB - mnB);
            lA = lA * soA + sA;  mA = mnA;
            lB = lB * soB + sB;  mB = mnB;

#pragma unroll
            for (int j = 0; j < 8; j++) {
                o[j][0] *= soA; o[j][1] *= soA;
                o[j][2] *= soB; o[j][3] *= soB;
            }

#pragma unroll
            for (int kk = 0; kk < 4; kk++) {
                uint32_t ph[4], pl[4];
                pack_hl2(c[2*kk][0],   c[2*kk][1],   ph[0], pl[0]);
                pack_hl2(c[2*kk][2],   c[2*kk][3],   ph[1], pl[1]);
                pack_hl2(c[2*kk+1][0], c[2*kk+1][1], ph[2], pl[2]);
                pack_hl2(c[2*kk+1][2], c[2*kk+1][3], ph[3], pl[3]);
#pragma unroll
                for (int jp = 0; jp < 4; jp++) {
                    uint32_t vh[4], vl[4];
                    ldsm_x4_t(vh, uVh + vboff + (uint32_t)(kk*16*ASTR*2) + jp*32);
                    ldsm_x4_t(vl, uVl + vboff + (uint32_t)(kk*16*ASTR*2) + jp*32);
                    mma_bf16(o[2*jp],   ph, vh);
                    mma_bf16(o[2*jp+1], ph, vh+2);
                    mma_bf16(o[2*jp],   ph, vl);
                    mma_bf16(o[2*jp+1], ph, vl+2);
                    mma_bf16(o[2*jp],   pl, vh);
                    mma_bf16(o[2*jp+1], pl, vh+2);
                }
            }
        }
    }

    // epilogue: normalize + write plain fp16 AO [b, s, h*64+col]
    {
        const float invA = 1.f / lA;
        const float invB = 1.f / lB;
        const size_t offA = ((size_t)bb * SEQ + rA) * DMODEL + h * HDIM + (lane & 3) * 2;
        const size_t offB = ((size_t)bb * SEQ + rB) * DMODEL + h * HDIM + (lane & 3) * 2;
#pragma unroll
        for (int j = 0; j < 8; j++) {
            *(uint32_t*)(g_AO16 + offA + j*8) = pack_h16(o[j][0] * invA, o[j][1] * invA);
            *(uint32_t*)(g_AO16 + offB + j*8) = pack_h16(o[j][2] * invB, o[j][3] * invB);
        }
    }
}

// ---------------------------------------------------------------------------
extern "C" void kernel_launch(void* const* d_in, const int* in_sizes, int n_in,
                              void* d_out, int out_size)
{
    const float* x  = (const float*)d_in[0];
    const float* Wq = (const float*)d_in[1];
    const float* bq = (const float*)d_in[2];
    const float* Wk = (const float*)d_in[3];
    const float* bk = (const float*)d_in[4];
    const float* Wv = (const float*)d_in[5];
    const float* bv = (const float*)d_in[6];
    const float* Wo = (const float*)d_in[7];
    const float* bo = (const float*)d_in[8];
    float* out = (float*)d_out;

    cudaFuncSetAttribute(hl_gemm, cudaFuncAttributeMaxDynamicSharedMemorySize, GEMM_SMEM_BYTES);
    cudaFuncSetAttribute(attn_tc, cudaFuncAttributeMaxDynamicSharedMemorySize, ATTN_SMEM_BYTES);

    conv_x<<<(BATCH*SEQ*INDIM)/1024, 256>>>(x);
    conv_w4<<<dim3((DMODEL*INDIM)/1024, 4), 256>>>(Wq, Wk, Wv, Wo);

    GemmArgs qa;
    qa.bias0 = bq; qa.bias1 = bk; qa.bias2 = bv; qa.out_o = nullptr; qa.mode = 0;
    hl_gemm<<<dim3(DMODEL/BN, (BATCH*SEQ)/BM, 3), 256, GEMM_SMEM_BYTES>>>(qa);

    attn_tc<<<dim3(SEQ/128, NHEADS, BATCH), 256, ATTN_SMEM_BYTES>>>();

    GemmArgs oa;
    oa.bias0 = bo; oa.bias1 = nullptr; oa.bias2 = nullptr; oa.out_o = out; oa.mode = 1;
    hl_gemm<<<dim3(DMODEL/BN, (BATCH*SEQ)/BM, 1), 256, GEMM_SMEM_BYTES>>>(oa);
}

// round 11
// speedup vs baseline: 4.2118x; 1.0870x over previous
#include <cuda_runtime.h>
#include <cuda_bf16.h>
#include <cuda_fp16.h>
#include <stdint.h>
#include <math.h>

#define BATCH  4
#define SEQ    2048
#define INDIM  1024
#define DMODEL 1024
#define NHEADS 16
#define HDIM   64
#define KTOT   1024

// Q prescale: 1/sqrt(64) * log2(e)  (softmax runs in base-2)
#define QSCALE_LOG2E 0.1803368801111244f

// ---------------------------------------------------------------------------
// Device scratch
// ---------------------------------------------------------------------------
#define QKV_ELE (BATCH*NHEADS*SEQ*HDIM)
__device__ __nv_bfloat16 g_Qh[QKV_ELE], g_Ql[QKV_ELE];   // bf16 hi/lo, pre-scaled
__device__ __nv_bfloat16 g_Kh[QKV_ELE], g_Kl[QKV_ELE];   // bf16 hi/lo
__device__ __half g_V16[QKV_ELE];                        // plain fp16
__device__ __half g_AO16[BATCH*SEQ*DMODEL];              // plain fp16
__device__ __half g_x16[BATCH*SEQ*INDIM];                // plain fp16
__device__ __half g_Wh[4][DMODEL*INDIM], g_Wl[4][DMODEL*INDIM];  // fp16 hi/lo

// ---------------------------------------------------------------------------
// PTX helpers
// ---------------------------------------------------------------------------
__device__ __forceinline__ uint32_t smem_u32(const void* p) {
    uint32_t a;
    asm("{ .reg .u64 t; cvta.to.shared.u64 t, %1; cvt.u32.u64 %0, t; }"
        : "=r"(a) : "l"(p));
    return a;
}
__device__ __forceinline__ void cp_async16(uint32_t dst, const void* src) {
    asm volatile("cp.async.cg.shared.global [%0], [%1], 16;" :: "r"(dst), "l"(src));
}
__device__ __forceinline__ void cp_commit()  { asm volatile("cp.async.commit_group;"); }
__device__ __forceinline__ void cp_wait0()   { asm volatile("cp.async.wait_group 0;"); }

__device__ __forceinline__ void ldsm_x4(uint32_t* r, uint32_t a) {
    asm volatile("ldmatrix.sync.aligned.m8n8.x4.shared.b16 {%0,%1,%2,%3}, [%4];"
        : "=r"(r[0]), "=r"(r[1]), "=r"(r[2]), "=r"(r[3]) : "r"(a));
}
__device__ __forceinline__ void ldsm_x4_t(uint32_t* r, uint32_t a) {
    asm volatile("ldmatrix.sync.aligned.m8n8.x4.trans.shared.b16 {%0,%1,%2,%3}, [%4];"
        : "=r"(r[0]), "=r"(r[1]), "=r"(r[2]), "=r"(r[3]) : "r"(a));
}
__device__ __forceinline__ void mma_bf16(float* c, const uint32_t* a, const uint32_t* b) {
    asm volatile(
        "mma.sync.aligned.m16n8k16.row.col.f32.bf16.bf16.f32 "
        "{%0,%1,%2,%3}, {%4,%5,%6,%7}, {%8,%9}, {%0,%1,%2,%3};"
        : "+f"(c[0]), "+f"(c[1]), "+f"(c[2]), "+f"(c[3])
        : "r"(a[0]), "r"(a[1]), "r"(a[2]), "r"(a[3]), "r"(b[0]), "r"(b[1]));
}
__device__ __forceinline__ void mma_f16(float* c, const uint32_t* a, const uint32_t* b) {
    asm volatile(
        "mma.sync.aligned.m16n8k16.row.col.f32.f16.f16.f32 "
        "{%0,%1,%2,%3}, {%4,%5,%6,%7}, {%8,%9}, {%0,%1,%2,%3};"
        : "+f"(c[0]), "+f"(c[1]), "+f"(c[2]), "+f"(c[3])
        : "r"(a[0]), "r"(a[1]), "r"(a[2]), "r"(a[3]), "r"(b[0]), "r"(b[1]));
}

__device__ __forceinline__ void split_hl(float v, __nv_bfloat16& h, __nv_bfloat16& l) {
    h = __float2bfloat16(v);
    l = __float2bfloat16(v - __bfloat162float(h));
}
__device__ __forceinline__ void pack_hl2(float x, float y, uint32_t& hp, uint32_t& lp) {
    __nv_bfloat16 hx, lx, hy, ly;
    split_hl(x, hx, lx); split_hl(y, hy, ly);
    hp = ((uint32_t)__bfloat16_as_ushort(hy) << 16) | __bfloat16_as_ushort(hx);
    lp = ((uint32_t)__bfloat16_as_ushort(ly) << 16) | __bfloat16_as_ushort(lx);
}
__device__ __forceinline__ void split_hl16(float v, __half& h, __half& l) {
    h = __float2half(v);
    l = __float2half(v - __half2float(h));
}
__device__ __forceinline__ void pack_hl2_f16(float x, float y, uint32_t& hp, uint32_t& lp) {
    __half hx, lx, hy, ly;
    split_hl16(x, hx, lx); split_hl16(y, hy, ly);
    hp = ((uint32_t)__half_as_ushort(hy) << 16) | __half_as_ushort(hx);
    lp = ((uint32_t)__half_as_ushort(ly) << 16) | __half_as_ushort(lx);
}
__device__ __forceinline__ uint32_t pack_h16(float x, float y) {
    return ((uint32_t)__half_as_ushort(__float2half(y)) << 16)
         | __half_as_ushort(__float2half(x));
}

// ---------------------------------------------------------------------------
// converters:  x -> plain fp16 ;  W -> fp16 hi/lo
// ---------------------------------------------------------------------------
__global__ __launch_bounds__(256) void conv_x(const float* __restrict__ src)
{
    size_t i = ((size_t)blockIdx.x * 256 + threadIdx.x) * 4;
    float4 v = *(const float4*)(src + i);
    __half o[4] = { __float2half(v.x), __float2half(v.y),
                    __float2half(v.z), __float2half(v.w) };
    *(uint2*)(g_x16 + i) = *(uint2*)o;
}

__global__ __launch_bounds__(256) void conv_w4(
    const float* __restrict__ Wq, const float* __restrict__ Wk,
    const float* __restrict__ Wv, const float* __restrict__ Wo)
{
    const int w = blockIdx.y;
    const float* src = (w == 0) ? Wq : (w == 1) ? Wk : (w == 2) ? Wv : Wo;
    __half* h = g_Wh[w];
    __half* l = g_Wl[w];
    size_t i = ((size_t)blockIdx.x * 256 + threadIdx.x) * 4;
    float4 v = *(const float4*)(src + i);
    __half h0, h1, h2, h3, l0, l1, l2, l3;
    split_hl16(v.x, h0, l0); split_hl16(v.y, h1, l1);
    split_hl16(v.z, h2, l2); split_hl16(v.w, h3, l3);
    __half hh[4] = {h0, h1, h2, h3};
    __half ll[4] = {l0, l1, l2, l3};
    *(uint2*)(h + i) = *(uint2*)hh;
    *(uint2*)(l + i) = *(uint2*)ll;
}

// ---------------------------------------------------------------------------
// fp16 2-MMA GEMM:  C[m,n] = sum_k A[m,k]*W[n,k] + bias[n]
// 128x128 block, 8 warps, BK=64, 2-stage cp.async, 2 CTAs/SM.
// mode 0: QKV -> Q/K bf16 hi/lo, V plain fp16, scatter [B,H,S,Dh]
// mode 1: O-proj -> fp32 out
// ---------------------------------------------------------------------------
#define BM 128
#define BN 128
#define BK 64
#define NCH (KTOT/BK)          // 16
#define LDK 72
#define TILE_E (128*LDK)
#define STAGE_E (3*TILE_E)
#define GEMM_SMEM_BYTES (2*STAGE_E*2)   // 110592

struct GemmArgs {
    const float* bias0; const float* bias1; const float* bias2;
    float* out_o;
    int mode;
};

__global__ __launch_bounds__(256, 2) void hl_gemm(GemmArgs args)
{
    extern __shared__ __align__(16) char dsm[];
    __half* smT = (__half*)dsm;

    const int t    = threadIdx.x;
    const int wid  = t >> 5;
    const int lane = t & 31;
    const int z    = blockIdx.z;
    const int m0   = blockIdx.y * BM;
    const int n0   = blockIdx.x * BN;
    const int wm   = wid & 1;
    const int wn   = wid >> 1;

    const __half *Ax, *Bh, *Bl;
    const float* bias;
    if (args.mode == 0) {
        Ax = g_x16;
        Bh = g_Wh[z]; Bl = g_Wl[z];
        bias = (z == 0) ? args.bias0 : (z == 1) ? args.bias1 : args.bias2;
    } else {
        Ax = g_AO16;
        Bh = g_Wh[3]; Bl = g_Wl[3];
        bias = args.bias0;
    }
    const __half* srcs[3] = { Ax, Bh, Bl };
    const int r0s[3] = { m0, n0, n0 };

    const uint32_t ub = smem_u32(smT);
    const uint32_t abase = (uint32_t)(((wm*64 + (lane & 15)) * LDK + ((lane >> 4) << 3)) * 2);
    const uint32_t bbase = (uint32_t)(((wn*32 + ((lane >> 4) << 3) + (lane & 7)) * LDK
                                      + (((lane >> 3) & 1) << 3)) * 2);

    float c[4][4][4];
#pragma unroll
    for (int mi = 0; mi < 4; mi++)
#pragma unroll
        for (int nj = 0; nj < 4; nj++)
#pragma unroll
            for (int r = 0; r < 4; r++) c[mi][nj][r] = 0.f;

    auto load_stage = [&](int stage, int kc) {
#pragma unroll
        for (int it = 0; it < 12; it++) {
            int idx  = t + it * 256;
            int tile = idx >> 10;
            int rem  = idx & 1023;
            int row  = rem >> 3;
            int ch   = rem & 7;
            const __half* sp = srcs[tile]
                + (size_t)(r0s[tile] + row) * KTOT + kc * BK + ch * 8;
            uint32_t dp = ub + (uint32_t)((stage * 3 + tile) * TILE_E + row * LDK + ch * 8) * 2;
            cp_async16(dp, sp);
        }
        cp_commit();
    };

    load_stage(0, 0);

    for (int kc = 0; kc < NCH; kc++) {
        cp_wait0();
        __syncthreads();
        if (kc + 1 < NCH) load_stage((kc + 1) & 1, kc + 1);

        const int s = kc & 1;
        const uint32_t uA  = ub + (uint32_t)((s*3 + 0) * TILE_E) * 2;
        const uint32_t uBh = ub + (uint32_t)((s*3 + 1) * TILE_E) * 2;
        const uint32_t uBl = ub + (uint32_t)((s*3 + 2) * TILE_E) * 2;

#pragma unroll
        for (int ks = 0; ks < 4; ks++) {
            uint32_t a[4][4];
#pragma unroll
            for (int mi = 0; mi < 4; mi++)
                ldsm_x4(a[mi], uA + abase + (uint32_t)(mi * 16 * LDK * 2) + ks * 32);
            uint32_t bh[2][4], bl[2][4];
#pragma unroll
            for (int j2 = 0; j2 < 2; j2++) {
                ldsm_x4(bh[j2], uBh + bbase + (uint32_t)(j2 * 16 * LDK * 2) + ks * 32);
                ldsm_x4(bl[j2], uBl + bbase + (uint32_t)(j2 * 16 * LDK * 2) + ks * 32);
            }
#pragma unroll
            for (int mi = 0; mi < 4; mi++)
#pragma unroll
                for (int nj = 0; nj < 4; nj++)
                    mma_f16(c[mi][nj], a[mi], &bh[nj >> 1][(nj & 1) * 2]);
#pragma unroll
            for (int mi = 0; mi < 4; mi++)
#pragma unroll
                for (int nj = 0; nj < 4; nj++)
                    mma_f16(c[mi][nj], a[mi], &bl[nj >> 1][(nj & 1) * 2]);
        }
    }

    // -------- register epilogue --------
    const float qscale = (args.mode == 0 && z == 0) ? QSCALE_LOG2E : 1.0f;
    float2 bv[4];
    int nn[4];
#pragma unroll
    for (int nj = 0; nj < 4; nj++) {
        nn[nj] = n0 + wn*32 + nj*8 + (lane & 3)*2;
        bv[nj] = *(const float2*)&bias[nn[nj]];
    }

    if (args.mode == 0) {
#pragma unroll
        for (int mi = 0; mi < 4; mi++) {
#pragma unroll
            for (int half = 0; half < 2; half++) {
                const int m  = m0 + wm*64 + mi*16 + (lane >> 2) + half*8;
                const int bb = m >> 11;
                const int ss = m & (SEQ - 1);
#pragma unroll
                for (int nj = 0; nj < 4; nj++) {
                    const int n  = nn[nj];
                    const int h  = n >> 6;
                    const int dh = n & 63;
                    const float v0 = (c[mi][nj][half*2+0] + bv[nj].x) * qscale;
                    const float v1 = (c[mi][nj][half*2+1] + bv[nj].y) * qscale;
                    const size_t off = (((size_t)bb * NHEADS + h) * SEQ + ss) * HDIM + dh;
                    if (z == 2) {
                        *(uint32_t*)(g_V16 + off) = pack_h16(v0, v1);
                    } else {
                        __nv_bfloat16 *dh_ = (z == 0) ? g_Qh : g_Kh;
                        __nv_bfloat16 *dl_ = (z == 0) ? g_Ql : g_Kl;
                        uint32_t hp, lp;
                        pack_hl2(v0, v1, hp, lp);
                        *(uint32_t*)(dh_ + off) = hp;
                        *(uint32_t*)(dl_ + off) = lp;
                    }
                }
            }
        }
    } else {
        float* outp = args.out_o;
#pragma unroll
        for (int mi = 0; mi < 4; mi++) {
#pragma unroll
            for (int half = 0; half < 2; half++) {
                const int m = m0 + wm*64 + mi*16 + (lane >> 2) + half*8;
#pragma unroll
                for (int nj = 0; nj < 4; nj++) {
                    const float v0 = c[mi][nj][half*2+0] + bv[nj].x;
                    const float v1 = c[mi][nj][half*2+1] + bv[nj].y;
                    *(float2*)(outp + (size_t)m * DMODEL + nn[nj]) = make_float2(v0, v1);
                }
            }
        }
    }
}

// ---------------------------------------------------------------------------
// Register-resident causal flash attention.
// QK: bf16 3-MMA (Q/K hi/lo).  PV: fp16, P hi/lo x V plain (4 MMAs per subtile).
// Softmax in base-2 (Q carries log2e).  Diagonal subtile skipping.
// SMEM: Qh/Ql 128x72 bf16 (36864) + 2 KV buffers (Kh,Kl bf16 + V fp16 = 27648).
// ---------------------------------------------------------------------------
#define ASTR 72
#define KVBUF 27648
#define ATTN_SMEM_BYTES (36864 + 2*KVBUF)   // 92160

__global__ __launch_bounds__(256, 2) void attn_tc()
{
    extern __shared__ __align__(16) char asmem[];
    __nv_bfloat16* sQh = (__nv_bfloat16*)(asmem);
    __nv_bfloat16* sQl = (__nv_bfloat16*)(asmem + 18432);

    const int t    = threadIdx.x;
    const int wid  = t >> 5;
    const int lane = t & 31;
    const int bq   = gridDim.x - 1 - blockIdx.x;   // heavy tiles first
    const int h    = blockIdx.y;
    const int bb   = blockIdx.z;
    const int q0   = bq * 128;
    const size_t base = ((size_t)bb * NHEADS + h) * SEQ * HDIM;

    // 3 sources: Kh, Kl (bf16), V (fp16) — all 2-byte elements
    const char* gsrc[3] = { (const char*)g_Kh, (const char*)g_Kl, (const char*)g_V16 };

    auto load_kv = [&](int buf, int k0) {
        char* dst0 = asmem + 36864 + buf * KVBUF;
#pragma unroll
        for (int it = 0; it < 6; it++) {
            int idx = t + it * 256;          // 0..1535: 3 arrays x 64 rows x 8 chunks
            int a   = idx >> 9;
            int rem = idx & 511;
            int row = rem >> 3, ch = rem & 7;
            uint32_t dp = smem_u32(dst0 + a * 9216 + (row * ASTR + ch * 8) * 2);
            cp_async16(dp, gsrc[a] + (base + (size_t)(k0 + row) * HDIM + ch * 8) * 2);
        }
        cp_commit();
    };

    {
#pragma unroll
        for (int it = 0; it < 8; it++) {
            int idx = t + it * 256;
            int a   = idx >> 10;
            int rem = idx & 1023;
            int row = rem >> 3, ch = rem & 7;
            const __nv_bfloat16* src = (a == 0 ? g_Qh : g_Ql) + base + (size_t)(q0 + row) * HDIM + ch * 8;
            uint32_t dp = smem_u32(asmem + a * 18432 + (row * ASTR + ch * 8) * 2);
            cp_async16(dp, src);
        }
        cp_commit();
    }
    load_kv(0, 0);

    const uint32_t uQh = smem_u32(sQh), uQl = smem_u32(sQl);
    const uint32_t aoff  = (uint32_t)(((wid*16 + (lane & 15)) * ASTR + ((lane >> 4) << 3)) * 2);
    const uint32_t kboff = (uint32_t)(((((lane >> 4) << 3) + (lane & 7)) * ASTR + (((lane >> 3) & 1) << 3)) * 2);
    const uint32_t vboff = (uint32_t)((((((lane >> 3) & 1) << 3) + (lane & 7)) * ASTR + ((lane >> 4) << 3)) * 2);

    float o[8][4];
#pragma unroll
    for (int j = 0; j < 8; j++)
#pragma unroll
        for (int r = 0; r < 4; r++) o[j][r] = 0.f;

    const int rA = q0 + wid*16 + (lane >> 2);
    const int rB = rA + 8;
    const int qwmin = q0 + wid*16;
    const int qwmax = qwmin + 15;
    float mA = -1e30f, mB = -1e30f, lA = 0.f, lB = 0.f;

    const int nkt = 2*bq + 2;
    for (int kt = 0; kt < nkt; kt++) {
        const int k0 = kt * 64;
        cp_wait0();
        __syncthreads();
        if (kt + 1 < nkt) load_kv((kt + 1) & 1, k0 + 64);

        const uint32_t ukv = smem_u32(asmem + 36864 + (kt & 1) * KVBUF);
        const uint32_t uKh = ukv, uKl = ukv + 9216, uV = ukv + 18432;

        if (k0 <= qwmax) {
            float c[8][4];
#pragma unroll
            for (int j = 0; j < 8; j++)
#pragma unroll
                for (int r = 0; r < 4; r++) c[j][r] = 0.f;

            // ---- S = Q.K^T (bf16 3-MMA), skip fully-masked jp subtiles ----
#pragma unroll
            for (int ks = 0; ks < 4; ks++) {
                uint32_t ah[4], al[4];
                ldsm_x4(ah, uQh + aoff + ks*32);
                ldsm_x4(al, uQl + aoff + ks*32);
#pragma unroll
                for (int jp = 0; jp < 4; jp++) {
                    if (k0 + jp*16 <= qwmax) {
                        uint32_t bh[4], bl[4];
                        ldsm_x4(bh, uKh + kboff + (uint32_t)(jp*16*ASTR*2) + ks*32);
                        ldsm_x4(bl, uKl + kboff + (uint32_t)(jp*16*ASTR*2) + ks*32);
                        mma_bf16(c[2*jp],   ah, bh);
                        mma_bf16(c[2*jp+1], ah, bh+2);
                        mma_bf16(c[2*jp],   ah, bl);
                        mma_bf16(c[2*jp+1], ah, bl+2);
                        mma_bf16(c[2*jp],   al, bh);
                        mma_bf16(c[2*jp+1], al, bh+2);
                    }
                }
            }

            if (k0 + 63 > qwmin) {
#pragma unroll
                for (int j = 0; j < 8; j++) {
                    int colb = k0 + j*8 + (lane & 3)*2;
                    if (colb     > rA) c[j][0] = -1e30f;
                    if (colb + 1 > rA) c[j][1] = -1e30f;
                    if (colb     > rB) c[j][2] = -1e30f;
                    if (colb + 1 > rB) c[j][3] = -1e30f;
                }
            }

            // ---- online softmax (base-2) ----
            float vmA = -1e30f, vmB = -1e30f;
#pragma unroll
            for (int j = 0; j < 8; j++) {
                vmA = fmaxf(vmA, fmaxf(c[j][0], c[j][1]));
                vmB = fmaxf(vmB, fmaxf(c[j][2], c[j][3]));
            }
            vmA = fmaxf(vmA, __shfl_xor_sync(0xffffffffu, vmA, 1));
            vmA = fmaxf(vmA, __shfl_xor_sync(0xffffffffu, vmA, 2));
            vmB = fmaxf(vmB, __shfl_xor_sync(0xffffffffu, vmB, 1));
            vmB = fmaxf(vmB, __shfl_xor_sync(0xffffffffu, vmB, 2));
            const float mnA = fmaxf(mA, vmA);
            const float mnB = fmaxf(mB, vmB);

            float sA = 0.f, sB = 0.f;
#pragma unroll
            for (int j = 0; j < 8; j++) {
                c[j][0] = exp2f(c[j][0] - mnA);
                c[j][1] = exp2f(c[j][1] - mnA);
                c[j][2] = exp2f(c[j][2] - mnB);
                c[j][3] = exp2f(c[j][3] - mnB);
                sA += c[j][0] + c[j][1];
                sB += c[j][2] + c[j][3];
            }
            sA += __shfl_xor_sync(0xffffffffu, sA, 1);
            sA += __shfl_xor_sync(0xffffffffu, sA, 2);
            sB += __shfl_xor_sync(0xffffffffu, sB, 1);
            sB += __shfl_xor_sync(0xffffffffu, sB, 2);

            const float soA = exp2f(mA - mnA);
            const float soB = exp2f(mB - mnB);
            lA = lA * soA + sA;  mA = mnA;
            lB = lB * soB + sB;  mB = mnB;

#pragma unroll
            for (int j = 0; j < 8; j++) {
                o[j][0] *= soA; o[j][1] *= soA;
                o[j][2] *= soB; o[j][3] *= soB;
            }

            // ---- O += P.V  (P fp16 hi/lo x V plain fp16: 4 MMAs/subtile) ----
#pragma unroll
            for (int kk = 0; kk < 4; kk++) {
                if (k0 + kk*16 <= qwmax) {
                    uint32_t ph[4], pl[4];
                    pack_hl2_f16(c[2*kk][0],   c[2*kk][1],   ph[0], pl[0]);
                    pack_hl2_f16(c[2*kk][2],   c[2*kk][3],   ph[1], pl[1]);
                    pack_hl2_f16(c[2*kk+1][0], c[2*kk+1][1], ph[2], pl[2]);
                    pack_hl2_f16(c[2*kk+1][2], c[2*kk+1][3], ph[3], pl[3]);
#pragma unroll
                    for (int jp = 0; jp < 4; jp++) {
                        uint32_t v[4];
                        ldsm_x4_t(v, uV + vboff + (uint32_t)(kk*16*ASTR*2) + jp*32);
                        mma_f16(o[2*jp],   ph, v);
                        mma_f16(o[2*jp+1], ph, v+2);
                        mma_f16(o[2*jp],   pl, v);
                        mma_f16(o[2*jp+1], pl, v+2);
                    }
                }
            }
        }
    }

    // epilogue: normalize + write plain fp16 AO [b, s, h*64+col]
    {
        const float invA = 1.f / lA;
        const float invB = 1.f / lB;
        const size_t offA = ((size_t)bb * SEQ + rA) * DMODEL + h * HDIM + (lane & 3) * 2;
        const size_t offB = ((size_t)bb * SEQ + rB) * DMODEL + h * HDIM + (lane & 3) * 2;
#pragma unroll
        for (int j = 0; j < 8; j++) {
            *(uint32_t*)(g_AO16 + offA + j*8) = pack_h16(o[j][0] * invA, o[j][1] * invA);
            *(uint32_t*)(g_AO16 + offB + j*8) = pack_h16(o[j][2] * invB, o[j][3] * invB);
        }
    }
}

// ---------------------------------------------------------------------------
extern "C" void kernel_launch(void* const* d_in, const int* in_sizes, int n_in,
                              void* d_out, int out_size)
{
    const float* x  = (const float*)d_in[0];
    const float* Wq = (const float*)d_in[1];
    const float* bq = (const float*)d_in[2];
    const float* Wk = (const float*)d_in[3];
    const float* bk = (const float*)d_in[4];
    const float* Wv = (const float*)d_in[5];
    const float* bv = (const float*)d_in[6];
    const float* Wo = (const float*)d_in[7];
    const float* bo = (const float*)d_in[8];
    float* out = (float*)d_out;

    cudaFuncSetAttribute(hl_gemm, cudaFuncAttributeMaxDynamicSharedMemorySize, GEMM_SMEM_BYTES);
    cudaFuncSetAttribute(attn_tc, cudaFuncAttributeMaxDynamicSharedMemorySize, ATTN_SMEM_BYTES);

    conv_x<<<(BATCH*SEQ*INDIM)/1024, 256>>>(x);
    conv_w4<<<dim3((DMODEL*INDIM)/1024, 4), 256>>>(Wq, Wk, Wv, Wo);

    GemmArgs qa;
    qa.bias0 = bq; qa.bias1 = bk; qa.bias2 = bv; qa.out_o = nullptr; qa.mode = 0;
    hl_gemm<<<dim3(DMODEL/BN, (BATCH*SEQ)/BM, 3), 256, GEMM_SMEM_BYTES>>>(qa);

    attn_tc<<<dim3(SEQ/128, NHEADS, BATCH), 256, ATTN_SMEM_BYTES>>>();

    GemmArgs oa;
    oa.bias0 = bo; oa.bias1 = nullptr; oa.bias2 = nullptr; oa.out_o = out; oa.mode = 1;
    hl_gemm<<<dim3(DMODEL/BN, (BATCH*SEQ)/BM, 1), 256, GEMM_SMEM_BYTES>>>(oa);
}

// round 12
// speedup vs baseline: 4.4990x; 1.0682x over previous
#include <cuda_runtime.h>
#include <cuda_bf16.h>
#include <cuda_fp16.h>
#include <stdint.h>
#include <math.h>

#define BATCH  4
#define SEQ    2048
#define INDIM  1024
#define DMODEL 1024
#define NHEADS 16
#define HDIM   64
#define KTOT   1024

// Q prescale: 1/sqrt(64) * log2(e)  (softmax runs in base-2)
#define QSCALE_LOG2E 0.1803368801111244f

// ---------------------------------------------------------------------------
// Device scratch
// ---------------------------------------------------------------------------
#define QKV_ELE (BATCH*NHEADS*SEQ*HDIM)
__device__ __nv_bfloat16 g_Qh[QKV_ELE], g_Ql[QKV_ELE];   // bf16 hi/lo, pre-scaled
__device__ __nv_bfloat16 g_Kh[QKV_ELE], g_Kl[QKV_ELE];   // bf16 hi/lo
__device__ __half g_V16[QKV_ELE];                        // plain fp16
__device__ __half g_AO16[BATCH*SEQ*DMODEL];              // plain fp16
__device__ __half g_x16[BATCH*SEQ*INDIM];                // plain fp16
__device__ __half g_Wh[4][DMODEL*INDIM], g_Wl[4][DMODEL*INDIM];  // fp16 hi/lo

// ---------------------------------------------------------------------------
// PTX helpers
// ---------------------------------------------------------------------------
__device__ __forceinline__ uint32_t smem_u32(const void* p) {
    uint32_t a;
    asm("{ .reg .u64 t; cvta.to.shared.u64 t, %1; cvt.u32.u64 %0, t; }"
        : "=r"(a) : "l"(p));
    return a;
}
__device__ __forceinline__ void cp_async16(uint32_t dst, const void* src) {
    asm volatile("cp.async.cg.shared.global [%0], [%1], 16;" :: "r"(dst), "l"(src));
}
__device__ __forceinline__ void cp_commit()  { asm volatile("cp.async.commit_group;"); }
__device__ __forceinline__ void cp_wait0()   { asm volatile("cp.async.wait_group 0;"); }

__device__ __forceinline__ void ldsm_x4(uint32_t* r, uint32_t a) {
    asm volatile("ldmatrix.sync.aligned.m8n8.x4.shared.b16 {%0,%1,%2,%3}, [%4];"
        : "=r"(r[0]), "=r"(r[1]), "=r"(r[2]), "=r"(r[3]) : "r"(a));
}
__device__ __forceinline__ void ldsm_x4_t(uint32_t* r, uint32_t a) {
    asm volatile("ldmatrix.sync.aligned.m8n8.x4.trans.shared.b16 {%0,%1,%2,%3}, [%4];"
        : "=r"(r[0]), "=r"(r[1]), "=r"(r[2]), "=r"(r[3]) : "r"(a));
}
__device__ __forceinline__ void mma_bf16(float* c, const uint32_t* a, const uint32_t* b) {
    asm volatile(
        "mma.sync.aligned.m16n8k16.row.col.f32.bf16.bf16.f32 "
        "{%0,%1,%2,%3}, {%4,%5,%6,%7}, {%8,%9}, {%0,%1,%2,%3};"
        : "+f"(c[0]), "+f"(c[1]), "+f"(c[2]), "+f"(c[3])
        : "r"(a[0]), "r"(a[1]), "r"(a[2]), "r"(a[3]), "r"(b[0]), "r"(b[1]));
}
__device__ __forceinline__ void mma_f16(float* c, const uint32_t* a, const uint32_t* b) {
    asm volatile(
        "mma.sync.aligned.m16n8k16.row.col.f32.f16.f16.f32 "
        "{%0,%1,%2,%3}, {%4,%5,%6,%7}, {%8,%9}, {%0,%1,%2,%3};"
        : "+f"(c[0]), "+f"(c[1]), "+f"(c[2]), "+f"(c[3])
        : "r"(a[0]), "r"(a[1]), "r"(a[2]), "r"(a[3]), "r"(b[0]), "r"(b[1]));
}

__device__ __forceinline__ void split_hl(float v, __nv_bfloat16& h, __nv_bfloat16& l) {
    h = __float2bfloat16(v);
    l = __float2bfloat16(v - __bfloat162float(h));
}
__device__ __forceinline__ void pack_hl2(float x, float y, uint32_t& hp, uint32_t& lp) {
    __nv_bfloat16 hx, lx, hy, ly;
    split_hl(x, hx, lx); split_hl(y, hy, ly);
    hp = ((uint32_t)__bfloat16_as_ushort(hy) << 16) | __bfloat16_as_ushort(hx);
    lp = ((uint32_t)__bfloat16_as_ushort(ly) << 16) | __bfloat16_as_ushort(lx);
}
__device__ __forceinline__ void split_hl16(float v, __half& h, __half& l) {
    h = __float2half(v);
    l = __float2half(v - __half2float(h));
}
__device__ __forceinline__ uint32_t pack_h16(float x, float y) {
    return ((uint32_t)__half_as_ushort(__float2half(y)) << 16)
         | __half_as_ushort(__float2half(x));
}

// ---------------------------------------------------------------------------
// converters:  x -> plain fp16 ;  W -> fp16 hi/lo
// ---------------------------------------------------------------------------
__global__ __launch_bounds__(256) void conv_x(const float* __restrict__ src)
{
    size_t i = ((size_t)blockIdx.x * 256 + threadIdx.x) * 4;
    float4 v = *(const float4*)(src + i);
    __half o[4] = { __float2half(v.x), __float2half(v.y),
                    __float2half(v.z), __float2half(v.w) };
    *(uint2*)(g_x16 + i) = *(uint2*)o;
}

__global__ __launch_bounds__(256) void conv_w4(
    const float* __restrict__ Wq, const float* __restrict__ Wk,
    const float* __restrict__ Wv, const float* __restrict__ Wo)
{
    const int w = blockIdx.y;
    const float* src = (w == 0) ? Wq : (w == 1) ? Wk : (w == 2) ? Wv : Wo;
    __half* h = g_Wh[w];
    __half* l = g_Wl[w];
    size_t i = ((size_t)blockIdx.x * 256 + threadIdx.x) * 4;
    float4 v = *(const float4*)(src + i);
    __half h0, h1, h2, h3, l0, l1, l2, l3;
    split_hl16(v.x, h0, l0); split_hl16(v.y, h1, l1);
    split_hl16(v.z, h2, l2); split_hl16(v.w, h3, l3);
    __half hh[4] = {h0, h1, h2, h3};
    __half ll[4] = {l0, l1, l2, l3};
    *(uint2*)(h + i) = *(uint2*)hh;
    *(uint2*)(l + i) = *(uint2*)ll;
}

// ---------------------------------------------------------------------------
// fp16 2-MMA GEMM:  C[m,n] = sum_k A[m,k]*W[n,k] + bias[n]
// 128x128 block, 8 warps, BK=64, 2-stage cp.async, 2 CTAs/SM.
// mode 0: QKV -> Q/K bf16 hi/lo, V plain fp16, scatter [B,H,S,Dh]
// mode 1: O-proj -> fp32 out
// ---------------------------------------------------------------------------
#define BM 128
#define BN 128
#define BK 64
#define NCH (KTOT/BK)          // 16
#define LDK 72
#define TILE_E (128*LDK)
#define STAGE_E (3*TILE_E)
#define GEMM_SMEM_BYTES (2*STAGE_E*2)   // 110592

struct GemmArgs {
    const float* bias0; const float* bias1; const float* bias2;
    float* out_o;
    int mode;
};

__global__ __launch_bounds__(256, 2) void hl_gemm(GemmArgs args)
{
    extern __shared__ __align__(16) char dsm[];
    __half* smT = (__half*)dsm;

    const int t    = threadIdx.x;
    const int wid  = t >> 5;
    const int lane = t & 31;
    const int z    = blockIdx.z;
    const int m0   = blockIdx.y * BM;
    const int n0   = blockIdx.x * BN;
    const int wm   = wid & 1;
    const int wn   = wid >> 1;

    const __half *Ax, *Bh, *Bl;
    const float* bias;
    if (args.mode == 0) {
        Ax = g_x16;
        Bh = g_Wh[z]; Bl = g_Wl[z];
        bias = (z == 0) ? args.bias0 : (z == 1) ? args.bias1 : args.bias2;
    } else {
        Ax = g_AO16;
        Bh = g_Wh[3]; Bl = g_Wl[3];
        bias = args.bias0;
    }
    const __half* srcs[3] = { Ax, Bh, Bl };
    const int r0s[3] = { m0, n0, n0 };

    const uint32_t ub = smem_u32(smT);
    const uint32_t abase = (uint32_t)(((wm*64 + (lane & 15)) * LDK + ((lane >> 4) << 3)) * 2);
    const uint32_t bbase = (uint32_t)(((wn*32 + ((lane >> 4) << 3) + (lane & 7)) * LDK
                                      + (((lane >> 3) & 1) << 3)) * 2);

    float c[4][4][4];
#pragma unroll
    for (int mi = 0; mi < 4; mi++)
#pragma unroll
        for (int nj = 0; nj < 4; nj++)
#pragma unroll
            for (int r = 0; r < 4; r++) c[mi][nj][r] = 0.f;

    auto load_stage = [&](int stage, int kc) {
#pragma unroll
        for (int it = 0; it < 12; it++) {
            int idx  = t + it * 256;
            int tile = idx >> 10;
            int rem  = idx & 1023;
            int row  = rem >> 3;
            int ch   = rem & 7;
            const __half* sp = srcs[tile]
                + (size_t)(r0s[tile] + row) * KTOT + kc * BK + ch * 8;
            uint32_t dp = ub + (uint32_t)((stage * 3 + tile) * TILE_E + row * LDK + ch * 8) * 2;
            cp_async16(dp, sp);
        }
        cp_commit();
    };

    load_stage(0, 0);

    for (int kc = 0; kc < NCH; kc++) {
        cp_wait0();
        __syncthreads();
        if (kc + 1 < NCH) load_stage((kc + 1) & 1, kc + 1);

        const int s = kc & 1;
        const uint32_t uA  = ub + (uint32_t)((s*3 + 0) * TILE_E) * 2;
        const uint32_t uBh = ub + (uint32_t)((s*3 + 1) * TILE_E) * 2;
        const uint32_t uBl = ub + (uint32_t)((s*3 + 2) * TILE_E) * 2;

#pragma unroll
        for (int ks = 0; ks < 4; ks++) {
            uint32_t a[4][4];
#pragma unroll
            for (int mi = 0; mi < 4; mi++)
                ldsm_x4(a[mi], uA + abase + (uint32_t)(mi * 16 * LDK * 2) + ks * 32);
            uint32_t bh[2][4], bl[2][4];
#pragma unroll
            for (int j2 = 0; j2 < 2; j2++) {
                ldsm_x4(bh[j2], uBh + bbase + (uint32_t)(j2 * 16 * LDK * 2) + ks * 32);
                ldsm_x4(bl[j2], uBl + bbase + (uint32_t)(j2 * 16 * LDK * 2) + ks * 32);
            }
#pragma unroll
            for (int mi = 0; mi < 4; mi++)
#pragma unroll
                for (int nj = 0; nj < 4; nj++)
                    mma_f16(c[mi][nj], a[mi], &bh[nj >> 1][(nj & 1) * 2]);
#pragma unroll
            for (int mi = 0; mi < 4; mi++)
#pragma unroll
                for (int nj = 0; nj < 4; nj++)
                    mma_f16(c[mi][nj], a[mi], &bl[nj >> 1][(nj & 1) * 2]);
        }
    }

    // -------- register epilogue --------
    const float qscale = (args.mode == 0 && z == 0) ? QSCALE_LOG2E : 1.0f;
    float2 bv[4];
    int nn[4];
#pragma unroll
    for (int nj = 0; nj < 4; nj++) {
        nn[nj] = n0 + wn*32 + nj*8 + (lane & 3)*2;
        bv[nj] = *(const float2*)&bias[nn[nj]];
    }

    if (args.mode == 0) {
#pragma unroll
        for (int mi = 0; mi < 4; mi++) {
#pragma unroll
            for (int half = 0; half < 2; half++) {
                const int m  = m0 + wm*64 + mi*16 + (lane >> 2) + half*8;
                const int bb = m >> 11;
                const int ss = m & (SEQ - 1);
#pragma unroll
                for (int nj = 0; nj < 4; nj++) {
                    const int n  = nn[nj];
                    const int h  = n >> 6;
                    const int dh = n & 63;
                    const float v0 = (c[mi][nj][half*2+0] + bv[nj].x) * qscale;
                    const float v1 = (c[mi][nj][half*2+1] + bv[nj].y) * qscale;
                    const size_t off = (((size_t)bb * NHEADS + h) * SEQ + ss) * HDIM + dh;
                    if (z == 2) {
                        *(uint32_t*)(g_V16 + off) = pack_h16(v0, v1);
                    } else {
                        __nv_bfloat16 *dh_ = (z == 0) ? g_Qh : g_Kh;
                        __nv_bfloat16 *dl_ = (z == 0) ? g_Ql : g_Kl;
                        uint32_t hp, lp;
                        pack_hl2(v0, v1, hp, lp);
                        *(uint32_t*)(dh_ + off) = hp;
                        *(uint32_t*)(dl_ + off) = lp;
                    }
                }
            }
        }
    } else {
        float* outp = args.out_o;
#pragma unroll
        for (int mi = 0; mi < 4; mi++) {
#pragma unroll
            for (int half = 0; half < 2; half++) {
                const int m = m0 + wm*64 + mi*16 + (lane >> 2) + half*8;
#pragma unroll
                for (int nj = 0; nj < 4; nj++) {
                    const float v0 = c[mi][nj][half*2+0] + bv[nj].x;
                    const float v1 = c[mi][nj][half*2+1] + bv[nj].y;
                    *(float2*)(outp + (size_t)m * DMODEL + nn[nj]) = make_float2(v0, v1);
                }
            }
        }
    }
}

// ---------------------------------------------------------------------------
// Register-resident causal flash attention.
// QK: bf16 3-MMA (Q/K hi/lo).  PV: plain fp16 P x plain fp16 V (2 MMAs/subtile).
// Softmax in base-2.  Diagonal subtile skipping.
// ---------------------------------------------------------------------------
#define ASTR 72
#define KVBUF 27648
#define ATTN_SMEM_BYTES (36864 + 2*KVBUF)   // 92160

__global__ __launch_bounds__(256, 2) void attn_tc()
{
    extern __shared__ __align__(16) char asmem[];
    __nv_bfloat16* sQh = (__nv_bfloat16*)(asmem);
    __nv_bfloat16* sQl = (__nv_bfloat16*)(asmem + 18432);

    const int t    = threadIdx.x;
    const int wid  = t >> 5;
    const int lane = t & 31;
    const int bq   = gridDim.x - 1 - blockIdx.x;   // heavy tiles first
    const int h    = blockIdx.y;
    const int bb   = blockIdx.z;
    const int q0   = bq * 128;
    const size_t base = ((size_t)bb * NHEADS + h) * SEQ * HDIM;

    const char* gsrc[3] = { (const char*)g_Kh, (const char*)g_Kl, (const char*)g_V16 };

    auto load_kv = [&](int buf, int k0) {
        char* dst0 = asmem + 36864 + buf * KVBUF;
#pragma unroll
        for (int it = 0; it < 6; it++) {
            int idx = t + it * 256;
            int a   = idx >> 9;
            int rem = idx & 511;
            int row = rem >> 3, ch = rem & 7;
            uint32_t dp = smem_u32(dst0 + a * 9216 + (row * ASTR + ch * 8) * 2);
            cp_async16(dp, gsrc[a] + (base + (size_t)(k0 + row) * HDIM + ch * 8) * 2);
        }
        cp_commit();
    };

    {
#pragma unroll
        for (int it = 0; it < 8; it++) {
            int idx = t + it * 256;
            int a   = idx >> 10;
            int rem = idx & 1023;
            int row = rem >> 3, ch = rem & 7;
            const __nv_bfloat16* src = (a == 0 ? g_Qh : g_Ql) + base + (size_t)(q0 + row) * HDIM + ch * 8;
            uint32_t dp = smem_u32(asmem + a * 18432 + (row * ASTR + ch * 8) * 2);
            cp_async16(dp, src);
        }
        cp_commit();
    }
    load_kv(0, 0);

    const uint32_t uQh = smem_u32(sQh), uQl = smem_u32(sQl);
    const uint32_t aoff  = (uint32_t)(((wid*16 + (lane & 15)) * ASTR + ((lane >> 4) << 3)) * 2);
    const uint32_t kboff = (uint32_t)(((((lane >> 4) << 3) + (lane & 7)) * ASTR + (((lane >> 3) & 1) << 3)) * 2);
    const uint32_t vboff = (uint32_t)((((((lane >> 3) & 1) << 3) + (lane & 7)) * ASTR + ((lane >> 4) << 3)) * 2);

    float o[8][4];
#pragma unroll
    for (int j = 0; j < 8; j++)
#pragma unroll
        for (int r = 0; r < 4; r++) o[j][r] = 0.f;

    const int rA = q0 + wid*16 + (lane >> 2);
    const int rB = rA + 8;
    const int qwmin = q0 + wid*16;
    const int qwmax = qwmin + 15;
    float mA = -1e30f, mB = -1e30f, lA = 0.f, lB = 0.f;

    const int nkt = 2*bq + 2;
    for (int kt = 0; kt < nkt; kt++) {
        const int k0 = kt * 64;
        cp_wait0();
        __syncthreads();
        if (kt + 1 < nkt) load_kv((kt + 1) & 1, k0 + 64);

        const uint32_t ukv = smem_u32(asmem + 36864 + (kt & 1) * KVBUF);
        const uint32_t uKh = ukv, uKl = ukv + 9216, uV = ukv + 18432;

        if (k0 <= qwmax) {
            float c[8][4];
#pragma unroll
            for (int j = 0; j < 8; j++)
#pragma unroll
                for (int r = 0; r < 4; r++) c[j][r] = 0.f;

            // ---- S = Q.K^T (bf16 3-MMA), skip fully-masked jp subtiles ----
#pragma unroll
            for (int ks = 0; ks < 4; ks++) {
                uint32_t ah[4], al[4];
                ldsm_x4(ah, uQh + aoff + ks*32);
                ldsm_x4(al, uQl + aoff + ks*32);
#pragma unroll
                for (int jp = 0; jp < 4; jp++) {
                    if (k0 + jp*16 <= qwmax) {
                        uint32_t bh[4], bl[4];
                        ldsm_x4(bh, uKh + kboff + (uint32_t)(jp*16*ASTR*2) + ks*32);
                        ldsm_x4(bl, uKl + kboff + (uint32_t)(jp*16*ASTR*2) + ks*32);
                        mma_bf16(c[2*jp],   ah, bh);
                        mma_bf16(c[2*jp+1], ah, bh+2);
                        mma_bf16(c[2*jp],   ah, bl);
                        mma_bf16(c[2*jp+1], ah, bl+2);
                        mma_bf16(c[2*jp],   al, bh);
                        mma_bf16(c[2*jp+1], al, bh+2);
                    }
                }
            }

            if (k0 + 63 > qwmin) {
#pragma unroll
                for (int j = 0; j < 8; j++) {
                    int colb = k0 + j*8 + (lane & 3)*2;
                    if (colb     > rA) c[j][0] = -1e30f;
                    if (colb + 1 > rA) c[j][1] = -1e30f;
                    if (colb     > rB) c[j][2] = -1e30f;
                    if (colb + 1 > rB) c[j][3] = -1e30f;
                }
            }

            // ---- online softmax (base-2) ----
            float vmA = -1e30f, vmB = -1e30f;
#pragma unroll
            for (int j = 0; j < 8; j++) {
                vmA = fmaxf(vmA, fmaxf(c[j][0], c[j][1]));
                vmB = fmaxf(vmB, fmaxf(c[j][2], c[j][3]));
            }
            vmA = fmaxf(vmA, __shfl_xor_sync(0xffffffffu, vmA, 1));
            vmA = fmaxf(vmA, __shfl_xor_sync(0xffffffffu, vmA, 2));
            vmB = fmaxf(vmB, __shfl_xor_sync(0xffffffffu, vmB, 1));
            vmB = fmaxf(vmB, __shfl_xor_sync(0xffffffffu, vmB, 2));
            const float mnA = fmaxf(mA, vmA);
            const float mnB = fmaxf(mB, vmB);

            float sA = 0.f, sB = 0.f;
#pragma unroll
            for (int j = 0; j < 8; j++) {
                c[j][0] = exp2f(c[j][0] - mnA);
                c[j][1] = exp2f(c[j][1] - mnA);
                c[j][2] = exp2f(c[j][2] - mnB);
                c[j][3] = exp2f(c[j][3] - mnB);
                sA += c[j][0] + c[j][1];
                sB += c[j][2] + c[j][3];
            }
            sA += __shfl_xor_sync(0xffffffffu, sA, 1);
            sA += __shfl_xor_sync(0xffffffffu, sA, 2);
            sB += __shfl_xor_sync(0xffffffffu, sB, 1);
            sB += __shfl_xor_sync(0xffffffffu, sB, 2);

            const float soA = exp2f(mA - mnA);
            const float soB = exp2f(mB - mnB);
            lA = lA * soA + sA;  mA = mnA;
            lB = lB * soB + sB;  mB = mnB;

#pragma unroll
            for (int j = 0; j < 8; j++) {
                o[j][0] *= soA; o[j][1] *= soA;
                o[j][2] *= soB; o[j][3] *= soB;
            }

            // ---- O += P.V  (plain fp16 P x plain fp16 V: 2 MMAs/subtile) ----
#pragma unroll
            for (int kk = 0; kk < 4; kk++) {
                if (k0 + kk*16 <= qwmax) {
                    uint32_t p[4];
                    p[0] = pack_h16(c[2*kk][0],   c[2*kk][1]);
                    p[1] = pack_h16(c[2*kk][2],   c[2*kk][3]);
                    p[2] = pack_h16(c[2*kk+1][0], c[2*kk+1][1]);
                    p[3] = pack_h16(c[2*kk+1][2], c[2*kk+1][3]);
#pragma unroll
                    for (int jp = 0; jp < 4; jp++) {
                        uint32_t v[4];
                        ldsm_x4_t(v, uV + vboff + (uint32_t)(kk*16*ASTR*2) + jp*32);
                        mma_f16(o[2*jp],   p, v);
                        mma_f16(o[2*jp+1], p, v+2);
                    }
                }
            }
        }
    }

    // epilogue: normalize + write plain fp16 AO [b, s, h*64+col]
    {
        const float invA = 1.f / lA;
        const float invB = 1.f / lB;
        const size_t offA = ((size_t)bb * SEQ + rA) * DMODEL + h * HDIM + (lane & 3) * 2;
        const size_t offB = ((size_t)bb * SEQ + rB) * DMODEL + h * HDIM + (lane & 3) * 2;
#pragma unroll
        for (int j = 0; j < 8; j++) {
            *(uint32_t*)(g_AO16 + offA + j*8) = pack_h16(o[j][0] * invA, o[j][1] * invA);
            *(uint32_t*)(g_AO16 + offB + j*8) = pack_h16(o[j][2] * invB, o[j][3] * invB);
        }
    }
}

// ---------------------------------------------------------------------------
extern "C" void kernel_launch(void* const* d_in, const int* in_sizes, int n_in,
                              void* d_out, int out_size)
{
    const float* x  = (const float*)d_in[0];
    const float* Wq = (const float*)d_in[1];
    const float* bq = (const float*)d_in[2];
    const float* Wk = (const float*)d_in[3];
    const float* bk = (const float*)d_in[4];
    const float* Wv = (const float*)d_in[5];
    const float* bv = (const float*)d_in[6];
    const float* Wo = (const float*)d_in[7];
    const float* bo = (const float*)d_in[8];
    float* out = (float*)d_out;

    cudaFuncSetAttribute(hl_gemm, cudaFuncAttributeMaxDynamicSharedMemorySize, GEMM_SMEM_BYTES);
    cudaFuncSetAttribute(attn_tc, cudaFuncAttributeMaxDynamicSharedMemorySize, ATTN_SMEM_BYTES);

    conv_x<<<(BATCH*SEQ*INDIM)/1024, 256>>>(x);
    conv_w4<<<dim3((DMODEL*INDIM)/1024, 4), 256>>>(Wq, Wk, Wv, Wo);

    GemmArgs qa;
    qa.bias0 = bq; qa.bias1 = bk; qa.bias2 = bv; qa.out_o = nullptr; qa.mode = 0;
    hl_gemm<<<dim3(DMODEL/BN, (BATCH*SEQ)/BM, 3), 256, GEMM_SMEM_BYTES>>>(qa);

    attn_tc<<<dim3(SEQ/128, NHEADS, BATCH), 256, ATTN_SMEM_BYTES>>>();

    GemmArgs oa;
    oa.bias0 = bo; oa.bias1 = nullptr; oa.bias2 = nullptr; oa.out_o = out; oa.mode = 1;
    hl_gemm<<<dim3(DMODEL/BN, (BATCH*SEQ)/BM, 1), 256, GEMM_SMEM_BYTES>>>(oa);
}

// round 13
// speedup vs baseline: 4.8131x; 1.0698x over previous
#include <cuda_runtime.h>
#include <cuda_bf16.h>
#include <cuda_fp16.h>
#include <stdint.h>
#include <math.h>

#define BATCH  4
#define SEQ    2048
#define INDIM  1024
#define DMODEL 1024
#define NHEADS 16
#define HDIM   64
#define KTOT   1024

// Q prescale: 1/sqrt(64) * log2(e)  (softmax runs in base-2)
#define QSCALE_LOG2E 0.1803368801111244f

// ---------------------------------------------------------------------------
// Device scratch (all fp16 now)
// ---------------------------------------------------------------------------
#define QKV_ELE (BATCH*NHEADS*SEQ*HDIM)
__device__ __half g_Q16[QKV_ELE];                        // plain fp16, pre-scaled
__device__ __half g_Kh16[QKV_ELE], g_Kl16[QKV_ELE];      // fp16 hi/lo
__device__ __half g_V16[QKV_ELE];                        // plain fp16
__device__ __half g_AO16[BATCH*SEQ*DMODEL];              // plain fp16
__device__ __half g_x16[BATCH*SEQ*INDIM];                // plain fp16
__device__ __half g_Wh[4][DMODEL*INDIM], g_Wl[4][DMODEL*INDIM];  // fp16 hi/lo

// ---------------------------------------------------------------------------
// PTX helpers
// ---------------------------------------------------------------------------
__device__ __forceinline__ uint32_t smem_u32(const void* p) {
    uint32_t a;
    asm("{ .reg .u64 t; cvta.to.shared.u64 t, %1; cvt.u32.u64 %0, t; }"
        : "=r"(a) : "l"(p));
    return a;
}
__device__ __forceinline__ void cp_async16(uint32_t dst, const void* src) {
    asm volatile("cp.async.cg.shared.global [%0], [%1], 16;" :: "r"(dst), "l"(src));
}
__device__ __forceinline__ void cp_commit()  { asm volatile("cp.async.commit_group;"); }
__device__ __forceinline__ void cp_wait0()   { asm volatile("cp.async.wait_group 0;"); }

__device__ __forceinline__ void ldsm_x4(uint32_t* r, uint32_t a) {
    asm volatile("ldmatrix.sync.aligned.m8n8.x4.shared.b16 {%0,%1,%2,%3}, [%4];"
        : "=r"(r[0]), "=r"(r[1]), "=r"(r[2]), "=r"(r[3]) : "r"(a));
}
__device__ __forceinline__ void ldsm_x4_t(uint32_t* r, uint32_t a) {
    asm volatile("ldmatrix.sync.aligned.m8n8.x4.trans.shared.b16 {%0,%1,%2,%3}, [%4];"
        : "=r"(r[0]), "=r"(r[1]), "=r"(r[2]), "=r"(r[3]) : "r"(a));
}
__device__ __forceinline__ void mma_f16(float* c, const uint32_t* a, const uint32_t* b) {
    asm volatile(
        "mma.sync.aligned.m16n8k16.row.col.f32.f16.f16.f32 "
        "{%0,%1,%2,%3}, {%4,%5,%6,%7}, {%8,%9}, {%0,%1,%2,%3};"
        : "+f"(c[0]), "+f"(c[1]), "+f"(c[2]), "+f"(c[3])
        : "r"(a[0]), "r"(a[1]), "r"(a[2]), "r"(a[3]), "r"(b[0]), "r"(b[1]));
}

__device__ __forceinline__ void split_hl16(float v, __half& h, __half& l) {
    h = __float2half(v);
    l = __float2half(v - __half2float(h));
}
__device__ __forceinline__ void pack_hl2_f16(float x, float y, uint32_t& hp, uint32_t& lp) {
    __half hx, lx, hy, ly;
    split_hl16(x, hx, lx); split_hl16(y, hy, ly);
    hp = ((uint32_t)__half_as_ushort(hy) << 16) | __half_as_ushort(hx);
    lp = ((uint32_t)__half_as_ushort(ly) << 16) | __half_as_ushort(lx);
}
__device__ __forceinline__ uint32_t pack_h16(float x, float y) {
    return ((uint32_t)__half_as_ushort(__float2half(y)) << 16)
         | __half_as_ushort(__float2half(x));
}

// ---------------------------------------------------------------------------
// converters:  x -> plain fp16 ;  W -> fp16 hi/lo
// ---------------------------------------------------------------------------
__global__ __launch_bounds__(256) void conv_x(const float* __restrict__ src)
{
    size_t i = ((size_t)blockIdx.x * 256 + threadIdx.x) * 4;
    float4 v = *(const float4*)(src + i);
    __half o[4] = { __float2half(v.x), __float2half(v.y),
                    __float2half(v.z), __float2half(v.w) };
    *(uint2*)(g_x16 + i) = *(uint2*)o;
}

__global__ __launch_bounds__(256) void conv_w4(
    const float* __restrict__ Wq, const float* __restrict__ Wk,
    const float* __restrict__ Wv, const float* __restrict__ Wo)
{
    const int w = blockIdx.y;
    const float* src = (w == 0) ? Wq : (w == 1) ? Wk : (w == 2) ? Wv : Wo;
    __half* h = g_Wh[w];
    __half* l = g_Wl[w];
    size_t i = ((size_t)blockIdx.x * 256 + threadIdx.x) * 4;
    float4 v = *(const float4*)(src + i);
    __half h0, h1, h2, h3, l0, l1, l2, l3;
    split_hl16(v.x, h0, l0); split_hl16(v.y, h1, l1);
    split_hl16(v.z, h2, l2); split_hl16(v.w, h3, l3);
    __half hh[4] = {h0, h1, h2, h3};
    __half ll[4] = {l0, l1, l2, l3};
    *(uint2*)(h + i) = *(uint2*)hh;
    *(uint2*)(l + i) = *(uint2*)ll;
}

// ---------------------------------------------------------------------------
// fp16 2-MMA GEMM:  C[m,n] = sum_k A[m,k]*W[n,k] + bias[n]
// 128x128 block, 8 warps, BK=64, 2-stage cp.async, 2 CTAs/SM.
// mode 0: QKV -> Q plain fp16 (scaled), K fp16 hi/lo, V plain fp16, [B,H,S,Dh]
// mode 1: O-proj -> fp32 out
// ---------------------------------------------------------------------------
#define BM 128
#define BN 128
#define BK 64
#define NCH (KTOT/BK)          // 16
#define LDK 72
#define TILE_E (128*LDK)
#define STAGE_E (3*TILE_E)
#define GEMM_SMEM_BYTES (2*STAGE_E*2)   // 110592

struct GemmArgs {
    const float* bias0; const float* bias1; const float* bias2;
    float* out_o;
    int mode;
};

__global__ __launch_bounds__(256, 2) void hl_gemm(GemmArgs args)
{
    extern __shared__ __align__(16) char dsm[];
    __half* smT = (__half*)dsm;

    const int t    = threadIdx.x;
    const int wid  = t >> 5;
    const int lane = t & 31;
    const int z    = blockIdx.z;
    const int m0   = blockIdx.y * BM;
    const int n0   = blockIdx.x * BN;
    const int wm   = wid & 1;
    const int wn   = wid >> 1;

    const __half *Ax, *Bh, *Bl;
    const float* bias;
    if (args.mode == 0) {
        Ax = g_x16;
        Bh = g_Wh[z]; Bl = g_Wl[z];
        bias = (z == 0) ? args.bias0 : (z == 1) ? args.bias1 : args.bias2;
    } else {
        Ax = g_AO16;
        Bh = g_Wh[3]; Bl = g_Wl[3];
        bias = args.bias0;
    }
    const __half* srcs[3] = { Ax, Bh, Bl };
    const int r0s[3] = { m0, n0, n0 };

    const uint32_t ub = smem_u32(smT);
    const uint32_t abase = (uint32_t)(((wm*64 + (lane & 15)) * LDK + ((lane >> 4) << 3)) * 2);
    const uint32_t bbase = (uint32_t)(((wn*32 + ((lane >> 4) << 3) + (lane & 7)) * LDK
                                      + (((lane >> 3) & 1) << 3)) * 2);

    float c[4][4][4];
#pragma unroll
    for (int mi = 0; mi < 4; mi++)
#pragma unroll
        for (int nj = 0; nj < 4; nj++)
#pragma unroll
            for (int r = 0; r < 4; r++) c[mi][nj][r] = 0.f;

    auto load_stage = [&](int stage, int kc) {
#pragma unroll
        for (int it = 0; it < 12; it++) {
            int idx  = t + it * 256;
            int tile = idx >> 10;
            int rem  = idx & 1023;
            int row  = rem >> 3;
            int ch   = rem & 7;
            const __half* sp = srcs[tile]
                + (size_t)(r0s[tile] + row) * KTOT + kc * BK + ch * 8;
            uint32_t dp = ub + (uint32_t)((stage * 3 + tile) * TILE_E + row * LDK + ch * 8) * 2;
            cp_async16(dp, sp);
        }
        cp_commit();
    };

    load_stage(0, 0);

    for (int kc = 0; kc < NCH; kc++) {
        cp_wait0();
        __syncthreads();
        if (kc + 1 < NCH) load_stage((kc + 1) & 1, kc + 1);

        const int s = kc & 1;
        const uint32_t uA  = ub + (uint32_t)((s*3 + 0) * TILE_E) * 2;
        const uint32_t uBh = ub + (uint32_t)((s*3 + 1) * TILE_E) * 2;
        const uint32_t uBl = ub + (uint32_t)((s*3 + 2) * TILE_E) * 2;

#pragma unroll
        for (int ks = 0; ks < 4; ks++) {
            uint32_t a[4][4];
#pragma unroll
            for (int mi = 0; mi < 4; mi++)
                ldsm_x4(a[mi], uA + abase + (uint32_t)(mi * 16 * LDK * 2) + ks * 32);
            uint32_t bh[2][4], bl[2][4];
#pragma unroll
            for (int j2 = 0; j2 < 2; j2++) {
                ldsm_x4(bh[j2], uBh + bbase + (uint32_t)(j2 * 16 * LDK * 2) + ks * 32);
                ldsm_x4(bl[j2], uBl + bbase + (uint32_t)(j2 * 16 * LDK * 2) + ks * 32);
            }
#pragma unroll
            for (int mi = 0; mi < 4; mi++)
#pragma unroll
                for (int nj = 0; nj < 4; nj++)
                    mma_f16(c[mi][nj], a[mi], &bh[nj >> 1][(nj & 1) * 2]);
#pragma unroll
            for (int mi = 0; mi < 4; mi++)
#pragma unroll
                for (int nj = 0; nj < 4; nj++)
                    mma_f16(c[mi][nj], a[mi], &bl[nj >> 1][(nj & 1) * 2]);
        }
    }

    // -------- register epilogue --------
    const float qscale = (args.mode == 0 && z == 0) ? QSCALE_LOG2E : 1.0f;
    float2 bv[4];
    int nn[4];
#pragma unroll
    for (int nj = 0; nj < 4; nj++) {
        nn[nj] = n0 + wn*32 + nj*8 + (lane & 3)*2;
        bv[nj] = *(const float2*)&bias[nn[nj]];
    }

    if (args.mode == 0) {
#pragma unroll
        for (int mi = 0; mi < 4; mi++) {
#pragma unroll
            for (int half = 0; half < 2; half++) {
                const int m  = m0 + wm*64 + mi*16 + (lane >> 2) + half*8;
                const int bb = m >> 11;
                const int ss = m & (SEQ - 1);
#pragma unroll
                for (int nj = 0; nj < 4; nj++) {
                    const int n  = nn[nj];
                    const int h  = n >> 6;
                    const int dh = n & 63;
                    const float v0 = (c[mi][nj][half*2+0] + bv[nj].x) * qscale;
                    const float v1 = (c[mi][nj][half*2+1] + bv[nj].y) * qscale;
                    const size_t off = (((size_t)bb * NHEADS + h) * SEQ + ss) * HDIM + dh;
                    if (z == 0) {
                        *(uint32_t*)(g_Q16 + off) = pack_h16(v0, v1);
                    } else if (z == 2) {
                        *(uint32_t*)(g_V16 + off) = pack_h16(v0, v1);
                    } else {
                        uint32_t hp, lp;
                        pack_hl2_f16(v0, v1, hp, lp);
                        *(uint32_t*)(g_Kh16 + off) = hp;
                        *(uint32_t*)(g_Kl16 + off) = lp;
                    }
                }
            }
        }
    } else {
        float* outp = args.out_o;
#pragma unroll
        for (int mi = 0; mi < 4; mi++) {
#pragma unroll
            for (int half = 0; half < 2; half++) {
                const int m = m0 + wm*64 + mi*16 + (lane >> 2) + half*8;
#pragma unroll
                for (int nj = 0; nj < 4; nj++) {
                    const float v0 = c[mi][nj][half*2+0] + bv[nj].x;
                    const float v1 = c[mi][nj][half*2+1] + bv[nj].y;
                    *(float2*)(outp + (size_t)m * DMODEL + nn[nj]) = make_float2(v0, v1);
                }
            }
        }
    }
}

// ---------------------------------------------------------------------------
// Register-resident causal flash attention — all fp16.
// QK: Q plain fp16 x K fp16 hi/lo (2 MMAs/c-frag).  PV: plain x plain.
// Softmax in base-2.  Diagonal subtile skipping.
// SMEM: Q 128x72 fp16 (18432) + 2 KV buffers (Kh,Kl,V fp16 = 27648 each).
// ---------------------------------------------------------------------------
#define ASTR 72
#define KVBUF 27648
#define ATTN_SMEM_BYTES (18432 + 2*KVBUF)   // 73728

__global__ __launch_bounds__(256, 2) void attn_tc()
{
    extern __shared__ __align__(16) char asmem[];
    __half* sQ = (__half*)(asmem);

    const int t    = threadIdx.x;
    const int wid  = t >> 5;
    const int lane = t & 31;
    const int bq   = gridDim.x - 1 - blockIdx.x;   // heavy tiles first
    const int h    = blockIdx.y;
    const int bb   = blockIdx.z;
    const int q0   = bq * 128;
    const size_t base = ((size_t)bb * NHEADS + h) * SEQ * HDIM;

    const char* gsrc[3] = { (const char*)g_Kh16, (const char*)g_Kl16, (const char*)g_V16 };

    auto load_kv = [&](int buf, int k0) {
        char* dst0 = asmem + 18432 + buf * KVBUF;
#pragma unroll
        for (int it = 0; it < 6; it++) {
            int idx = t + it * 256;          // 0..1535: 3 arrays x 64 rows x 8 chunks
            int a   = idx >> 9;
            int rem = idx & 511;
            int row = rem >> 3, ch = rem & 7;
            uint32_t dp = smem_u32(dst0 + a * 9216 + (row * ASTR + ch * 8) * 2);
            cp_async16(dp, gsrc[a] + (base + (size_t)(k0 + row) * HDIM + ch * 8) * 2);
        }
        cp_commit();
    };

    // Q loader: 128 rows x 8 chunks = 1024, 4/thread
    {
#pragma unroll
        for (int it = 0; it < 4; it++) {
            int idx = t + it * 256;
            int row = idx >> 3, ch = idx & 7;
            uint32_t dp = smem_u32(asmem + (row * ASTR + ch * 8) * 2);
            cp_async16(dp, g_Q16 + base + (size_t)(q0 + row) * HDIM + ch * 8);
        }
        cp_commit();
    }
    load_kv(0, 0);

    const uint32_t uQ = smem_u32(sQ);
    const uint32_t aoff  = (uint32_t)(((wid*16 + (lane & 15)) * ASTR + ((lane >> 4) << 3)) * 2);
    const uint32_t kboff = (uint32_t)(((((lane >> 4) << 3) + (lane & 7)) * ASTR + (((lane >> 3) & 1) << 3)) * 2);
    const uint32_t vboff = (uint32_t)((((((lane >> 3) & 1) << 3) + (lane & 7)) * ASTR + ((lane >> 4) << 3)) * 2);

    float o[8][4];
#pragma unroll
    for (int j = 0; j < 8; j++)
#pragma unroll
        for (int r = 0; r < 4; r++) o[j][r] = 0.f;

    const int rA = q0 + wid*16 + (lane >> 2);
    const int rB = rA + 8;
    const int qwmin = q0 + wid*16;
    const int qwmax = qwmin + 15;
    float mA = -1e30f, mB = -1e30f, lA = 0.f, lB = 0.f;

    const int nkt = 2*bq + 2;
    for (int kt = 0; kt < nkt; kt++) {
        const int k0 = kt * 64;
        cp_wait0();
        __syncthreads();
        if (kt + 1 < nkt) load_kv((kt + 1) & 1, k0 + 64);

        const uint32_t ukv = smem_u32(asmem + 18432 + (kt & 1) * KVBUF);
        const uint32_t uKh = ukv, uKl = ukv + 9216, uV = ukv + 18432;

        if (k0 <= qwmax) {
            float c[8][4];
#pragma unroll
            for (int j = 0; j < 8; j++)
#pragma unroll
                for (int r = 0; r < 4; r++) c[j][r] = 0.f;

            // ---- S = Q.K^T  (Q plain x K hi/lo: 2 MMAs per c-frag) ----
#pragma unroll
            for (int ks = 0; ks < 4; ks++) {
                uint32_t a[4];
                ldsm_x4(a, uQ + aoff + ks*32);
#pragma unroll
                for (int jp = 0; jp < 4; jp++) {
                    if (k0 + jp*16 <= qwmax) {
                        uint32_t bh[4], bl[4];
                        ldsm_x4(bh, uKh + kboff + (uint32_t)(jp*16*ASTR*2) + ks*32);
                        ldsm_x4(bl, uKl + kboff + (uint32_t)(jp*16*ASTR*2) + ks*32);
                        mma_f16(c[2*jp],   a, bh);
                        mma_f16(c[2*jp+1], a, bh+2);
                        mma_f16(c[2*jp],   a, bl);
                        mma_f16(c[2*jp+1], a, bl+2);
                    }
                }
            }

            if (k0 + 63 > qwmin) {
#pragma unroll
                for (int j = 0; j < 8; j++) {
                    int colb = k0 + j*8 + (lane & 3)*2;
                    if (colb     > rA) c[j][0] = -1e30f;
                    if (colb + 1 > rA) c[j][1] = -1e30f;
                    if (colb     > rB) c[j][2] = -1e30f;
                    if (colb + 1 > rB) c[j][3] = -1e30f;
                }
            }

            // ---- online softmax (base-2) ----
            float vmA = -1e30f, vmB = -1e30f;
#pragma unroll
            for (int j = 0; j < 8; j++) {
                vmA = fmaxf(vmA, fmaxf(c[j][0], c[j][1]));
                vmB = fmaxf(vmB, fmaxf(c[j][2], c[j][3]));
            }
            vmA = fmaxf(vmA, __shfl_xor_sync(0xffffffffu, vmA, 1));
            vmA = fmaxf(vmA, __shfl_xor_sync(0xffffffffu, vmA, 2));
            vmB = fmaxf(vmB, __shfl_xor_sync(0xffffffffu, vmB, 1));
            vmB = fmaxf(vmB, __shfl_xor_sync(0xffffffffu, vmB, 2));
            const float mnA = fmaxf(mA, vmA);
            const float mnB = fmaxf(mB, vmB);

            float sA = 0.f, sB = 0.f;
#pragma unroll
            for (int j = 0; j < 8; j++) {
                c[j][0] = exp2f(c[j][0] - mnA);
                c[j][1] = exp2f(c[j][1] - mnA);
                c[j][2] = exp2f(c[j][2] - mnB);
                c[j][3] = exp2f(c[j][3] - mnB);
                sA += c[j][0] + c[j][1];
                sB += c[j][2] + c[j][3];
            }
            sA += __shfl_xor_sync(0xffffffffu, sA, 1);
            sA += __shfl_xor_sync(0xffffffffu, sA, 2);
            sB += __shfl_xor_sync(0xffffffffu, sB, 1);
            sB += __shfl_xor_sync(0xffffffffu, sB, 2);

            const float soA = exp2f(mA - mnA);
            const float soB = exp2f(mB - mnB);
            lA = lA * soA + sA;  mA = mnA;
            lB = lB * soB + sB;  mB = mnB;

#pragma unroll
            for (int j = 0; j < 8; j++) {
                o[j][0] *= soA; o[j][1] *= soA;
                o[j][2] *= soB; o[j][3] *= soB;
            }

            // ---- O += P.V  (plain fp16 x plain fp16: 2 MMAs/subtile) ----
#pragma unroll
            for (int kk = 0; kk < 4; kk++) {
                if (k0 + kk*16 <= qwmax) {
                    uint32_t p[4];
                    p[0] = pack_h16(c[2*kk][0],   c[2*kk][1]);
                    p[1] = pack_h16(c[2*kk][2],   c[2*kk][3]);
                    p[2] = pack_h16(c[2*kk+1][0], c[2*kk+1][1]);
                    p[3] = pack_h16(c[2*kk+1][2], c[2*kk+1][3]);
#pragma unroll
                    for (int jp = 0; jp < 4; jp++) {
                        uint32_t v[4];
                        ldsm_x4_t(v, uV + vboff + (uint32_t)(kk*16*ASTR*2) + jp*32);
                        mma_f16(o[2*jp],   p, v);
                        mma_f16(o[2*jp+1], p, v+2);
                    }
                }
            }
        }
    }

    // epilogue: normalize + write plain fp16 AO [b, s, h*64+col]
    {
        const float invA = 1.f / lA;
        const float invB = 1.f / lB;
        const size_t offA = ((size_t)bb * SEQ + rA) * DMODEL + h * HDIM + (lane & 3) * 2;
        const size_t offB = ((size_t)bb * SEQ + rB) * DMODEL + h * HDIM + (lane & 3) * 2;
#pragma unroll
        for (int j = 0; j < 8; j++) {
            *(uint32_t*)(g_AO16 + offA + j*8) = pack_h16(o[j][0] * invA, o[j][1] * invA);
            *(uint32_t*)(g_AO16 + offB + j*8) = pack_h16(o[j][2] * invB, o[j][3] * invB);
        }
    }
}

// ---------------------------------------------------------------------------
extern "C" void kernel_launch(void* const* d_in, const int* in_sizes, int n_in,
                              void* d_out, int out_size)
{
    const float* x  = (const float*)d_in[0];
    const float* Wq = (const float*)d_in[1];
    const float* bq = (const float*)d_in[2];
    const float* Wk = (const float*)d_in[3];
    const float* bk = (const float*)d_in[4];
    const float* Wv = (const float*)d_in[5];
    const float* bv = (const float*)d_in[6];
    const float* Wo = (const float*)d_in[7];
    const float* bo = (const float*)d_in[8];
    float* out = (float*)d_out;

    cudaFuncSetAttribute(hl_gemm, cudaFuncAttributeMaxDynamicSharedMemorySize, GEMM_SMEM_BYTES);
    cudaFuncSetAttribute(attn_tc, cudaFuncAttributeMaxDynamicSharedMemorySize, ATTN_SMEM_BYTES);

    conv_x<<<(BATCH*SEQ*INDIM)/1024, 256>>>(x);
    conv_w4<<<dim3((DMODEL*INDIM)/1024, 4), 256>>>(Wq, Wk, Wv, Wo);

    GemmArgs qa;
    qa.bias0 = bq; qa.bias1 = bk; qa.bias2 = bv; qa.out_o = nullptr; qa.mode = 0;
    hl_gemm<<<dim3(DMODEL/BN, (BATCH*SEQ)/BM, 3), 256, GEMM_SMEM_BYTES>>>(qa);

    attn_tc<<<dim3(SEQ/128, NHEADS, BATCH), 256, ATTN_SMEM_BYTES>>>();

    GemmArgs oa;
    oa.bias0 = bo; oa.bias1 = nullptr; oa.bias2 = nullptr; oa.out_o = out; oa.mode = 1;
    hl_gemm<<<dim3(DMODEL/BN, (BATCH*SEQ)/BM, 1), 256, GEMM_SMEM_BYTES>>>(oa);
}

// round 14
// speedup vs baseline: 6.3977x; 1.3292x over previous
#include <cuda_runtime.h>
#include <cuda_bf16.h>
#include <cuda_fp16.h>
#include <stdint.h>
#include <math.h>

#define BATCH  4
#define SEQ    2048
#define INDIM  1024
#define DMODEL 1024
#define NHEADS 16
#define HDIM   64
#define KTOT   1024

// Q prescale: 1/sqrt(64) * log2(e)  (softmax runs in base-2)
#define QSCALE_LOG2E 0.1803368801111244f

// ---------------------------------------------------------------------------
// Device scratch (all fp16)
// ---------------------------------------------------------------------------
#define QKV_ELE (BATCH*NHEADS*SEQ*HDIM)
__device__ __half g_Q16[QKV_ELE];                        // plain fp16, pre-scaled
__device__ __half g_Kh16[QKV_ELE], g_Kl16[QKV_ELE];      // fp16 hi/lo
__device__ __half g_V16[QKV_ELE];                        // plain fp16
__device__ __half g_AO16[BATCH*SEQ*DMODEL];              // plain fp16
__device__ __half g_x16[BATCH*SEQ*INDIM];                // plain fp16
__device__ __half g_W16[4][DMODEL*INDIM];                // plain fp16

// ---------------------------------------------------------------------------
// PTX helpers
// ---------------------------------------------------------------------------
__device__ __forceinline__ uint32_t smem_u32(const void* p) {
    uint32_t a;
    asm("{ .reg .u64 t; cvta.to.shared.u64 t, %1; cvt.u32.u64 %0, t; }"
        : "=r"(a) : "l"(p));
    return a;
}
__device__ __forceinline__ void cp_async16(uint32_t dst, const void* src) {
    asm volatile("cp.async.cg.shared.global [%0], [%1], 16;" :: "r"(dst), "l"(src));
}
__device__ __forceinline__ void cp_commit()  { asm volatile("cp.async.commit_group;"); }
__device__ __forceinline__ void cp_wait0()   { asm volatile("cp.async.wait_group 0;"); }

__device__ __forceinline__ void ldsm_x4(uint32_t* r, uint32_t a) {
    asm volatile("ldmatrix.sync.aligned.m8n8.x4.shared.b16 {%0,%1,%2,%3}, [%4];"
        : "=r"(r[0]), "=r"(r[1]), "=r"(r[2]), "=r"(r[3]) : "r"(a));
}
__device__ __forceinline__ void ldsm_x4_t(uint32_t* r, uint32_t a) {
    asm volatile("ldmatrix.sync.aligned.m8n8.x4.trans.shared.b16 {%0,%1,%2,%3}, [%4];"
        : "=r"(r[0]), "=r"(r[1]), "=r"(r[2]), "=r"(r[3]) : "r"(a));
}
__device__ __forceinline__ void mma_f16(float* c, const uint32_t* a, const uint32_t* b) {
    asm volatile(
        "mma.sync.aligned.m16n8k16.row.col.f32.f16.f16.f32 "
        "{%0,%1,%2,%3}, {%4,%5,%6,%7}, {%8,%9}, {%0,%1,%2,%3};"
        : "+f"(c[0]), "+f"(c[1]), "+f"(c[2]), "+f"(c[3])
        : "r"(a[0]), "r"(a[1]), "r"(a[2]), "r"(a[3]), "r"(b[0]), "r"(b[1]));
}

__device__ __forceinline__ void split_hl16(float v, __half& h, __half& l) {
    h = __float2half(v);
    l = __float2half(v - __half2float(h));
}
__device__ __forceinline__ void pack_hl2_f16(float x, float y, uint32_t& hp, uint32_t& lp) {
    __half hx, lx, hy, ly;
    split_hl16(x, hx, lx); split_hl16(y, hy, ly);
    hp = ((uint32_t)__half_as_ushort(hy) << 16) | __half_as_ushort(hx);
    lp = ((uint32_t)__half_as_ushort(ly) << 16) | __half_as_ushort(lx);
}
__device__ __forceinline__ uint32_t pack_h16(float x, float y) {
    return ((uint32_t)__half_as_ushort(__float2half(y)) << 16)
         | __half_as_ushort(__float2half(x));
}

// ---------------------------------------------------------------------------
// converters: all plain fp16 now
// ---------------------------------------------------------------------------
__global__ __launch_bounds__(256) void conv_x(const float* __restrict__ src)
{
    size_t i = ((size_t)blockIdx.x * 256 + threadIdx.x) * 4;
    float4 v = *(const float4*)(src + i);
    __half o[4] = { __float2half(v.x), __float2half(v.y),
                    __float2half(v.z), __float2half(v.w) };
    *(uint2*)(g_x16 + i) = *(uint2*)o;
}

__global__ __launch_bounds__(256) void conv_w4(
    const float* __restrict__ Wq, const float* __restrict__ Wk,
    const float* __restrict__ Wv, const float* __restrict__ Wo)
{
    const int w = blockIdx.y;
    const float* src = (w == 0) ? Wq : (w == 1) ? Wk : (w == 2) ? Wv : Wo;
    __half* h = g_W16[w];
    size_t i = ((size_t)blockIdx.x * 256 + threadIdx.x) * 4;
    float4 v = *(const float4*)(src + i);
    __half o[4] = { __float2half(v.x), __float2half(v.y),
                    __float2half(v.z), __float2half(v.w) };
    *(uint2*)(h + i) = *(uint2*)o;
}

// ---------------------------------------------------------------------------
// fp16 1-MMA GEMM:  C[m,n] = sum_k A[m,k]*W[n,k] + bias[n]
// A plain fp16, W plain fp16.  128x128 block, 8 warps, BK=64,
// 2-stage cp.async, 2 CTAs/SM, register epilogue.
// mode 0: QKV -> Q plain fp16 (scaled), K fp16 hi/lo, V plain fp16, [B,H,S,Dh]
// mode 1: O-proj -> fp32 out
// ---------------------------------------------------------------------------
#define BM 128
#define BN 128
#define BK 64
#define NCH (KTOT/BK)          // 16
#define LDK 72
#define TILE_E (128*LDK)       // 9216
#define STAGE_E (2*TILE_E)     // A, B
#define GEMM_SMEM_BYTES (2*STAGE_E*2)   // 73728

struct GemmArgs {
    const float* bias0; const float* bias1; const float* bias2;
    float* out_o;
    int mode;
};

__global__ __launch_bounds__(256, 2) void hl_gemm(GemmArgs args)
{
    extern __shared__ __align__(16) char dsm[];
    __half* smT = (__half*)dsm;

    const int t    = threadIdx.x;
    const int wid  = t >> 5;
    const int lane = t & 31;
    const int z    = blockIdx.z;
    const int m0   = blockIdx.y * BM;
    const int n0   = blockIdx.x * BN;
    const int wm   = wid & 1;
    const int wn   = wid >> 1;

    const __half *Ax, *Bx;
    const float* bias;
    if (args.mode == 0) {
        Ax = g_x16;
        Bx = g_W16[z];
        bias = (z == 0) ? args.bias0 : (z == 1) ? args.bias1 : args.bias2;
    } else {
        Ax = g_AO16;
        Bx = g_W16[3];
        bias = args.bias0;
    }
    const __half* srcs[2] = { Ax, Bx };
    const int r0s[2] = { m0, n0 };

    const uint32_t ub = smem_u32(smT);
    const uint32_t abase = (uint32_t)(((wm*64 + (lane & 15)) * LDK + ((lane >> 4) << 3)) * 2);
    const uint32_t bbase = (uint32_t)(((wn*32 + ((lane >> 4) << 3) + (lane & 7)) * LDK
                                      + (((lane >> 3) & 1) << 3)) * 2);

    float c[4][4][4];
#pragma unroll
    for (int mi = 0; mi < 4; mi++)
#pragma unroll
        for (int nj = 0; nj < 4; nj++)
#pragma unroll
            for (int r = 0; r < 4; r++) c[mi][nj][r] = 0.f;

    // stage fill: 2 tiles x 128 rows x 8 chunks = 2048, 8/thread
    auto load_stage = [&](int stage, int kc) {
#pragma unroll
        for (int it = 0; it < 8; it++) {
            int idx  = t + it * 256;
            int tile = idx >> 10;
            int rem  = idx & 1023;
            int row  = rem >> 3;
            int ch   = rem & 7;
            const __half* sp = srcs[tile]
                + (size_t)(r0s[tile] + row) * KTOT + kc * BK + ch * 8;
            uint32_t dp = ub + (uint32_t)((stage * 2 + tile) * TILE_E + row * LDK + ch * 8) * 2;
            cp_async16(dp, sp);
        }
        cp_commit();
    };

    load_stage(0, 0);

    for (int kc = 0; kc < NCH; kc++) {
        cp_wait0();
        __syncthreads();
        if (kc + 1 < NCH) load_stage((kc + 1) & 1, kc + 1);

        const int s = kc & 1;
        const uint32_t uA = ub + (uint32_t)((s*2 + 0) * TILE_E) * 2;
        const uint32_t uB = ub + (uint32_t)((s*2 + 1) * TILE_E) * 2;

#pragma unroll
        for (int ks = 0; ks < 4; ks++) {
            uint32_t a[4][4];
#pragma unroll
            for (int mi = 0; mi < 4; mi++)
                ldsm_x4(a[mi], uA + abase + (uint32_t)(mi * 16 * LDK * 2) + ks * 32);
            uint32_t b[2][4];
#pragma unroll
            for (int j2 = 0; j2 < 2; j2++)
                ldsm_x4(b[j2], uB + bbase + (uint32_t)(j2 * 16 * LDK * 2) + ks * 32);
#pragma unroll
            for (int mi = 0; mi < 4; mi++)
#pragma unroll
                for (int nj = 0; nj < 4; nj++)
                    mma_f16(c[mi][nj], a[mi], &b[nj >> 1][(nj & 1) * 2]);
        }
    }

    // -------- register epilogue --------
    const float qscale = (args.mode == 0 && z == 0) ? QSCALE_LOG2E : 1.0f;
    float2 bv[4];
    int nn[4];
#pragma unroll
    for (int nj = 0; nj < 4; nj++) {
        nn[nj] = n0 + wn*32 + nj*8 + (lane & 3)*2;
        bv[nj] = *(const float2*)&bias[nn[nj]];
    }

    if (args.mode == 0) {
#pragma unroll
        for (int mi = 0; mi < 4; mi++) {
#pragma unroll
            for (int half = 0; half < 2; half++) {
                const int m  = m0 + wm*64 + mi*16 + (lane >> 2) + half*8;
                const int bb = m >> 11;
                const int ss = m & (SEQ - 1);
#pragma unroll
                for (int nj = 0; nj < 4; nj++) {
                    const int n  = nn[nj];
                    const int h  = n >> 6;
                    const int dh = n & 63;
                    const float v0 = (c[mi][nj][half*2+0] + bv[nj].x) * qscale;
                    const float v1 = (c[mi][nj][half*2+1] + bv[nj].y) * qscale;
                    const size_t off = (((size_t)bb * NHEADS + h) * SEQ + ss) * HDIM + dh;
                    if (z == 0) {
                        *(uint32_t*)(g_Q16 + off) = pack_h16(v0, v1);
                    } else if (z == 2) {
                        *(uint32_t*)(g_V16 + off) = pack_h16(v0, v1);
                    } else {
                        uint32_t hp, lp;
                        pack_hl2_f16(v0, v1, hp, lp);
                        *(uint32_t*)(g_Kh16 + off) = hp;
                        *(uint32_t*)(g_Kl16 + off) = lp;
                    }
                }
            }
        }
    } else {
        float* outp = args.out_o;
#pragma unroll
        for (int mi = 0; mi < 4; mi++) {
#pragma unroll
            for (int half = 0; half < 2; half++) {
                const int m = m0 + wm*64 + mi*16 + (lane >> 2) + half*8;
#pragma unroll
                for (int nj = 0; nj < 4; nj++) {
                    const float v0 = c[mi][nj][half*2+0] + bv[nj].x;
                    const float v1 = c[mi][nj][half*2+1] + bv[nj].y;
                    *(float2*)(outp + (size_t)m * DMODEL + nn[nj]) = make_float2(v0, v1);
                }
            }
        }
    }
}

// ---------------------------------------------------------------------------
// Register-resident causal flash attention — all fp16 (unchanged from R13).
// QK: Q plain x K hi/lo.  PV: plain x plain.  Base-2 softmax, subtile skip.
// ---------------------------------------------------------------------------
#define ASTR 72
#define KVBUF 27648
#define ATTN_SMEM_BYTES (18432 + 2*KVBUF)   // 73728

__global__ __launch_bounds__(256, 2) void attn_tc()
{
    extern __shared__ __align__(16) char asmem[];
    __half* sQ = (__half*)(asmem);

    const int t    = threadIdx.x;
    const int wid  = t >> 5;
    const int lane = t & 31;
    const int bq   = gridDim.x - 1 - blockIdx.x;   // heavy tiles first
    const int h    = blockIdx.y;
    const int bb   = blockIdx.z;
    const int q0   = bq * 128;
    const size_t base = ((size_t)bb * NHEADS + h) * SEQ * HDIM;

    const char* gsrc[3] = { (const char*)g_Kh16, (const char*)g_Kl16, (const char*)g_V16 };

    auto load_kv = [&](int buf, int k0) {
        char* dst0 = asmem + 18432 + buf * KVBUF;
#pragma unroll
        for (int it = 0; it < 6; it++) {
            int idx = t + it * 256;
            int a   = idx >> 9;
            int rem = idx & 511;
            int row = rem >> 3, ch = rem & 7;
            uint32_t dp = smem_u32(dst0 + a * 9216 + (row * ASTR + ch * 8) * 2);
            cp_async16(dp, gsrc[a] + (base + (size_t)(k0 + row) * HDIM + ch * 8) * 2);
        }
        cp_commit();
    };

    {
#pragma unroll
        for (int it = 0; it < 4; it++) {
            int idx = t + it * 256;
            int row = idx >> 3, ch = idx & 7;
            uint32_t dp = smem_u32(asmem + (row * ASTR + ch * 8) * 2);
            cp_async16(dp, g_Q16 + base + (size_t)(q0 + row) * HDIM + ch * 8);
        }
        cp_commit();
    }
    load_kv(0, 0);

    const uint32_t uQ = smem_u32(sQ);
    const uint32_t aoff  = (uint32_t)(((wid*16 + (lane & 15)) * ASTR + ((lane >> 4) << 3)) * 2);
    const uint32_t kboff = (uint32_t)(((((lane >> 4) << 3) + (lane & 7)) * ASTR + (((lane >> 3) & 1) << 3)) * 2);
    const uint32_t vboff = (uint32_t)((((((lane >> 3) & 1) << 3) + (lane & 7)) * ASTR + ((lane >> 4) << 3)) * 2);

    float o[8][4];
#pragma unroll
    for (int j = 0; j < 8; j++)
#pragma unroll
        for (int r = 0; r < 4; r++) o[j][r] = 0.f;

    const int rA = q0 + wid*16 + (lane >> 2);
    const int rB = rA + 8;
    const int qwmin = q0 + wid*16;
    const int qwmax = qwmin + 15;
    float mA = -1e30f, mB = -1e30f, lA = 0.f, lB = 0.f;

    const int nkt = 2*bq + 2;
    for (int kt = 0; kt < nkt; kt++) {
        const int k0 = kt * 64;
        cp_wait0();
        __syncthreads();
        if (kt + 1 < nkt) load_kv((kt + 1) & 1, k0 + 64);

        const uint32_t ukv = smem_u32(asmem + 18432 + (kt & 1) * KVBUF);
        const uint32_t uKh = ukv, uKl = ukv + 9216, uV = ukv + 18432;

        if (k0 <= qwmax) {
            float c[8][4];
#pragma unroll
            for (int j = 0; j < 8; j++)
#pragma unroll
                for (int r = 0; r < 4; r++) c[j][r] = 0.f;

            // ---- S = Q.K^T  (Q plain x K hi/lo) ----
#pragma unroll
            for (int ks = 0; ks < 4; ks++) {
                uint32_t a[4];
                ldsm_x4(a, uQ + aoff + ks*32);
#pragma unroll
                for (int jp = 0; jp < 4; jp++) {
                    if (k0 + jp*16 <= qwmax) {
                        uint32_t bh[4], bl[4];
                        ldsm_x4(bh, uKh + kboff + (uint32_t)(jp*16*ASTR*2) + ks*32);
                        ldsm_x4(bl, uKl + kboff + (uint32_t)(jp*16*ASTR*2) + ks*32);
                        mma_f16(c[2*jp],   a, bh);
                        mma_f16(c[2*jp+1], a, bh+2);
                        mma_f16(c[2*jp],   a, bl);
                        mma_f16(c[2*jp+1], a, bl+2);
                    }
                }
            }

            if (k0 + 63 > qwmin) {
#pragma unroll
                for (int j = 0; j < 8; j++) {
                    int colb = k0 + j*8 + (lane & 3)*2;
                    if (colb     > rA) c[j][0] = -1e30f;
                    if (colb + 1 > rA) c[j][1] = -1e30f;
                    if (colb     > rB) c[j][2] = -1e30f;
                    if (colb + 1 > rB) c[j][3] = -1e30f;
                }
            }

            // ---- online softmax (base-2) ----
            float vmA = -1e30f, vmB = -1e30f;
#pragma unroll
            for (int j = 0; j < 8; j++) {
                vmA = fmaxf(vmA, fmaxf(c[j][0], c[j][1]));
                vmB = fmaxf(vmB, fmaxf(c[j][2], c[j][3]));
            }
            vmA = fmaxf(vmA, __shfl_xor_sync(0xffffffffu, vmA, 1));
            vmA = fmaxf(vmA, __shfl_xor_sync(0xffffffffu, vmA, 2));
            vmB = fmaxf(vmB, __shfl_xor_sync(0xffffffffu, vmB, 1));
            vmB = fmaxf(vmB, __shfl_xor_sync(0xffffffffu, vmB, 2));
            const float mnA = fmaxf(mA, vmA);
            const float mnB = fmaxf(mB, vmB);

            float sA = 0.f, sB = 0.f;
#pragma unroll
            for (int j = 0; j < 8; j++) {
                c[j][0] = exp2f(c[j][0] - mnA);
                c[j][1] = exp2f(c[j][1] - mnA);
                c[j][2] = exp2f(c[j][2] - mnB);
                c[j][3] = exp2f(c[j][3] - mnB);
                sA += c[j][0] + c[j][1];
                sB += c[j][2] + c[j][3];
            }
            sA += __shfl_xor_sync(0xffffffffu, sA, 1);
            sA += __shfl_xor_sync(0xffffffffu, sA, 2);
            sB += __shfl_xor_sync(0xffffffffu, sB, 1);
            sB += __shfl_xor_sync(0xffffffffu, sB, 2);

            const float soA = exp2f(mA - mnA);
            const float soB = exp2f(mB - mnB);
            lA = lA * soA + sA;  mA = mnA;
            lB = lB * soB + sB;  mB = mnB;

#pragma unroll
            for (int j = 0; j < 8; j++) {
                o[j][0] *= soA; o[j][1] *= soA;
                o[j][2] *= soB; o[j][3] *= soB;
            }

            // ---- O += P.V  (plain x plain) ----
#pragma unroll
            for (int kk = 0; kk < 4; kk++) {
                if (k0 + kk*16 <= qwmax) {
                    uint32_t p[4];
                    p[0] = pack_h16(c[2*kk][0],   c[2*kk][1]);
                    p[1] = pack_h16(c[2*kk][2],   c[2*kk][3]);
                    p[2] = pack_h16(c[2*kk+1][0], c[2*kk+1][1]);
                    p[3] = pack_h16(c[2*kk+1][2], c[2*kk+1][3]);
#pragma unroll
                    for (int jp = 0; jp < 4; jp++) {
                        uint32_t v[4];
                        ldsm_x4_t(v, uV + vboff + (uint32_t)(kk*16*ASTR*2) + jp*32);
                        mma_f16(o[2*jp],   p, v);
                        mma_f16(o[2*jp+1], p, v+2);
                    }
                }
            }
        }
    }

    // epilogue: normalize + write plain fp16 AO [b, s, h*64+col]
    {
        const float invA = 1.f / lA;
        const float invB = 1.f / lB;
        const size_t offA = ((size_t)bb * SEQ + rA) * DMODEL + h * HDIM + (lane & 3) * 2;
        const size_t offB = ((size_t)bb * SEQ + rB) * DMODEL + h * HDIM + (lane & 3) * 2;
#pragma unroll
        for (int j = 0; j < 8; j++) {
            *(uint32_t*)(g_AO16 + offA + j*8) = pack_h16(o[j][0] * invA, o[j][1] * invA);
            *(uint32_t*)(g_AO16 + offB + j*8) = pack_h16(o[j][2] * invB, o[j][3] * invB);
        }
    }
}

// ---------------------------------------------------------------------------
extern "C" void kernel_launch(void* const* d_in, const int* in_sizes, int n_in,
                              void* d_out, int out_size)
{
    const float* x  = (const float*)d_in[0];
    const float* Wq = (const float*)d_in[1];
    const float* bq = (const float*)d_in[2];
    const float* Wk = (const float*)d_in[3];
    const float* bk = (const float*)d_in[4];
    const float* Wv = (const float*)d_in[5];
    const float* bv = (const float*)d_in[6];
    const float* Wo = (const float*)d_in[7];
    const float* bo = (const float*)d_in[8];
    float* out = (float*)d_out;

    cudaFuncSetAttribute(hl_gemm, cudaFuncAttributeMaxDynamicSharedMemorySize, GEMM_SMEM_BYTES);
    cudaFuncSetAttribute(attn_tc, cudaFuncAttributeMaxDynamicSharedMemorySize, ATTN_SMEM_BYTES);

    conv_x<<<(BATCH*SEQ*INDIM)/1024, 256>>>(x);
    conv_w4<<<dim3((DMODEL*INDIM)/1024, 4), 256>>>(Wq, Wk, Wv, Wo);

    GemmArgs qa;
    qa.bias0 = bq; qa.bias1 = bk; qa.bias2 = bv; qa.out_o = nullptr; qa.mode = 0;
    hl_gemm<<<dim3(DMODEL/BN, (BATCH*SEQ)/BM, 3), 256, GEMM_SMEM_BYTES>>>(qa);

    attn_tc<<<dim3(SEQ/128, NHEADS, BATCH), 256, ATTN_SMEM_BYTES>>>();

    GemmArgs oa;
    oa.bias0 = bo; oa.bias1 = nullptr; oa.bias2 = nullptr; oa.out_o = out; oa.mode = 1;
    hl_gemm<<<dim3(DMODEL/BN, (BATCH*SEQ)/BM, 1), 256, GEMM_SMEM_BYTES>>>(oa);
}

// round 15
// speedup vs baseline: 7.0161x; 1.0967x over previous
#include <cuda_runtime.h>
#include <cuda_bf16.h>
#include <cuda_fp16.h>
#include <stdint.h>
#include <math.h>

#define BATCH  4
#define SEQ    2048
#define INDIM  1024
#define DMODEL 1024
#define NHEADS 16
#define HDIM   64
#define KTOT   1024

// Q prescale: 1/sqrt(64) * log2(e)  (softmax runs in base-2)
#define QSCALE_LOG2E 0.1803368801111244f

// ---------------------------------------------------------------------------
// Device scratch (all plain fp16 now)
// ---------------------------------------------------------------------------
#define QKV_ELE (BATCH*NHEADS*SEQ*HDIM)
__device__ __half g_Q16[QKV_ELE];                        // plain fp16, pre-scaled
__device__ __half g_K16[QKV_ELE];                        // plain fp16
__device__ __half g_V16[QKV_ELE];                        // plain fp16
__device__ __half g_AO16[BATCH*SEQ*DMODEL];              // plain fp16
__device__ __half g_x16[BATCH*SEQ*INDIM];                // plain fp16
__device__ __half g_W16[4][DMODEL*INDIM];                // plain fp16

// ---------------------------------------------------------------------------
// PTX helpers
// ---------------------------------------------------------------------------
__device__ __forceinline__ uint32_t smem_u32(const void* p) {
    uint32_t a;
    asm("{ .reg .u64 t; cvta.to.shared.u64 t, %1; cvt.u32.u64 %0, t; }"
        : "=r"(a) : "l"(p));
    return a;
}
__device__ __forceinline__ void cp_async16(uint32_t dst, const void* src) {
    asm volatile("cp.async.cg.shared.global [%0], [%1], 16;" :: "r"(dst), "l"(src));
}
__device__ __forceinline__ void cp_commit()  { asm volatile("cp.async.commit_group;"); }
__device__ __forceinline__ void cp_wait0()   { asm volatile("cp.async.wait_group 0;"); }

__device__ __forceinline__ void ldsm_x4(uint32_t* r, uint32_t a) {
    asm volatile("ldmatrix.sync.aligned.m8n8.x4.shared.b16 {%0,%1,%2,%3}, [%4];"
        : "=r"(r[0]), "=r"(r[1]), "=r"(r[2]), "=r"(r[3]) : "r"(a));
}
__device__ __forceinline__ void ldsm_x4_t(uint32_t* r, uint32_t a) {
    asm volatile("ldmatrix.sync.aligned.m8n8.x4.trans.shared.b16 {%0,%1,%2,%3}, [%4];"
        : "=r"(r[0]), "=r"(r[1]), "=r"(r[2]), "=r"(r[3]) : "r"(a));
}
__device__ __forceinline__ void mma_f16(float* c, const uint32_t* a, const uint32_t* b) {
    asm volatile(
        "mma.sync.aligned.m16n8k16.row.col.f32.f16.f16.f32 "
        "{%0,%1,%2,%3}, {%4,%5,%6,%7}, {%8,%9}, {%0,%1,%2,%3};"
        : "+f"(c[0]), "+f"(c[1]), "+f"(c[2]), "+f"(c[3])
        : "r"(a[0]), "r"(a[1]), "r"(a[2]), "r"(a[3]), "r"(b[0]), "r"(b[1]));
}

__device__ __forceinline__ uint32_t pack_h16(float x, float y) {
    return ((uint32_t)__half_as_ushort(__float2half(y)) << 16)
         | __half_as_ushort(__float2half(x));
}

// ---------------------------------------------------------------------------
// converters: all plain fp16
// ---------------------------------------------------------------------------
__global__ __launch_bounds__(256) void conv_x(const float* __restrict__ src)
{
    size_t i = ((size_t)blockIdx.x * 256 + threadIdx.x) * 4;
    float4 v = *(const float4*)(src + i);
    __half o[4] = { __float2half(v.x), __float2half(v.y),
                    __float2half(v.z), __float2half(v.w) };
    *(uint2*)(g_x16 + i) = *(uint2*)o;
}

__global__ __launch_bounds__(256) void conv_w4(
    const float* __restrict__ Wq, const float* __restrict__ Wk,
    const float* __restrict__ Wv, const float* __restrict__ Wo)
{
    const int w = blockIdx.y;
    const float* src = (w == 0) ? Wq : (w == 1) ? Wk : (w == 2) ? Wv : Wo;
    __half* h = g_W16[w];
    size_t i = ((size_t)blockIdx.x * 256 + threadIdx.x) * 4;
    float4 v = *(const float4*)(src + i);
    __half o[4] = { __float2half(v.x), __float2half(v.y),
                    __float2half(v.z), __float2half(v.w) };
    *(uint2*)(h + i) = *(uint2*)o;
}

// ---------------------------------------------------------------------------
// fp16 1-MMA GEMM:  C[m,n] = sum_k A[m,k]*W[n,k] + bias[n]
// 128x128 block, 8 warps, BK=64, 2-stage cp.async, 2 CTAs/SM.
// mode 0: QKV -> Q (scaled) / K / V plain fp16, scatter [B,H,S,Dh]
// mode 1: O-proj -> fp32 out
// ---------------------------------------------------------------------------
#define BM 128
#define BN 128
#define BK 64
#define NCH (KTOT/BK)          // 16
#define LDK 72
#define TILE_E (128*LDK)       // 9216
#define STAGE_E (2*TILE_E)
#define GEMM_SMEM_BYTES (2*STAGE_E*2)   // 73728

struct GemmArgs {
    const float* bias0; const float* bias1; const float* bias2;
    float* out_o;
    int mode;
};

__global__ __launch_bounds__(256, 2) void hl_gemm(GemmArgs args)
{
    extern __shared__ __align__(16) char dsm[];
    __half* smT = (__half*)dsm;

    const int t    = threadIdx.x;
    const int wid  = t >> 5;
    const int lane = t & 31;
    const int z    = blockIdx.z;
    const int m0   = blockIdx.y * BM;
    const int n0   = blockIdx.x * BN;
    const int wm   = wid & 1;
    const int wn   = wid >> 1;

    const __half *Ax, *Bx;
    const float* bias;
    if (args.mode == 0) {
        Ax = g_x16;
        Bx = g_W16[z];
        bias = (z == 0) ? args.bias0 : (z == 1) ? args.bias1 : args.bias2;
    } else {
        Ax = g_AO16;
        Bx = g_W16[3];
        bias = args.bias0;
    }
    const __half* srcs[2] = { Ax, Bx };
    const int r0s[2] = { m0, n0 };

    const uint32_t ub = smem_u32(smT);
    const uint32_t abase = (uint32_t)(((wm*64 + (lane & 15)) * LDK + ((lane >> 4) << 3)) * 2);
    const uint32_t bbase = (uint32_t)(((wn*32 + ((lane >> 4) << 3) + (lane & 7)) * LDK
                                      + (((lane >> 3) & 1) << 3)) * 2);

    float c[4][4][4];
#pragma unroll
    for (int mi = 0; mi < 4; mi++)
#pragma unroll
        for (int nj = 0; nj < 4; nj++)
#pragma unroll
            for (int r = 0; r < 4; r++) c[mi][nj][r] = 0.f;

    auto load_stage = [&](int stage, int kc) {
#pragma unroll
        for (int it = 0; it < 8; it++) {
            int idx  = t + it * 256;
            int tile = idx >> 10;
            int rem  = idx & 1023;
            int row  = rem >> 3;
            int ch   = rem & 7;
            const __half* sp = srcs[tile]
                + (size_t)(r0s[tile] + row) * KTOT + kc * BK + ch * 8;
            uint32_t dp = ub + (uint32_t)((stage * 2 + tile) * TILE_E + row * LDK + ch * 8) * 2;
            cp_async16(dp, sp);
        }
        cp_commit();
    };

    load_stage(0, 0);

    for (int kc = 0; kc < NCH; kc++) {
        cp_wait0();
        __syncthreads();
        if (kc + 1 < NCH) load_stage((kc + 1) & 1, kc + 1);

        const int s = kc & 1;
        const uint32_t uA = ub + (uint32_t)((s*2 + 0) * TILE_E) * 2;
        const uint32_t uB = ub + (uint32_t)((s*2 + 1) * TILE_E) * 2;

#pragma unroll
        for (int ks = 0; ks < 4; ks++) {
            uint32_t a[4][4];
#pragma unroll
            for (int mi = 0; mi < 4; mi++)
                ldsm_x4(a[mi], uA + abase + (uint32_t)(mi * 16 * LDK * 2) + ks * 32);
            uint32_t b[2][4];
#pragma unroll
            for (int j2 = 0; j2 < 2; j2++)
                ldsm_x4(b[j2], uB + bbase + (uint32_t)(j2 * 16 * LDK * 2) + ks * 32);
#pragma unroll
            for (int mi = 0; mi < 4; mi++)
#pragma unroll
                for (int nj = 0; nj < 4; nj++)
                    mma_f16(c[mi][nj], a[mi], &b[nj >> 1][(nj & 1) * 2]);
        }
    }

    // -------- register epilogue --------
    const float qscale = (args.mode == 0 && z == 0) ? QSCALE_LOG2E : 1.0f;
    float2 bv[4];
    int nn[4];
#pragma unroll
    for (int nj = 0; nj < 4; nj++) {
        nn[nj] = n0 + wn*32 + nj*8 + (lane & 3)*2;
        bv[nj] = *(const float2*)&bias[nn[nj]];
    }

    if (args.mode == 0) {
        __half* dst = (z == 0) ? g_Q16 : (z == 1) ? g_K16 : g_V16;
#pragma unroll
        for (int mi = 0; mi < 4; mi++) {
#pragma unroll
            for (int half = 0; half < 2; half++) {
                const int m  = m0 + wm*64 + mi*16 + (lane >> 2) + half*8;
                const int bb = m >> 11;
                const int ss = m & (SEQ - 1);
#pragma unroll
                for (int nj = 0; nj < 4; nj++) {
                    const int n  = nn[nj];
                    const int h  = n >> 6;
                    const int dh = n & 63;
                    const float v0 = (c[mi][nj][half*2+0] + bv[nj].x) * qscale;
                    const float v1 = (c[mi][nj][half*2+1] + bv[nj].y) * qscale;
                    const size_t off = (((size_t)bb * NHEADS + h) * SEQ + ss) * HDIM + dh;
                    *(uint32_t*)(dst + off) = pack_h16(v0, v1);
                }
            }
        }
    } else {
        float* outp = args.out_o;
#pragma unroll
        for (int mi = 0; mi < 4; mi++) {
#pragma unroll
            for (int half = 0; half < 2; half++) {
                const int m = m0 + wm*64 + mi*16 + (lane >> 2) + half*8;
#pragma unroll
                for (int nj = 0; nj < 4; nj++) {
                    const float v0 = c[mi][nj][half*2+0] + bv[nj].x;
                    const float v1 = c[mi][nj][half*2+1] + bv[nj].y;
                    *(float2*)(outp + (size_t)m * DMODEL + nn[nj]) = make_float2(v0, v1);
                }
            }
        }
    }
}

// ---------------------------------------------------------------------------
// Register-resident causal flash attention — all plain fp16.
// QK: 1 MMA per (ks,jp,cfrag-pair).  PV: plain x plain.
// Base-2 softmax, diagonal subtile skipping, double-buffered K/V.
// SMEM: Q 128x72 (18432) + 2 KV buffers (K,V fp16 = 18432 each) = 55296.
// ---------------------------------------------------------------------------
#define ASTR 72
#define KVBUF 18432
#define ATTN_SMEM_BYTES (18432 + 2*KVBUF)   // 55296

__global__ __launch_bounds__(256, 2) void attn_tc()
{
    extern __shared__ __align__(16) char asmem[];
    __half* sQ = (__half*)(asmem);

    const int t    = threadIdx.x;
    const int wid  = t >> 5;
    const int lane = t & 31;
    const int bq   = gridDim.x - 1 - blockIdx.x;   // heavy tiles first
    const int h    = blockIdx.y;
    const int bb   = blockIdx.z;
    const int q0   = bq * 128;
    const size_t base = ((size_t)bb * NHEADS + h) * SEQ * HDIM;

    const char* gsrc[2] = { (const char*)g_K16, (const char*)g_V16 };

    auto load_kv = [&](int buf, int k0) {
        char* dst0 = asmem + 18432 + buf * KVBUF;
#pragma unroll
        for (int it = 0; it < 4; it++) {
            int idx = t + it * 256;          // 0..1023: 2 arrays x 64 rows x 8 chunks
            int a   = idx >> 9;
            int rem = idx & 511;
            int row = rem >> 3, ch = rem & 7;
            uint32_t dp = smem_u32(dst0 + a * 9216 + (row * ASTR + ch * 8) * 2);
            cp_async16(dp, gsrc[a] + (base + (size_t)(k0 + row) * HDIM + ch * 8) * 2);
        }
        cp_commit();
    };

    // Q loader
    {
#pragma unroll
        for (int it = 0; it < 4; it++) {
            int idx = t + it * 256;
            int row = idx >> 3, ch = idx & 7;
            uint32_t dp = smem_u32(asmem + (row * ASTR + ch * 8) * 2);
            cp_async16(dp, g_Q16 + base + (size_t)(q0 + row) * HDIM + ch * 8);
        }
        cp_commit();
    }
    load_kv(0, 0);

    const uint32_t uQ = smem_u32(sQ);
    const uint32_t aoff  = (uint32_t)(((wid*16 + (lane & 15)) * ASTR + ((lane >> 4) << 3)) * 2);
    const uint32_t kboff = (uint32_t)(((((lane >> 4) << 3) + (lane & 7)) * ASTR + (((lane >> 3) & 1) << 3)) * 2);
    const uint32_t vboff = (uint32_t)((((((lane >> 3) & 1) << 3) + (lane & 7)) * ASTR + ((lane >> 4) << 3)) * 2);

    float o[8][4];
#pragma unroll
    for (int j = 0; j < 8; j++)
#pragma unroll
        for (int r = 0; r < 4; r++) o[j][r] = 0.f;

    const int rA = q0 + wid*16 + (lane >> 2);
    const int rB = rA + 8;
    const int qwmin = q0 + wid*16;
    const int qwmax = qwmin + 15;
    float mA = -1e30f, mB = -1e30f, lA = 0.f, lB = 0.f;

    const int nkt = 2*bq + 2;
    for (int kt = 0; kt < nkt; kt++) {
        const int k0 = kt * 64;
        cp_wait0();
        __syncthreads();
        if (kt + 1 < nkt) load_kv((kt + 1) & 1, k0 + 64);

        const uint32_t ukv = smem_u32(asmem + 18432 + (kt & 1) * KVBUF);
        const uint32_t uK = ukv, uV = ukv + 9216;

        if (k0 <= qwmax) {
            float c[8][4];
#pragma unroll
            for (int j = 0; j < 8; j++)
#pragma unroll
                for (int r = 0; r < 4; r++) c[j][r] = 0.f;

            // ---- S = Q.K^T  (plain x plain: 2 MMAs per (ks,jp)) ----
#pragma unroll
            for (int ks = 0; ks < 4; ks++) {
                uint32_t a[4];
                ldsm_x4(a, uQ + aoff + ks*32);
#pragma unroll
                for (int jp = 0; jp < 4; jp++) {
                    if (k0 + jp*16 <= qwmax) {
                        uint32_t bk[4];
                        ldsm_x4(bk, uK + kboff + (uint32_t)(jp*16*ASTR*2) + ks*32);
                        mma_f16(c[2*jp],   a, bk);
                        mma_f16(c[2*jp+1], a, bk+2);
                    }
                }
            }

            if (k0 + 63 > qwmin) {
#pragma unroll
                for (int j = 0; j < 8; j++) {
                    int colb = k0 + j*8 + (lane & 3)*2;
                    if (colb     > rA) c[j][0] = -1e30f;
                    if (colb + 1 > rA) c[j][1] = -1e30f;
                    if (colb     > rB) c[j][2] = -1e30f;
                    if (colb + 1 > rB) c[j][3] = -1e30f;
                }
            }

            // ---- online softmax (base-2) ----
            float vmA = -1e30f, vmB = -1e30f;
#pragma unroll
            for (int j = 0; j < 8; j++) {
                vmA = fmaxf(vmA, fmaxf(c[j][0], c[j][1]));
                vmB = fmaxf(vmB, fmaxf(c[j][2], c[j][3]));
            }
            vmA = fmaxf(vmA, __shfl_xor_sync(0xffffffffu, vmA, 1));
            vmA = fmaxf(vmA, __shfl_xor_sync(0xffffffffu, vmA, 2));
            vmB = fmaxf(vmB, __shfl_xor_sync(0xffffffffu, vmB, 1));
            vmB = fmaxf(vmB, __shfl_xor_sync(0xffffffffu, vmB, 2));
            const float mnA = fmaxf(mA, vmA);
            const float mnB = fmaxf(mB, vmB);

            float sA = 0.f, sB = 0.f;
#pragma unroll
            for (int j = 0; j < 8; j++) {
                c[j][0] = exp2f(c[j][0] - mnA);
                c[j][1] = exp2f(c[j][1] - mnA);
                c[j][2] = exp2f(c[j][2] - mnB);
                c[j][3] = exp2f(c[j][3] - mnB);
                sA += c[j][0] + c[j][1];
                sB += c[j][2] + c[j][3];
            }
            sA += __shfl_xor_sync(0xffffffffu, sA, 1);
            sA += __shfl_xor_sync(0xffffffffu, sA, 2);
            sB += __shfl_xor_sync(0xffffffffu, sB, 1);
            sB += __shfl_xor_sync(0xffffffffu, sB, 2);

            const float soA = exp2f(mA - mnA);
            const float soB = exp2f(mB - mnB);
            lA = lA * soA + sA;  mA = mnA;
            lB = lB * soB + sB;  mB = mnB;

#pragma unroll
            for (int j = 0; j < 8; j++) {
                o[j][0] *= soA; o[j][1] *= soA;
                o[j][2] *= soB; o[j][3] *= soB;
            }

            // ---- O += P.V  (plain x plain) ----
#pragma unroll
            for (int kk = 0; kk < 4; kk++) {
                if (k0 + kk*16 <= qwmax) {
                    uint32_t p[4];
                    p[0] = pack_h16(c[2*kk][0],   c[2*kk][1]);
                    p[1] = pack_h16(c[2*kk][2],   c[2*kk][3]);
                    p[2] = pack_h16(c[2*kk+1][0], c[2*kk+1][1]);
                    p[3] = pack_h16(c[2*kk+1][2], c[2*kk+1][3]);
#pragma unroll
                    for (int jp = 0; jp < 4; jp++) {
                        uint32_t v[4];
                        ldsm_x4_t(v, uV + vboff + (uint32_t)(kk*16*ASTR*2) + jp*32);
                        mma_f16(o[2*jp],   p, v);
                        mma_f16(o[2*jp+1], p, v+2);
                    }
                }
            }
        }
    }

    // epilogue: normalize + write plain fp16 AO [b, s, h*64+col]
    {
        const float invA = 1.f / lA;
        const float invB = 1.f / lB;
        const size_t offA = ((size_t)bb * SEQ + rA) * DMODEL + h * HDIM + (lane & 3) * 2;
        const size_t offB = ((size_t)bb * SEQ + rB) * DMODEL + h * HDIM + (lane & 3) * 2;
#pragma unroll
        for (int j = 0; j < 8; j++) {
            *(uint32_t*)(g_AO16 + offA + j*8) = pack_h16(o[j][0] * invA, o[j][1] * invA);
            *(uint32_t*)(g_AO16 + offB + j*8) = pack_h16(o[j][2] * invB, o[j][3] * invB);
        }
    }
}

// ---------------------------------------------------------------------------
extern "C" void kernel_launch(void* const* d_in, const int* in_sizes, int n_in,
                              void* d_out, int out_size)
{
    const float* x  = (const float*)d_in[0];
    const float* Wq = (const float*)d_in[1];
    const float* bq = (const float*)d_in[2];
    const float* Wk = (const float*)d_in[3];
    const float* bk = (const float*)d_in[4];
    const float* Wv = (const float*)d_in[5];
    const float* bv = (const float*)d_in[6];
    const float* Wo = (const float*)d_in[7];
    const float* bo = (const float*)d_in[8];
    float* out = (float*)d_out;

    cudaFuncSetAttribute(hl_gemm, cudaFuncAttributeMaxDynamicSharedMemorySize, GEMM_SMEM_BYTES);
    cudaFuncSetAttribute(attn_tc, cudaFuncAttributeMaxDynamicSharedMemorySize, ATTN_SMEM_BYTES);

    conv_x<<<(BATCH*SEQ*INDIM)/1024, 256>>>(x);
    conv_w4<<<dim3((DMODEL*INDIM)/1024, 4), 256>>>(Wq, Wk, Wv, Wo);

    GemmArgs qa;
    qa.bias0 = bq; qa.bias1 = bk; qa.bias2 = bv; qa.out_o = nullptr; qa.mode = 0;
    hl_gemm<<<dim3(DMODEL/BN, (BATCH*SEQ)/BM, 3), 256, GEMM_SMEM_BYTES>>>(qa);

    attn_tc<<<dim3(SEQ/128, NHEADS, BATCH), 256, ATTN_SMEM_BYTES>>>();

    GemmArgs oa;
    oa.bias0 = bo; oa.bias1 = nullptr; oa.bias2 = nullptr; oa.out_o = out; oa.mode = 1;
    hl_gemm<<<dim3(DMODEL/BN, (BATCH*SEQ)/BM, 1), 256, GEMM_SMEM_BYTES>>>(oa);
}